// round 7
// baseline (speedup 1.0000x reference)
#include <cuda_runtime.h>
#include <cuda_bf16.h>
#include <math.h>

#define DIMK 1024
#define CC   128
#define BB   8
#define TT   2048
#define ROWS (BB*TT)   // 16384

typedef unsigned long long ull;

// ------------------------- device scratch (no allocs allowed) -------------
__device__ float g_Q [ROWS*CC];
__device__ float g_K [ROWS*CC];   // normalized k
__device__ float g_V [ROWS*CC];
__device__ float g_G [ROWS*CC];
__device__ float g_O [ROWS*CC];
__device__ float g_Al[ROWS];
__device__ float g_Be[ROWS];

__device__ __forceinline__ float sigmoidf_(float x) { return 1.0f / (1.0f + expf(-x)); }

// ---- packed f32x2 helpers ----
__device__ __forceinline__ ull pack2(float lo, float hi) {
    ull r; asm("mov.b64 %0, {%1, %2};" : "=l"(r) : "f"(lo), "f"(hi)); return r;
}
__device__ __forceinline__ void unpack2(ull v, float& lo, float& hi) {
    asm("mov.b64 {%0, %1}, %2;" : "=f"(lo), "=f"(hi) : "l"(v));
}
__device__ __forceinline__ ull fma2(ull a, ull b, ull c) {
    ull d; asm("fma.rn.f32x2 %0, %1, %2, %3;" : "=l"(d) : "l"(a), "l"(b), "l"(c)); return d;
}
__device__ __forceinline__ ull mul2(ull a, ull b) {
    ull d; asm("mul.rn.f32x2 %0, %1, %2;" : "=l"(d) : "l"(a), "l"(b)); return d;
}

// ===========================================================================
// Kernel 1: projections  q,k,v,g = x @ W + b  (f32x2 SGEMM, 128x128x16)
// with register double-buffering of global loads.
// ===========================================================================
__global__ __launch_bounds__(256) void proj_gemm(
    const float* __restrict__ x,
    const float* __restrict__ Wq, const float* __restrict__ Wk,
    const float* __restrict__ Wv, const float* __restrict__ Wg,
    const float* __restrict__ bq, const float* __restrict__ bk,
    const float* __restrict__ bv, const float* __restrict__ bg)
{
    __shared__ __align__(16) float As2[16][256];
    __shared__ __align__(16) float Bs[16][128];

    const int mid  = blockIdx.y;
    const float* W    = (mid == 0) ? Wq : (mid == 1) ? Wk : (mid == 2) ? Wv : Wg;
    const float* bias = (mid == 0) ? bq : (mid == 1) ? bk : (mid == 2) ? bv : bg;
    float* outp       = (mid == 0) ? g_Q : (mid == 1) ? g_K : (mid == 2) ? g_V : g_G;

    const int row0 = blockIdx.x * 128;
    const int tid  = threadIdx.x;
    const int tx   = tid & 15;
    const int ty   = tid >> 4;
    const int lr   = tid >> 2;
    const int lc   = (tid & 3) * 4;
    const int bkk  = tid >> 5;
    const int bn   = (tid & 31) * 4;

    ull acc[8][4];
#pragma unroll
    for (int m = 0; m < 8; ++m)
#pragma unroll
        for (int n = 0; n < 4; ++n) acc[m][n] = 0ull;

    float4 aR[2], bR[2];
#pragma unroll
    for (int h = 0; h < 2; ++h) {
        aR[h] = *(const float4*)(x + (size_t)(row0 + lr + h * 64) * DIMK + lc);
        bR[h] = *(const float4*)(W + (size_t)(bkk + h * 8) * CC + bn);
    }

    for (int k0 = 0; k0 < DIMK; k0 += 16) {
#pragma unroll
        for (int h = 0; h < 2; ++h) {
            int r = lr + h * 64;
            *(float2*)&As2[lc + 0][2 * r] = make_float2(aR[h].x, aR[h].x);
            *(float2*)&As2[lc + 1][2 * r] = make_float2(aR[h].y, aR[h].y);
            *(float2*)&As2[lc + 2][2 * r] = make_float2(aR[h].z, aR[h].z);
            *(float2*)&As2[lc + 3][2 * r] = make_float2(aR[h].w, aR[h].w);
            *(float4*)&Bs[bkk + h * 8][bn] = bR[h];
        }
        __syncthreads();

        if (k0 + 16 < DIMK) {
#pragma unroll
            for (int h = 0; h < 2; ++h) {
                aR[h] = *(const float4*)(x + (size_t)(row0 + lr + h * 64) * DIMK + k0 + 16 + lc);
                bR[h] = *(const float4*)(W + (size_t)(k0 + 16 + bkk + h * 8) * CC + bn);
            }
        }
#pragma unroll
        for (int kk = 0; kk < 16; ++kk) {
            const ulonglong2* ap = (const ulonglong2*)&As2[kk][2 * (ty * 8)];
            const ulonglong2* bp = (const ulonglong2*)&Bs[kk][tx * 8];
            ulonglong2 a01 = ap[0], a23 = ap[1], a45 = ap[2], a67 = ap[3];
            ulonglong2 b01 = bp[0], b23 = bp[1];
            ull ar[8] = {a01.x, a01.y, a23.x, a23.y, a45.x, a45.y, a67.x, a67.y};
            ull br[4] = {b01.x, b01.y, b23.x, b23.y};
#pragma unroll
            for (int m = 0; m < 8; ++m)
#pragma unroll
                for (int n = 0; n < 4; ++n)
                    acc[m][n] = fma2(ar[m], br[n], acc[m][n]);
        }
        __syncthreads();
    }

#pragma unroll
    for (int m = 0; m < 8; ++m) {
        int row = row0 + ty * 8 + m;
#pragma unroll
        for (int n = 0; n < 4; ++n) {
            int col = tx * 8 + 2 * n;
            float e0, e1; unpack2(acc[m][n], e0, e1);
            float v0 = e0 + bias[col];
            float v1 = e1 + bias[col + 1];
            if (mid == 3) { v0 = sigmoidf_(v0); v1 = sigmoidf_(v1); }
            *(float2*)&outp[(size_t)row * CC + col] = make_float2(v0, v1);
        }
    }
}

// ===========================================================================
// Kernel 2: alpha/beta
// ===========================================================================
__global__ __launch_bounds__(256) void ab_kernel(
    const float* __restrict__ x,
    const float* __restrict__ Wa, const float* __restrict__ ba,
    const float* __restrict__ Wb, const float* __restrict__ bb)
{
    const int warp = threadIdx.x >> 5, lane = threadIdx.x & 31;
    const int row  = blockIdx.x * 8 + warp;
    const float* xr = x + (size_t)row * DIMK;
    float accA = 0.0f, accB = 0.0f;
#pragma unroll
    for (int it = 0; it < 8; ++it) {
        int kidx = it * 128 + lane * 4;
        float4 xv = *(const float4*)(xr + kidx);
        float4 wa = *(const float4*)(Wa + kidx);
        float4 wb = *(const float4*)(Wb + kidx);
        accA += xv.x * wa.x + xv.y * wa.y + xv.z * wa.z + xv.w * wa.w;
        accB += xv.x * wb.x + xv.y * wb.y + xv.z * wb.z + xv.w * wb.w;
    }
#pragma unroll
    for (int o = 16; o; o >>= 1) {
        accA += __shfl_xor_sync(0xffffffffu, accA, o);
        accB += __shfl_xor_sync(0xffffffffu, accB, o);
    }
    if (lane == 0) {
        g_Al[row] = sigmoidf_(accA + ba[0]);
        g_Be[row] = sigmoidf_(accB + bb[0]);
    }
}

// ===========================================================================
// Kernel 3: normalize k rows
// ===========================================================================
__global__ __launch_bounds__(256) void knorm_kernel()
{
    const int warp = threadIdx.x >> 5, lane = threadIdx.x & 31;
    const int row  = blockIdx.x * 8 + warp;
    float* kp = g_K + (size_t)row * CC + lane * 4;
    float4 kv = *(float4*)kp;
    float ss = kv.x * kv.x + kv.y * kv.y + kv.z * kv.z + kv.w * kv.w;
#pragma unroll
    for (int o = 16; o; o >>= 1) ss += __shfl_xor_sync(0xffffffffu, ss, o);
    float scale = 1.0f / fmaxf(sqrtf(ss), 1e-12f);
    kv.x *= scale; kv.y *= scale; kv.z *= scale; kv.w *= scale;
    *(float4*)kp = kv;
}

// ===========================================================================
// Kernel 4: gated-delta scan, one CTA (256 threads) per batch.
// A threads (0..127): own row i of S_hat in regs (64 ull).
// B threads (128..255): own row j of S_hat^T; fuse update+output dot.
// Producer->consumer: A bar.arrive after writing u; B bar.sync — A never
// waits for B mid-step. S_true = c*S_hat, c block-uniform.
// ===========================================================================
__global__ __launch_bounds__(256, 1) void scan_kernel()
{
    const int b    = blockIdx.x;
    const int tid  = threadIdx.x;
    const bool isA = (tid < 128);
    const int  r   = tid & 127;

    __shared__ __align__(16) float k_sh[2][128], q_sh[2][128];
    __shared__ __align__(16) float v_sh[2][128], g_sh[2][128];
    __shared__ __align__(16) float u_sh[128];
    __shared__ float2 ab_sh[2];

    ull Sp[64];
#pragma unroll
    for (int j = 0; j < 64; ++j) Sp[j] = 0ull;
    float c = 1.0f;

    const size_t base = (size_t)b * TT * CC;
    const float* Qb = g_Q + base;
    const float* Kb = g_K + base;
    const float* Vb = g_V + base;
    const float* Gb = g_G + base;
    const float* Ab = g_Al + (size_t)b * TT;
    const float* Bb = g_Be + (size_t)b * TT;
    float*       Ob = g_O + base;

    // preload t=0
    float s0, s1;
    if (isA) { s0 = Kb[r]; s1 = Qb[r]; }
    else     { s0 = Vb[r]; s1 = Gb[r]; }
    float2 abr = make_float2(0.f, 0.f);
    if (tid == 0) abr = make_float2(Ab[0], Bb[0]);

    int p = 0;
    for (int t = 0; t < TT; ++t) {
        if (isA) { k_sh[p][r] = s0; q_sh[p][r] = s1; }
        else     { v_sh[p][r] = s0; g_sh[p][r] = s1; }
        if (tid == 0) ab_sh[p] = abr;
        __syncthreads();

        // prefetch t+1 (issued before any waiting)
        if (t + 1 < TT) {
            const size_t off = (size_t)(t + 1) * CC + r;
            if (isA) { s0 = Kb[off]; s1 = Qb[off]; }
            else     { s0 = Vb[off]; s1 = Gb[off]; }
            if (tid == 0) abr = make_float2(Ab[t + 1], Bb[t + 1]);
        }

        const float aa = ab_sh[p].x;
        const float cn = aa * c;

        if (isA) {
            const float bbv = ab_sh[p].y;
            // dot: S_hat[r,:] . k
            const ulonglong2* k16 = (const ulonglong2*)k_sh[p];
            ull a0 = 0ull, a1 = 0ull, a2 = 0ull, a3 = 0ull;
#pragma unroll
            for (int j = 0; j < 16; ++j) {
                ulonglong2 xa = k16[2 * j], xb = k16[2 * j + 1];
                a0 = fma2(Sp[4 * j + 0], xa.x, a0);
                a1 = fma2(Sp[4 * j + 1], xa.y, a1);
                a2 = fma2(Sp[4 * j + 2], xb.x, a2);
                a3 = fma2(Sp[4 * j + 3], xb.y, a3);
            }
            float f0, f1, f2, f3, f4, f5, f6, f7;
            unpack2(a0, f0, f1); unpack2(a1, f2, f3);
            unpack2(a2, f4, f5); unpack2(a3, f6, f7);
            const float dot = ((f0 + f1) + (f2 + f3)) + ((f4 + f5) + (f6 + f7));

            const float u = bbv * v_sh[p][r] - aa * bbv * (c * dot);
            u_sh[r] = u;
            asm volatile("bar.arrive 1, 256;" ::: "memory");

            // S_hat[r,:] += (u/cn) * k
            const float w = u * (1.0f / cn);
            const ull w2 = pack2(w, w);
#pragma unroll
            for (int j = 0; j < 16; ++j) {
                ulonglong2 ka = k16[2 * j], kb = k16[2 * j + 1];
                Sp[4 * j + 0] = fma2(w2, ka.x, Sp[4 * j + 0]);
                Sp[4 * j + 1] = fma2(w2, ka.y, Sp[4 * j + 1]);
                Sp[4 * j + 2] = fma2(w2, kb.x, Sp[4 * j + 2]);
                Sp[4 * j + 3] = fma2(w2, kb.y, Sp[4 * j + 3]);
            }
        } else {
            asm volatile("bar.sync 1, 256;" ::: "memory");
            // fused: S_hat^T[r,:] += (k_r/cn)*u ; ohat = S_hat^T_new[r,:].q
            const float kj   = k_sh[p][r];
            const float kw   = kj * (1.0f / cn);
            const ull   kw2  = pack2(kw, kw);
            const ulonglong2* u16 = (const ulonglong2*)u_sh;
            const ulonglong2* q16 = (const ulonglong2*)q_sh[p];
            ull o0 = 0ull, o1 = 0ull, o2 = 0ull, o3 = 0ull;
#pragma unroll
            for (int j = 0; j < 16; ++j) {
                ulonglong2 ua = u16[2 * j], ub = u16[2 * j + 1];
                ulonglong2 qa = q16[2 * j], qb = q16[2 * j + 1];
                Sp[4 * j + 0] = fma2(kw2, ua.x, Sp[4 * j + 0]);
                o0 = fma2(Sp[4 * j + 0], qa.x, o0);
                Sp[4 * j + 1] = fma2(kw2, ua.y, Sp[4 * j + 1]);
                o1 = fma2(Sp[4 * j + 1], qa.y, o1);
                Sp[4 * j + 2] = fma2(kw2, ub.x, Sp[4 * j + 2]);
                o2 = fma2(Sp[4 * j + 2], qb.x, o2);
                Sp[4 * j + 3] = fma2(kw2, ub.y, Sp[4 * j + 3]);
                o3 = fma2(Sp[4 * j + 3], qb.y, o3);
            }
            float f0, f1, f2, f3, f4, f5, f6, f7;
            unpack2(o0, f0, f1); unpack2(o1, f2, f3);
            unpack2(o2, f4, f5); unpack2(o3, f6, f7);
            const float ohat = ((f0 + f1) + (f2 + f3)) + ((f4 + f5) + (f6 + f7));
            Ob[(size_t)t * CC + r] = (cn * ohat) * g_sh[p][r];
        }

        c = cn;
        if (c < 1e-10f) {
            const ull c2 = pack2(c, c);
#pragma unroll
            for (int j = 0; j < 64; ++j) Sp[j] = mul2(Sp[j], c2);
            c = 1.0f;
        }
        p ^= 1;
    }
}

// ===========================================================================
// Kernel 5: out = O @ Wo + bo   (f32x2 SGEMM, prefetched)
// ===========================================================================
__global__ __launch_bounds__(256) void out_gemm(
    const float* __restrict__ Wo, const float* __restrict__ bo,
    float* __restrict__ out)
{
    __shared__ __align__(16) float As2[16][256];
    __shared__ __align__(16) float Bs[16][128];

    const int row0 = blockIdx.x * 128;
    const int col0 = blockIdx.y * 128;
    const int tid  = threadIdx.x;
    const int tx   = tid & 15;
    const int ty   = tid >> 4;
    const int lr   = tid >> 2;
    const int lc   = (tid & 3) * 4;
    const int bkk  = tid >> 5;
    const int bn   = (tid & 31) * 4;

    ull acc[8][4];
#pragma unroll
    for (int m = 0; m < 8; ++m)
#pragma unroll
        for (int n = 0; n < 4; ++n) acc[m][n] = 0ull;

    float4 aR[2], bR[2];
#pragma unroll
    for (int h = 0; h < 2; ++h) {
        aR[h] = *(const float4*)(g_O + (size_t)(row0 + lr + h * 64) * CC + lc);
        bR[h] = *(const float4*)(Wo + (size_t)(bkk + h * 8) * DIMK + col0 + bn);
    }

    for (int k0 = 0; k0 < CC; k0 += 16) {
#pragma unroll
        for (int h = 0; h < 2; ++h) {
            int r = lr + h * 64;
            *(float2*)&As2[lc + 0][2 * r] = make_float2(aR[h].x, aR[h].x);
            *(float2*)&As2[lc + 1][2 * r] = make_float2(aR[h].y, aR[h].y);
            *(float2*)&As2[lc + 2][2 * r] = make_float2(aR[h].z, aR[h].z);
            *(float2*)&As2[lc + 3][2 * r] = make_float2(aR[h].w, aR[h].w);
            *(float4*)&Bs[bkk + h * 8][bn] = bR[h];
        }
        __syncthreads();

        if (k0 + 16 < CC) {
#pragma unroll
            for (int h = 0; h < 2; ++h) {
                aR[h] = *(const float4*)(g_O + (size_t)(row0 + lr + h * 64) * CC + k0 + 16 + lc);
                bR[h] = *(const float4*)(Wo + (size_t)(k0 + 16 + bkk + h * 8) * DIMK + col0 + bn);
            }
        }
#pragma unroll
        for (int kk = 0; kk < 16; ++kk) {
            const ulonglong2* ap = (const ulonglong2*)&As2[kk][2 * (ty * 8)];
            const ulonglong2* bp = (const ulonglong2*)&Bs[kk][tx * 8];
            ulonglong2 a01 = ap[0], a23 = ap[1], a45 = ap[2], a67 = ap[3];
            ulonglong2 b01 = bp[0], b23 = bp[1];
            ull ar[8] = {a01.x, a01.y, a23.x, a23.y, a45.x, a45.y, a67.x, a67.y};
            ull br[4] = {b01.x, b01.y, b23.x, b23.y};
#pragma unroll
            for (int m = 0; m < 8; ++m)
#pragma unroll
                for (int n = 0; n < 4; ++n)
                    acc[m][n] = fma2(ar[m], br[n], acc[m][n]);
        }
        __syncthreads();
    }

#pragma unroll
    for (int m = 0; m < 8; ++m) {
        int row = row0 + ty * 8 + m;
#pragma unroll
        for (int n = 0; n < 4; ++n) {
            int col = col0 + tx * 8 + 2 * n;
            float e0, e1; unpack2(acc[m][n], e0, e1);
            *(float2*)&out[(size_t)row * DIMK + col] =
                make_float2(e0 + bo[col], e1 + bo[col + 1]);
        }
    }
}

// ===========================================================================
extern "C" void kernel_launch(void* const* d_in, const int* in_sizes, int n_in,
                              void* d_out, int out_size)
{
    const float* x  = (const float*)d_in[0];
    const float* Wq = (const float*)d_in[1];  const float* bq = (const float*)d_in[2];
    const float* Wk = (const float*)d_in[3];  const float* bk = (const float*)d_in[4];
    const float* Wv = (const float*)d_in[5];  const float* bv = (const float*)d_in[6];
    const float* Wa = (const float*)d_in[7];  const float* ba = (const float*)d_in[8];
    const float* Wb = (const float*)d_in[9];  const float* bb = (const float*)d_in[10];
    const float* Wg = (const float*)d_in[11]; const float* bg = (const float*)d_in[12];
    const float* Wo = (const float*)d_in[13]; const float* bo = (const float*)d_in[14];
    float* out = (float*)d_out;

    proj_gemm<<<dim3(128, 4), 256>>>(x, Wq, Wk, Wv, Wg, bq, bk, bv, bg);
    ab_kernel<<<2048, 256>>>(x, Wa, ba, Wb, bb);
    knorm_kernel<<<2048, 256>>>();
    scan_kernel<<<BB, 256>>>();
    out_gemm<<<dim3(128, 8), 256>>>(Wo, bo, out);
}

// round 8
// speedup vs baseline: 1.5046x; 1.5046x over previous
#include <cuda_runtime.h>
#include <cuda_bf16.h>
#include <math.h>

#define DIMK 1024
#define CC   128
#define BB   8
#define TT   2048
#define ROWS (BB*TT)
#define LCH  64
#define NCH  (TT/LCH)     // 32
#define NCHT (BB*NCH)     // 256

typedef unsigned long long ull;

__device__ float g_Q [ROWS*CC];
__device__ float g_K [ROWS*CC];
__device__ float g_V [ROWS*CC];
__device__ float g_G [ROWS*CC];
__device__ float g_O [ROWS*CC];
__device__ float g_Al[ROWS];
__device__ float g_Be[ROWS];
__device__ float g_U0[NCHT*LCH*CC];
__device__ float g_W [NCHT*LCH*CC];
__device__ float g_U [NCHT*LCH*CC];
__device__ float g_Sc[NCHT*CC*CC];     // chunk-start state, layout [j][i] = S[i][j]
__device__ float g_Gm[NCHT*LCH];

__device__ __forceinline__ float sigmoidf_(float x) { return 1.0f / (1.0f + expf(-x)); }
__device__ __forceinline__ ull pack2(float lo, float hi) {
    ull r; asm("mov.b64 %0, {%1, %2};" : "=l"(r) : "f"(lo), "f"(hi)); return r;
}
__device__ __forceinline__ void unpack2(ull v, float& lo, float& hi) {
    asm("mov.b64 {%0, %1}, %2;" : "=f"(lo), "=f"(hi) : "l"(v));
}
__device__ __forceinline__ ull fma2(ull a, ull b, ull c) {
    ull d; asm("fma.rn.f32x2 %0, %1, %2, %3;" : "=l"(d) : "l"(a), "l"(b), "l"(c)); return d;
}
__device__ __forceinline__ ull mul2(ull a, ull b) {
    ull d; asm("mul.rn.f32x2 %0, %1, %2;" : "=l"(d) : "l"(a), "l"(b)); return d;
}

// ====================== Kernel 1: projections (f32x2 SGEMM) ================
__global__ __launch_bounds__(256) void proj_gemm(
    const float* __restrict__ x,
    const float* __restrict__ Wq, const float* __restrict__ Wk,
    const float* __restrict__ Wv, const float* __restrict__ Wg,
    const float* __restrict__ bq, const float* __restrict__ bk,
    const float* __restrict__ bv, const float* __restrict__ bg)
{
    __shared__ __align__(16) float As2[16][256];
    __shared__ __align__(16) float Bs[16][128];
    const int mid  = blockIdx.y;
    const float* W    = (mid == 0) ? Wq : (mid == 1) ? Wk : (mid == 2) ? Wv : Wg;
    const float* bias = (mid == 0) ? bq : (mid == 1) ? bk : (mid == 2) ? bv : bg;
    float* outp       = (mid == 0) ? g_Q : (mid == 1) ? g_K : (mid == 2) ? g_V : g_G;
    const int row0 = blockIdx.x * 128;
    const int tid = threadIdx.x, tx = tid & 15, ty = tid >> 4;
    const int lr = tid >> 2, lc = (tid & 3) * 4, bkk = tid >> 5, bn = (tid & 31) * 4;

    ull acc[8][4];
#pragma unroll
    for (int m = 0; m < 8; ++m)
#pragma unroll
        for (int n = 0; n < 4; ++n) acc[m][n] = 0ull;

    float4 aR[2], bR[2];
#pragma unroll
    for (int h = 0; h < 2; ++h) {
        aR[h] = *(const float4*)(x + (size_t)(row0 + lr + h * 64) * DIMK + lc);
        bR[h] = *(const float4*)(W + (size_t)(bkk + h * 8) * CC + bn);
    }
    for (int k0 = 0; k0 < DIMK; k0 += 16) {
#pragma unroll
        for (int h = 0; h < 2; ++h) {
            int r = lr + h * 64;
            *(float2*)&As2[lc + 0][2 * r] = make_float2(aR[h].x, aR[h].x);
            *(float2*)&As2[lc + 1][2 * r] = make_float2(aR[h].y, aR[h].y);
            *(float2*)&As2[lc + 2][2 * r] = make_float2(aR[h].z, aR[h].z);
            *(float2*)&As2[lc + 3][2 * r] = make_float2(aR[h].w, aR[h].w);
            *(float4*)&Bs[bkk + h * 8][bn] = bR[h];
        }
        __syncthreads();
        if (k0 + 16 < DIMK) {
#pragma unroll
            for (int h = 0; h < 2; ++h) {
                aR[h] = *(const float4*)(x + (size_t)(row0 + lr + h * 64) * DIMK + k0 + 16 + lc);
                bR[h] = *(const float4*)(W + (size_t)(k0 + 16 + bkk + h * 8) * CC + bn);
            }
        }
#pragma unroll
        for (int kk = 0; kk < 16; ++kk) {
            const ulonglong2* ap = (const ulonglong2*)&As2[kk][2 * (ty * 8)];
            const ulonglong2* bp = (const ulonglong2*)&Bs[kk][tx * 8];
            ulonglong2 a01 = ap[0], a23 = ap[1], a45 = ap[2], a67 = ap[3];
            ulonglong2 b01 = bp[0], b23 = bp[1];
            ull ar[8] = {a01.x, a01.y, a23.x, a23.y, a45.x, a45.y, a67.x, a67.y};
            ull br[4] = {b01.x, b01.y, b23.x, b23.y};
#pragma unroll
            for (int m = 0; m < 8; ++m)
#pragma unroll
                for (int n = 0; n < 4; ++n)
                    acc[m][n] = fma2(ar[m], br[n], acc[m][n]);
        }
        __syncthreads();
    }
#pragma unroll
    for (int m = 0; m < 8; ++m) {
        int row = row0 + ty * 8 + m;
#pragma unroll
        for (int n = 0; n < 4; ++n) {
            int col = tx * 8 + 2 * n;
            float e0, e1; unpack2(acc[m][n], e0, e1);
            float v0 = e0 + bias[col], v1 = e1 + bias[col + 1];
            if (mid == 3) { v0 = sigmoidf_(v0); v1 = sigmoidf_(v1); }
            *(float2*)&outp[(size_t)row * CC + col] = make_float2(v0, v1);
        }
    }
}

// ====================== Kernel 2: alpha/beta ================================
__global__ __launch_bounds__(256) void ab_kernel(
    const float* __restrict__ x,
    const float* __restrict__ Wa, const float* __restrict__ ba,
    const float* __restrict__ Wb, const float* __restrict__ bb)
{
    const int warp = threadIdx.x >> 5, lane = threadIdx.x & 31;
    const int row  = blockIdx.x * 8 + warp;
    const float* xr = x + (size_t)row * DIMK;
    float accA = 0.0f, accB = 0.0f;
#pragma unroll
    for (int it = 0; it < 8; ++it) {
        int kidx = it * 128 + lane * 4;
        float4 xv = *(const float4*)(xr + kidx);
        float4 wa = *(const float4*)(Wa + kidx);
        float4 wb = *(const float4*)(Wb + kidx);
        accA += xv.x * wa.x + xv.y * wa.y + xv.z * wa.z + xv.w * wa.w;
        accB += xv.x * wb.x + xv.y * wb.y + xv.z * wb.z + xv.w * wb.w;
    }
#pragma unroll
    for (int o = 16; o; o >>= 1) {
        accA += __shfl_xor_sync(0xffffffffu, accA, o);
        accB += __shfl_xor_sync(0xffffffffu, accB, o);
    }
    if (lane == 0) {
        g_Al[row] = sigmoidf_(accA + ba[0]);
        g_Be[row] = sigmoidf_(accB + bb[0]);
    }
}

// ====================== Kernel 3: k normalize ===============================
__global__ __launch_bounds__(256) void knorm_kernel()
{
    const int warp = threadIdx.x >> 5, lane = threadIdx.x & 31;
    const int row  = blockIdx.x * 8 + warp;
    float* kp = g_K + (size_t)row * CC + lane * 4;
    float4 kv = *(float4*)kp;
    float ss = kv.x * kv.x + kv.y * kv.y + kv.z * kv.z + kv.w * kv.w;
#pragma unroll
    for (int o = 16; o; o >>= 1) ss += __shfl_xor_sync(0xffffffffu, ss, o);
    float scale = 1.0f / fmaxf(sqrtf(ss), 1e-12f);
    kv.x *= scale; kv.y *= scale; kv.z *= scale; kv.w *= scale;
    *(float4*)kp = kv;
}

// ====================== Kernel P: per-chunk precompute ======================
// gamma; A = b_t*(gam_t/gam_s)*(k_t.k_s) (s<t); forward-substitute
// U0 = (I+A)^-1 diag(b)V ; W = (I+A)^-1 diag(b*gam)K. Columns independent.
#define PREP_SMEM ((64*132 + 64*128 + 64*128 + 64*64 + 192) * 4)
__global__ __launch_bounds__(256) void prep_kernel()
{
    extern __shared__ float sh[];
    float* Kp  = sh;              // [64][132]
    float* U0s = Kp  + 64 * 132;
    float* Wsh = U0s + 64 * 128;
    float* Am  = Wsh + 64 * 128;  // [64][64]
    float* gam = Am  + 64 * 64;
    float* asv = gam + 64;
    float* bsv = asv + 64;

    const int ch = blockIdx.x, tid = threadIdx.x;
    const size_t rbase = (size_t)ch * LCH, eb = rbase * CC;

    for (int x = tid; x < LCH * CC; x += 256) {
        int t = x >> 7, i = x & 127;
        Kp[t * 132 + i] = g_K[eb + x];
    }
    if (tid < 64) { asv[tid] = g_Al[rbase + tid]; bsv[tid] = g_Be[rbase + tid]; }
    __syncthreads();
    if (tid == 0) {
        float g = 1.0f;
        for (int t = 0; t < 64; ++t) { g *= asv[t]; gam[t] = g; }
    }
    __syncthreads();

    {   // A matrix: thread -> t = tid>>2, 16 s values
        const int t = tid >> 2, s0 = (tid & 3) * 16;
        for (int m = 0; m < 16; ++m) {
            int s = s0 + m;
            float a0 = 0.f, a1 = 0.f, a2 = 0.f, a3 = 0.f;
            for (int i = 0; i < 128; i += 4) {
                float4 kt = *(float4*)&Kp[t * 132 + i];
                float4 ks = *(float4*)&Kp[s * 132 + i];
                a0 = fmaf(kt.x, ks.x, a0); a1 = fmaf(kt.y, ks.y, a1);
                a2 = fmaf(kt.z, ks.z, a2); a3 = fmaf(kt.w, ks.w, a3);
            }
            Am[t * 64 + s] = (s < t) ? bsv[t] * (gam[t] / gam[s]) * ((a0 + a1) + (a2 + a3)) : 0.0f;
        }
    }
    __syncthreads();

    {   // substitution: each thread owns one column of U0 or W; no barriers
        const int  i   = tid & 127;
        const bool isU = (tid < 128);
        float* X = isU ? U0s : Wsh;
        for (int t = 0; t < 64; ++t) {
            float rhs = isU ? bsv[t] * g_V[eb + (size_t)t * CC + i]
                            : (bsv[t] * gam[t]) * Kp[t * 132 + i];
            float a0 = 0.f, a1 = 0.f, a2 = 0.f, a3 = 0.f;
            int s = 0;
            for (; s + 4 <= t; s += 4) {
                a0 = fmaf(Am[t * 64 + s + 0], X[(s + 0) * 128 + i], a0);
                a1 = fmaf(Am[t * 64 + s + 1], X[(s + 1) * 128 + i], a1);
                a2 = fmaf(Am[t * 64 + s + 2], X[(s + 2) * 128 + i], a2);
                a3 = fmaf(Am[t * 64 + s + 3], X[(s + 3) * 128 + i], a3);
            }
            for (; s < t; ++s) a0 = fmaf(Am[t * 64 + s], X[s * 128 + i], a0);
            X[t * 128 + i] = rhs - ((a0 + a1) + (a2 + a3));
        }
    }
    __syncthreads();
    for (int x = tid; x < LCH * CC; x += 256) {
        g_U0[eb + x] = U0s[x];
        g_W [eb + x] = Wsh[x];
    }
    if (tid < 64) g_Gm[rbase + tid] = gam[tid];
}

// ====================== Kernel S: sequential chunk recurrence ===============
// Per chunk: store S_c; U = U0 - W S^T; S <- gamL*S + Y^T K (Y = diag(gamL/gam)U)
// Ssh[j][i] = S[i][j].
#define SEQ_SMEM ((16384 + 16384 + 8192 + 8192 + 64) * 4)
__global__ __launch_bounds__(256, 1) void seq_kernel()
{
    extern __shared__ float sh[];
    float* Ssh = sh;             // 128*128  [j][i]
    float* Wd  = Ssh + 16384;    // 64*256   -W duplicated pairs
    float* Ks  = Wd  + 16384;    // 64*128
    float* Ysh = Ks  + 8192;     // 64*128
    float* gam = Ysh + 8192;     // 64

    const int b = blockIdx.x, tid = threadIdx.x;
    for (int x = tid; x < 16384; x += 256) Ssh[x] = 0.0f;

    const int t0 = (tid >> 4) * 4;        // GEMM1 rows
    const int i0 = (tid & 15) * 8;        // cols
    const int j0 = (tid >> 4) * 8;        // GEMM2 rows

    for (int c = 0; c < NCH; ++c) {
        const size_t ch = (size_t)(b * NCH + c);
        const size_t eb = ch * LCH * CC;
        __syncthreads();
        // chunk-start state out
        for (int x = tid * 4; x < 16384; x += 1024)
            *(float4*)&g_Sc[ch * 16384 + x] = *(float4*)&Ssh[x];
        // load -W (dup) and K
        for (int x = tid; x < 2048; x += 256) {
            int base = x * 4, t = base >> 7, j = base & 127;
            float4 w4 = *(const float4*)&g_W[eb + base];
            *(float4*)&Wd[t * 256 + 2 * j]     = make_float4(-w4.x, -w4.x, -w4.y, -w4.y);
            *(float4*)&Wd[t * 256 + 2 * j + 4] = make_float4(-w4.z, -w4.z, -w4.w, -w4.w);
            *(float4*)&Ks[base] = *(const float4*)&g_K[eb + base];
        }
        if (tid < 64) gam[tid] = g_Gm[ch * LCH + tid];
        float4 u0r[4][2];
#pragma unroll
        for (int a = 0; a < 4; ++a) {
            u0r[a][0] = *(const float4*)&g_U0[eb + (size_t)(t0 + a) * CC + i0];
            u0r[a][1] = *(const float4*)&g_U0[eb + (size_t)(t0 + a) * CC + i0 + 4];
        }
        __syncthreads();
        const float gamL = gam[63];

        // GEMM1: U[t][i] = U0 - sum_j W[t][j]*Ssh[j][i]
        ull acc[4][4];
#pragma unroll
        for (int a = 0; a < 4; ++a) {
            acc[a][0] = pack2(u0r[a][0].x, u0r[a][0].y);
            acc[a][1] = pack2(u0r[a][0].z, u0r[a][0].w);
            acc[a][2] = pack2(u0r[a][1].x, u0r[a][1].y);
            acc[a][3] = pack2(u0r[a][1].z, u0r[a][1].w);
        }
        for (int j = 0; j < 128; ++j) {
            ull w0 = *(ull*)&Wd[(t0 + 0) * 256 + 2 * j];
            ull w1 = *(ull*)&Wd[(t0 + 1) * 256 + 2 * j];
            ull w2 = *(ull*)&Wd[(t0 + 2) * 256 + 2 * j];
            ull w3 = *(ull*)&Wd[(t0 + 3) * 256 + 2 * j];
            ulonglong2 sA = *(ulonglong2*)&Ssh[j * 128 + i0];
            ulonglong2 sB = *(ulonglong2*)&Ssh[j * 128 + i0 + 4];
            ull sp[4] = {sA.x, sA.y, sB.x, sB.y};
#pragma unroll
            for (int p = 0; p < 4; ++p) {
                acc[0][p] = fma2(w0, sp[p], acc[0][p]);
                acc[1][p] = fma2(w1, sp[p], acc[1][p]);
                acc[2][p] = fma2(w2, sp[p], acc[2][p]);
                acc[3][p] = fma2(w3, sp[p], acc[3][p]);
            }
        }
#pragma unroll
        for (int a = 0; a < 4; ++a) {
            int t = t0 + a;
            float rt = gamL / gam[t];
            float f[8];
            unpack2(acc[a][0], f[0], f[1]); unpack2(acc[a][1], f[2], f[3]);
            unpack2(acc[a][2], f[4], f[5]); unpack2(acc[a][3], f[6], f[7]);
            *(float4*)&g_U[eb + (size_t)t * CC + i0]     = make_float4(f[0], f[1], f[2], f[3]);
            *(float4*)&g_U[eb + (size_t)t * CC + i0 + 4] = make_float4(f[4], f[5], f[6], f[7]);
            *(float4*)&Ysh[t * 128 + i0]     = make_float4(rt * f[0], rt * f[1], rt * f[2], rt * f[3]);
            *(float4*)&Ysh[t * 128 + i0 + 4] = make_float4(rt * f[4], rt * f[5], rt * f[6], rt * f[7]);
        }
        __syncthreads();

        // GEMM2: Ssh[j][i] = gamL*Ssh[j][i] + sum_t K[t][j]*Y[t][i]
        ull s2[8][4];
        const ull gl2 = pack2(gamL, gamL);
#pragma unroll
        for (int jj = 0; jj < 8; ++jj) {
            ulonglong2 oA = *(ulonglong2*)&Ssh[(j0 + jj) * 128 + i0];
            ulonglong2 oB = *(ulonglong2*)&Ssh[(j0 + jj) * 128 + i0 + 4];
            s2[jj][0] = mul2(oA.x, gl2); s2[jj][1] = mul2(oA.y, gl2);
            s2[jj][2] = mul2(oB.x, gl2); s2[jj][3] = mul2(oB.y, gl2);
        }
        for (int t = 0; t < 64; ++t) {
            float4 kA = *(float4*)&Ks[t * 128 + j0];
            float4 kB = *(float4*)&Ks[t * 128 + j0 + 4];
            ull kp[8] = {pack2(kA.x, kA.x), pack2(kA.y, kA.y), pack2(kA.z, kA.z), pack2(kA.w, kA.w),
                         pack2(kB.x, kB.x), pack2(kB.y, kB.y), pack2(kB.z, kB.z), pack2(kB.w, kB.w)};
            ulonglong2 yA = *(ulonglong2*)&Ysh[t * 128 + i0];
            ulonglong2 yB = *(ulonglong2*)&Ysh[t * 128 + i0 + 4];
            ull yp[4] = {yA.x, yA.y, yB.x, yB.y};
#pragma unroll
            for (int jj = 0; jj < 8; ++jj)
#pragma unroll
                for (int p = 0; p < 4; ++p)
                    s2[jj][p] = fma2(kp[jj], yp[p], s2[jj][p]);
        }
#pragma unroll
        for (int jj = 0; jj < 8; ++jj) {
            *(ulonglong2*)&Ssh[(j0 + jj) * 128 + i0]     = make_ulonglong2(s2[jj][0], s2[jj][1]);
            *(ulonglong2*)&Ssh[(j0 + jj) * 128 + i0 + 4] = make_ulonglong2(s2[jj][2], s2[jj][3]);
        }
    }
}

// ====================== Kernel O: per-chunk outputs =========================
// O[t][j] = gate * ( gam_t*(Q S0)[t][j] + sum_{s<=t} (gam_t/gam_s)(q_t.u_s) K[s][j] )
#define OUTP_SMEM ((128*132 + 64*132 + 128*68 + 64*128 + 64*68 + 64) * 4)
__global__ __launch_bounds__(256) void outp_kernel()
{
    extern __shared__ float sh[];
    float* S2t = sh;               // [i][j] = S0[i][j]
    float* Qs  = S2t + 128 * 132;  // [t][i]
    float* Ut  = Qs  + 64 * 132;   // [i][t] = U[t][i]
    float* Ks  = Ut  + 128 * 68;   // [s][j]
    float* Ps  = Ks  + 64 * 128;   // [t][s]
    float* gam = Ps  + 64 * 68;

    const int ch = blockIdx.x, tid = threadIdx.x;
    const size_t eb = (size_t)ch * LCH * CC;

    for (int x = tid; x < 16384; x += 256) {
        int j = x >> 7, i = x & 127;
        S2t[i * 132 + j] = g_Sc[(size_t)ch * 16384 + x];   // g_Sc[j][i]=S[i][j]
    }
    for (int x = tid; x < 8192; x += 256) {
        int t = x >> 7, i = x & 127;
        Qs[t * 132 + i] = g_Q[eb + x];
        Ut[i * 68 + t]  = g_U[eb + x];
        Ks[x]           = g_K[eb + x];
    }
    if (tid < 64) gam[tid] = g_Gm[(size_t)ch * LCH + tid];
    __syncthreads();

    {   // P[t][s]
        const int t0 = (tid >> 4) * 4, s0 = (tid & 15) * 4;
        float pa[4][4];
#pragma unroll
        for (int a = 0; a < 4; ++a)
#pragma unroll
            for (int e = 0; e < 4; ++e) pa[a][e] = 0.0f;
        for (int i = 0; i < 128; ++i) {
            float qv[4];
#pragma unroll
            for (int a = 0; a < 4; ++a) qv[a] = Qs[(t0 + a) * 132 + i];
            float4 dv = *(float4*)&Ut[i * 68 + s0];
            float dr[4] = {dv.x, dv.y, dv.z, dv.w};
#pragma unroll
            for (int a = 0; a < 4; ++a)
#pragma unroll
                for (int e = 0; e < 4; ++e) pa[a][e] = fmaf(qv[a], dr[e], pa[a][e]);
        }
#pragma unroll
        for (int a = 0; a < 4; ++a) {
            int t = t0 + a;
#pragma unroll
            for (int e = 0; e < 4; ++e) {
                int s = s0 + e;
                Ps[t * 68 + s] = (s <= t) ? (gam[t] / gam[s]) * pa[a][e] : 0.0f;
            }
        }
    }
    __syncthreads();

    {   // O[t][j]
        const int t0 = (tid >> 4) * 4, j0 = (tid & 15) * 8;
        ull oa[4][4];
#pragma unroll
        for (int a = 0; a < 4; ++a)
#pragma unroll
            for (int p = 0; p < 4; ++p) oa[a][p] = 0ull;
        for (int i = 0; i < 128; ++i) {
            ull qd[4];
#pragma unroll
            for (int a = 0; a < 4; ++a) {
                float q = Qs[(t0 + a) * 132 + i];
                qd[a] = pack2(q, q);
            }
            ulonglong2 sA = *(ulonglong2*)&S2t[i * 132 + j0];
            ulonglong2 sB = *(ulonglong2*)&S2t[i * 132 + j0 + 4];
            ull sp[4] = {sA.x, sA.y, sB.x, sB.y};
#pragma unroll
            for (int a = 0; a < 4; ++a)
#pragma unroll
                for (int p = 0; p < 4; ++p) oa[a][p] = fma2(qd[a], sp[p], oa[a][p]);
        }
#pragma unroll
        for (int a = 0; a < 4; ++a) {
            const ull g2 = pack2(gam[t0 + a], gam[t0 + a]);
#pragma unroll
            for (int p = 0; p < 4; ++p) oa[a][p] = mul2(oa[a][p], g2);
        }
        for (int s = 0; s < 64; ++s) {
            ull pd[4];
#pragma unroll
            for (int a = 0; a < 4; ++a) {
                float pv = Ps[(t0 + a) * 68 + s];
                pd[a] = pack2(pv, pv);
            }
            ulonglong2 kA = *(ulonglong2*)&Ks[s * 128 + j0];
            ulonglong2 kB = *(ulonglong2*)&Ks[s * 128 + j0 + 4];
            ull kp[4] = {kA.x, kA.y, kB.x, kB.y};
#pragma unroll
            for (int a = 0; a < 4; ++a)
#pragma unroll
                for (int p = 0; p < 4; ++p) oa[a][p] = fma2(pd[a], kp[p], oa[a][p]);
        }
#pragma unroll
        for (int a = 0; a < 4; ++a) {
            const size_t row = eb + (size_t)(t0 + a) * CC + j0;
            float f[8];
            unpack2(oa[a][0], f[0], f[1]); unpack2(oa[a][1], f[2], f[3]);
            unpack2(oa[a][2], f[4], f[5]); unpack2(oa[a][3], f[6], f[7]);
            float4 gA = *(const float4*)&g_G[row];
            float4 gB = *(const float4*)&g_G[row + 4];
            *(float4*)&g_O[row]     = make_float4(f[0] * gA.x, f[1] * gA.y, f[2] * gA.z, f[3] * gA.w);
            *(float4*)&g_O[row + 4] = make_float4(f[4] * gB.x, f[5] * gB.y, f[6] * gB.z, f[7] * gB.w);
        }
    }
}

// ====================== Kernel 5: out = O @ Wo + bo =========================
__global__ __launch_bounds__(256) void out_gemm(
    const float* __restrict__ Wo, const float* __restrict__ bo,
    float* __restrict__ out)
{
    __shared__ __align__(16) float As2[16][256];
    __shared__ __align__(16) float Bs[16][128];
    const int row0 = blockIdx.x * 128, col0 = blockIdx.y * 128;
    const int tid = threadIdx.x, tx = tid & 15, ty = tid >> 4;
    const int lr = tid >> 2, lc = (tid & 3) * 4, bkk = tid >> 5, bn = (tid & 31) * 4;

    ull acc[8][4];
#pragma unroll
    for (int m = 0; m < 8; ++m)
#pragma unroll
        for (int n = 0; n < 4; ++n) acc[m][n] = 0ull;

    float4 aR[2], bR[2];
#pragma unroll
    for (int h = 0; h < 2; ++h) {
        aR[h] = *(const float4*)(g_O + (size_t)(row0 + lr + h * 64) * CC + lc);
        bR[h] = *(const float4*)(Wo + (size_t)(bkk + h * 8) * DIMK + col0 + bn);
    }
    for (int k0 = 0; k0 < CC; k0 += 16) {
#pragma unroll
        for (int h = 0; h < 2; ++h) {
            int r = lr + h * 64;
            *(float2*)&As2[lc + 0][2 * r] = make_float2(aR[h].x, aR[h].x);
            *(float2*)&As2[lc + 1][2 * r] = make_float2(aR[h].y, aR[h].y);
            *(float2*)&As2[lc + 2][2 * r] = make_float2(aR[h].z, aR[h].z);
            *(float2*)&As2[lc + 3][2 * r] = make_float2(aR[h].w, aR[h].w);
            *(float4*)&Bs[bkk + h * 8][bn] = bR[h];
        }
        __syncthreads();
        if (k0 + 16 < CC) {
#pragma unroll
            for (int h = 0; h < 2; ++h) {
                aR[h] = *(const float4*)(g_O + (size_t)(row0 + lr + h * 64) * CC + k0 + 16 + lc);
                bR[h] = *(const float4*)(Wo + (size_t)(k0 + 16 + bkk + h * 8) * DIMK + col0 + bn);
            }
        }
#pragma unroll
        for (int kk = 0; kk < 16; ++kk) {
            const ulonglong2* ap = (const ulonglong2*)&As2[kk][2 * (ty * 8)];
            const ulonglong2* bp = (const ulonglong2*)&Bs[kk][tx * 8];
            ulonglong2 a01 = ap[0], a23 = ap[1], a45 = ap[2], a67 = ap[3];
            ulonglong2 b01 = bp[0], b23 = bp[1];
            ull ar[8] = {a01.x, a01.y, a23.x, a23.y, a45.x, a45.y, a67.x, a67.y};
            ull br[4] = {b01.x, b01.y, b23.x, b23.y};
#pragma unroll
            for (int m = 0; m < 8; ++m)
#pragma unroll
                for (int n = 0; n < 4; ++n)
                    acc[m][n] = fma2(ar[m], br[n], acc[m][n]);
        }
        __syncthreads();
    }
#pragma unroll
    for (int m = 0; m < 8; ++m) {
        int row = row0 + ty * 8 + m;
#pragma unroll
        for (int n = 0; n < 4; ++n) {
            int col = col0 + tx * 8 + 2 * n;
            float e0, e1; unpack2(acc[m][n], e0, e1);
            *(float2*)&out[(size_t)row * DIMK + col] =
                make_float2(e0 + bo[col], e1 + bo[col + 1]);
        }
    }
}

// ===========================================================================
extern "C" void kernel_launch(void* const* d_in, const int* in_sizes, int n_in,
                              void* d_out, int out_size)
{
    const float* x  = (const float*)d_in[0];
    const float* Wq = (const float*)d_in[1];  const float* bq = (const float*)d_in[2];
    const float* Wk = (const float*)d_in[3];  const float* bk = (const float*)d_in[4];
    const float* Wv = (const float*)d_in[5];  const float* bv = (const float*)d_in[6];
    const float* Wa = (const float*)d_in[7];  const float* ba = (const float*)d_in[8];
    const float* Wb = (const float*)d_in[9];  const float* bb = (const float*)d_in[10];
    const float* Wg = (const float*)d_in[11]; const float* bg = (const float*)d_in[12];
    const float* Wo = (const float*)d_in[13]; const float* bo = (const float*)d_in[14];
    float* out = (float*)d_out;

    static int attr_done = 0;
    if (!attr_done) {
        cudaFuncSetAttribute(prep_kernel, cudaFuncAttributeMaxDynamicSharedMemorySize, PREP_SMEM);
        cudaFuncSetAttribute(seq_kernel,  cudaFuncAttributeMaxDynamicSharedMemorySize, SEQ_SMEM);
        cudaFuncSetAttribute(outp_kernel, cudaFuncAttributeMaxDynamicSharedMemorySize, OUTP_SMEM);
        attr_done = 1;
    }

    proj_gemm<<<dim3(128, 4), 256>>>(x, Wq, Wk, Wv, Wg, bq, bk, bv, bg);
    ab_kernel<<<2048, 256>>>(x, Wa, ba, Wb, bb);
    knorm_kernel<<<2048, 256>>>();
    prep_kernel<<<NCHT, 256, PREP_SMEM>>>();
    seq_kernel<<<BB, 256, SEQ_SMEM>>>();
    outp_kernel<<<NCHT, 256, OUTP_SMEM>>>();
    out_gemm<<<dim3(128, 8), 256>>>(Wo, bo, out);
}

// round 9
// speedup vs baseline: 2.0284x; 1.3482x over previous
#include <cuda_runtime.h>
#include <cuda_bf16.h>
#include <math.h>

#define DIMK 1024
#define CC   128
#define BB   8
#define TT   2048
#define ROWS (BB*TT)
#define LCH  64
#define NCH  (TT/LCH)     // 32
#define NCHT (BB*NCH)     // 256

typedef unsigned long long ull;

__device__ float g_Q [ROWS*CC];
__device__ float g_K [ROWS*CC];
__device__ float g_V [ROWS*CC];
__device__ float g_G [ROWS*CC];
__device__ float g_O [ROWS*CC];
__device__ float g_Al[ROWS];
__device__ float g_Be[ROWS];
__device__ float g_U0[NCHT*LCH*CC];
__device__ float g_W [NCHT*LCH*CC];
__device__ float g_U [NCHT*LCH*CC];
__device__ float g_Sc[NCHT*CC*CC];     // chunk-start state, [j][i] = S[i][j]
__device__ float g_Gm[NCHT*LCH];

__device__ __forceinline__ float sigmoidf_(float x) { return 1.0f / (1.0f + expf(-x)); }
__device__ __forceinline__ ull pack2(float lo, float hi) {
    ull r; asm("mov.b64 %0, {%1, %2};" : "=l"(r) : "f"(lo), "f"(hi)); return r;
}
__device__ __forceinline__ void unpack2(ull v, float& lo, float& hi) {
    asm("mov.b64 {%0, %1}, %2;" : "=f"(lo), "=f"(hi) : "l"(v));
}
__device__ __forceinline__ ull fma2(ull a, ull b, ull c) {
    ull d; asm("fma.rn.f32x2 %0, %1, %2, %3;" : "=l"(d) : "l"(a), "l"(b), "l"(c)); return d;
}
__device__ __forceinline__ ull mul2(ull a, ull b) {
    ull d; asm("mul.rn.f32x2 %0, %1, %2;" : "=l"(d) : "l"(a), "l"(b)); return d;
}

// ====================== Kernel 1: projections (f32x2 SGEMM) ================
__global__ __launch_bounds__(256) void proj_gemm(
    const float* __restrict__ x,
    const float* __restrict__ Wq, const float* __restrict__ Wk,
    const float* __restrict__ Wv, const float* __restrict__ Wg,
    const float* __restrict__ bq, const float* __restrict__ bk,
    const float* __restrict__ bv, const float* __restrict__ bg)
{
    __shared__ __align__(16) float As2[16][256];
    __shared__ __align__(16) float Bs[16][128];
    const int mid  = blockIdx.y;
    const float* W    = (mid == 0) ? Wq : (mid == 1) ? Wk : (mid == 2) ? Wv : Wg;
    const float* bias = (mid == 0) ? bq : (mid == 1) ? bk : (mid == 2) ? bv : bg;
    float* outp       = (mid == 0) ? g_Q : (mid == 1) ? g_K : (mid == 2) ? g_V : g_G;
    const int row0 = blockIdx.x * 128;
    const int tid = threadIdx.x, tx = tid & 15, ty = tid >> 4;
    const int lr = tid >> 2, lc = (tid & 3) * 4, bkk = tid >> 5, bn = (tid & 31) * 4;

    ull acc[8][4];
#pragma unroll
    for (int m = 0; m < 8; ++m)
#pragma unroll
        for (int n = 0; n < 4; ++n) acc[m][n] = 0ull;

    float4 aR[2], bR[2];
#pragma unroll
    for (int h = 0; h < 2; ++h) {
        aR[h] = *(const float4*)(x + (size_t)(row0 + lr + h * 64) * DIMK + lc);
        bR[h] = *(const float4*)(W + (size_t)(bkk + h * 8) * CC + bn);
    }
    for (int k0 = 0; k0 < DIMK; k0 += 16) {
#pragma unroll
        for (int h = 0; h < 2; ++h) {
            int r = lr + h * 64;
            *(float2*)&As2[lc + 0][2 * r] = make_float2(aR[h].x, aR[h].x);
            *(float2*)&As2[lc + 1][2 * r] = make_float2(aR[h].y, aR[h].y);
            *(float2*)&As2[lc + 2][2 * r] = make_float2(aR[h].z, aR[h].z);
            *(float2*)&As2[lc + 3][2 * r] = make_float2(aR[h].w, aR[h].w);
            *(float4*)&Bs[bkk + h * 8][bn] = bR[h];
        }
        __syncthreads();
        if (k0 + 16 < DIMK) {
#pragma unroll
            for (int h = 0; h < 2; ++h) {
                aR[h] = *(const float4*)(x + (size_t)(row0 + lr + h * 64) * DIMK + k0 + 16 + lc);
                bR[h] = *(const float4*)(W + (size_t)(k0 + 16 + bkk + h * 8) * CC + bn);
            }
        }
#pragma unroll
        for (int kk = 0; kk < 16; ++kk) {
            const ulonglong2* ap = (const ulonglong2*)&As2[kk][2 * (ty * 8)];
            const ulonglong2* bp = (const ulonglong2*)&Bs[kk][tx * 8];
            ulonglong2 a01 = ap[0], a23 = ap[1], a45 = ap[2], a67 = ap[3];
            ulonglong2 b01 = bp[0], b23 = bp[1];
            ull ar[8] = {a01.x, a01.y, a23.x, a23.y, a45.x, a45.y, a67.x, a67.y};
            ull br[4] = {b01.x, b01.y, b23.x, b23.y};
#pragma unroll
            for (int m = 0; m < 8; ++m)
#pragma unroll
                for (int n = 0; n < 4; ++n)
                    acc[m][n] = fma2(ar[m], br[n], acc[m][n]);
        }
        __syncthreads();
    }
#pragma unroll
    for (int m = 0; m < 8; ++m) {
        int row = row0 + ty * 8 + m;
#pragma unroll
        for (int n = 0; n < 4; ++n) {
            int col = tx * 8 + 2 * n;
            float e0, e1; unpack2(acc[m][n], e0, e1);
            float v0 = e0 + bias[col], v1 = e1 + bias[col + 1];
            if (mid == 3) { v0 = sigmoidf_(v0); v1 = sigmoidf_(v1); }
            *(float2*)&outp[(size_t)row * CC + col] = make_float2(v0, v1);
        }
    }
}

// ====================== Kernel 2: alpha/beta ================================
__global__ __launch_bounds__(256) void ab_kernel(
    const float* __restrict__ x,
    const float* __restrict__ Wa, const float* __restrict__ ba,
    const float* __restrict__ Wb, const float* __restrict__ bb)
{
    const int warp = threadIdx.x >> 5, lane = threadIdx.x & 31;
    const int row  = blockIdx.x * 8 + warp;
    const float* xr = x + (size_t)row * DIMK;
    float accA = 0.0f, accB = 0.0f;
#pragma unroll
    for (int it = 0; it < 8; ++it) {
        int kidx = it * 128 + lane * 4;
        float4 xv = *(const float4*)(xr + kidx);
        float4 wa = *(const float4*)(Wa + kidx);
        float4 wb = *(const float4*)(Wb + kidx);
        accA += xv.x * wa.x + xv.y * wa.y + xv.z * wa.z + xv.w * wa.w;
        accB += xv.x * wb.x + xv.y * wb.y + xv.z * wb.z + xv.w * wb.w;
    }
#pragma unroll
    for (int o = 16; o; o >>= 1) {
        accA += __shfl_xor_sync(0xffffffffu, accA, o);
        accB += __shfl_xor_sync(0xffffffffu, accB, o);
    }
    if (lane == 0) {
        g_Al[row] = sigmoidf_(accA + ba[0]);
        g_Be[row] = sigmoidf_(accB + bb[0]);
    }
}

// ====================== Kernel 3: k normalize ===============================
__global__ __launch_bounds__(256) void knorm_kernel()
{
    const int warp = threadIdx.x >> 5, lane = threadIdx.x & 31;
    const int row  = blockIdx.x * 8 + warp;
    float* kp = g_K + (size_t)row * CC + lane * 4;
    float4 kv = *(float4*)kp;
    float ss = kv.x * kv.x + kv.y * kv.y + kv.z * kv.z + kv.w * kv.w;
#pragma unroll
    for (int o = 16; o; o >>= 1) ss += __shfl_xor_sync(0xffffffffu, ss, o);
    float scale = 1.0f / fmaxf(sqrtf(ss), 1e-12f);
    kv.x *= scale; kv.y *= scale; kv.z *= scale; kv.w *= scale;
    *(float4*)kp = kv;
}

// ====================== Kernel P: per-chunk precompute ======================
// Substitution column lives in REGISTERS (each thread owns one column).
#define PREP_SMEM ((64*132 + 64*64 + 192) * 4)
__global__ __launch_bounds__(256) void prep_kernel()
{
    extern __shared__ float sh[];
    float* Kp  = sh;              // [64][132]
    float* Am  = Kp + 64 * 132;   // [64][64]
    float* gam = Am + 4096;
    float* asv = gam + 64;
    float* bsv = asv + 64;

    const int ch = blockIdx.x, tid = threadIdx.x;
    const size_t rbase = (size_t)ch * LCH, eb = rbase * CC;

    for (int x = tid; x < LCH * CC; x += 256) {
        int t = x >> 7, i = x & 127;
        Kp[t * 132 + i] = g_K[eb + x];
    }
    if (tid < 64) { asv[tid] = g_Al[rbase + tid]; bsv[tid] = g_Be[rbase + tid]; }
    __syncthreads();
    if (tid == 0) {
        float g = 1.0f;
        for (int t = 0; t < 64; ++t) { g *= asv[t]; gam[t] = g; }
    }
    __syncthreads();

    {   // A[t][s] = b_t*(gam_t/gam_s)*(k_t.k_s), s<t
        const int t = tid >> 2, s0 = (tid & 3) * 16;
        for (int m = 0; m < 16; ++m) {
            int s = s0 + m;
            float a0 = 0.f, a1 = 0.f, a2 = 0.f, a3 = 0.f;
            for (int i = 0; i < 128; i += 4) {
                float4 kt = *(float4*)&Kp[t * 132 + i];
                float4 ks = *(float4*)&Kp[s * 132 + i];
                a0 = fmaf(kt.x, ks.x, a0); a1 = fmaf(kt.y, ks.y, a1);
                a2 = fmaf(kt.z, ks.z, a2); a3 = fmaf(kt.w, ks.w, a3);
            }
            Am[t * 64 + s] = (s < t) ? bsv[t] * (gam[t] / gam[s]) * ((a0 + a1) + (a2 + a3)) : 0.0f;
        }
    }
    __syncthreads();

    {   // register-resident forward substitution, fully unrolled triangular
        const int  i   = tid & 127;
        const bool isU = (tid < 128);
        float X[64];
#pragma unroll
        for (int t = 0; t < 64; ++t) {
            float rhs = isU ? bsv[t] * g_V[eb + (size_t)t * CC + i]
                            : (bsv[t] * gam[t]) * Kp[t * 132 + i];
            float a0 = 0.f, a1 = 0.f, a2 = 0.f, a3 = 0.f;
#pragma unroll
            for (int s = 0; s + 4 <= t; s += 4) {
                a0 = fmaf(Am[t * 64 + s + 0], X[s + 0], a0);
                a1 = fmaf(Am[t * 64 + s + 1], X[s + 1], a1);
                a2 = fmaf(Am[t * 64 + s + 2], X[s + 2], a2);
                a3 = fmaf(Am[t * 64 + s + 3], X[s + 3], a3);
            }
#pragma unroll
            for (int s = t & ~3; s < t; ++s)
                a0 = fmaf(Am[t * 64 + s], X[s], a0);
            X[t] = rhs - ((a0 + a1) + (a2 + a3));
        }
        float* dst = isU ? g_U0 : g_W;
#pragma unroll
        for (int t = 0; t < 64; ++t)
            dst[eb + (size_t)t * CC + i] = X[t];
    }
    if (tid < 64) g_Gm[rbase + tid] = gam[tid];
}

// ====================== Kernel S: sequential chunk recurrence ===============
// 4 CTAs per batch, each owning a 32-column slice of the state (index i).
// Ssh[j][ii] = S[i][j], ii = i - slice*32. No cross-CTA communication.
#define SEQ_SMEM ((128*32 + 64*260 + 64*260 + 64*32 + 64) * 4)
__global__ __launch_bounds__(256, 1) void seq_kernel()
{
    extern __shared__ float sh[];
    float* Ssh = sh;               // [j][ii] 128*32
    float* Wd  = Ssh + 4096;       // -W dup pairs, row stride 260
    float* Kd  = Wd + 64 * 260;    // K dup pairs, row stride 260
    float* Ysh = Kd + 64 * 260;    // [t][ii] 64*32
    float* gam = Ysh + 2048;

    const int b   = blockIdx.x >> 2;
    const int sl  = blockIdx.x & 3;
    const int tid = threadIdx.x;
    const int icol0 = sl * 32;

    for (int x = tid; x < 4096; x += 256) Ssh[x] = 0.0f;

    const int t1  = tid >> 2;            // GEMM1: one t-row per thread
    const int ii0 = (tid & 3) * 8;       // 8 state-cols (4 packed pairs)
    const int j2  = (tid >> 2) * 2;      // GEMM2: two j-rows per thread

    for (int c = 0; c < NCH; ++c) {
        const size_t ch = (size_t)(b * NCH + c);
        const size_t eb = ch * LCH * CC;
        __syncthreads();

        // chunk-start state slice -> g_Sc[ch][j][icol0+ii]
        for (int x = tid; x < 1024; x += 256) {
            int j = x >> 3, ii = (x & 7) * 4;
            *(float4*)&g_Sc[ch * 16384 + (size_t)j * 128 + icol0 + ii] =
                *(float4*)&Ssh[j * 32 + ii];
        }
        // stage -W (dup) and K (dup)
        for (int x = tid; x < 2048; x += 256) {
            int base = x * 4, t = base >> 7, j = base & 127;
            float4 w4 = *(const float4*)&g_W[eb + base];
            *(float4*)&Wd[t * 260 + 2 * j]     = make_float4(-w4.x, -w4.x, -w4.y, -w4.y);
            *(float4*)&Wd[t * 260 + 2 * j + 4] = make_float4(-w4.z, -w4.z, -w4.w, -w4.w);
            float4 k4 = *(const float4*)&g_K[eb + base];
            *(float4*)&Kd[t * 260 + 2 * j]     = make_float4(k4.x, k4.x, k4.y, k4.y);
            *(float4*)&Kd[t * 260 + 2 * j + 4] = make_float4(k4.z, k4.z, k4.w, k4.w);
        }
        if (tid < 64) gam[tid] = g_Gm[ch * LCH + tid];
        float4 u0a = *(const float4*)&g_U0[eb + (size_t)t1 * CC + icol0 + ii0];
        float4 u0b = *(const float4*)&g_U0[eb + (size_t)t1 * CC + icol0 + ii0 + 4];
        __syncthreads();
        const float gamL = gam[63];

        // GEMM1: U[t1][ii] = U0 - sum_j W[t1][j] * Ssh[j][ii]
        ull acc0 = pack2(u0a.x, u0a.y), acc1 = pack2(u0a.z, u0a.w);
        ull acc2 = pack2(u0b.x, u0b.y), acc3 = pack2(u0b.z, u0b.w);
#pragma unroll 4
        for (int j = 0; j < 128; ++j) {
            ull w = *(ull*)&Wd[t1 * 260 + 2 * j];
            ulonglong2 sA = *(ulonglong2*)&Ssh[j * 32 + ii0];
            ulonglong2 sB = *(ulonglong2*)&Ssh[j * 32 + ii0 + 4];
            acc0 = fma2(w, sA.x, acc0);
            acc1 = fma2(w, sA.y, acc1);
            acc2 = fma2(w, sB.x, acc2);
            acc3 = fma2(w, sB.y, acc3);
        }
        {
            float f0, f1, f2, f3, f4, f5, f6, f7;
            unpack2(acc0, f0, f1); unpack2(acc1, f2, f3);
            unpack2(acc2, f4, f5); unpack2(acc3, f6, f7);
            const float rt = gamL / gam[t1];
            *(float4*)&g_U[eb + (size_t)t1 * CC + icol0 + ii0]     = make_float4(f0, f1, f2, f3);
            *(float4*)&g_U[eb + (size_t)t1 * CC + icol0 + ii0 + 4] = make_float4(f4, f5, f6, f7);
            *(float4*)&Ysh[t1 * 32 + ii0]     = make_float4(rt * f0, rt * f1, rt * f2, rt * f3);
            *(float4*)&Ysh[t1 * 32 + ii0 + 4] = make_float4(rt * f4, rt * f5, rt * f6, rt * f7);
        }
        __syncthreads();

        // GEMM2: Ssh[j][ii] = gamL*Ssh + sum_t K[t][j]*Y[t][ii]
        ull s2[2][4];
        const ull gl2 = pack2(gamL, gamL);
#pragma unroll
        for (int jj = 0; jj < 2; ++jj) {
            ulonglong2 oA = *(ulonglong2*)&Ssh[(j2 + jj) * 32 + ii0];
            ulonglong2 oB = *(ulonglong2*)&Ssh[(j2 + jj) * 32 + ii0 + 4];
            s2[jj][0] = mul2(oA.x, gl2); s2[jj][1] = mul2(oA.y, gl2);
            s2[jj][2] = mul2(oB.x, gl2); s2[jj][3] = mul2(oB.y, gl2);
        }
#pragma unroll 4
        for (int t = 0; t < 64; ++t) {
            ull k0 = *(ull*)&Kd[t * 260 + 2 * j2];
            ull k1 = *(ull*)&Kd[t * 260 + 2 * j2 + 2];
            ulonglong2 yA = *(ulonglong2*)&Ysh[t * 32 + ii0];
            ulonglong2 yB = *(ulonglong2*)&Ysh[t * 32 + ii0 + 4];
            s2[0][0] = fma2(k0, yA.x, s2[0][0]); s2[0][1] = fma2(k0, yA.y, s2[0][1]);
            s2[0][2] = fma2(k0, yB.x, s2[0][2]); s2[0][3] = fma2(k0, yB.y, s2[0][3]);
            s2[1][0] = fma2(k1, yA.x, s2[1][0]); s2[1][1] = fma2(k1, yA.y, s2[1][1]);
            s2[1][2] = fma2(k1, yB.x, s2[1][2]); s2[1][3] = fma2(k1, yB.y, s2[1][3]);
        }
#pragma unroll
        for (int jj = 0; jj < 2; ++jj) {
            *(ulonglong2*)&Ssh[(j2 + jj) * 32 + ii0]     = make_ulonglong2(s2[jj][0], s2[jj][1]);
            *(ulonglong2*)&Ssh[(j2 + jj) * 32 + ii0 + 4] = make_ulonglong2(s2[jj][2], s2[jj][3]);
        }
    }
}

// ====================== Kernel O: per-chunk outputs =========================
#define OUTP_SMEM ((128*132 + 64*132 + 128*68 + 64*128 + 64*68 + 64) * 4)
__global__ __launch_bounds__(256) void outp_kernel()
{
    extern __shared__ float sh[];
    float* S2t = sh;               // [i][j] = S0[i][j]
    float* Qs  = S2t + 128 * 132;  // [t][i]
    float* Ut  = Qs  + 64 * 132;   // [i][t] = U[t][i]
    float* Ks  = Ut  + 128 * 68;   // [s][j]
    float* Ps  = Ks  + 64 * 128;   // [t][s]
    float* gam = Ps  + 64 * 68;

    const int ch = blockIdx.x, tid = threadIdx.x;
    const size_t eb = (size_t)ch * LCH * CC;

    for (int x = tid; x < 16384; x += 256) {
        int j = x >> 7, i = x & 127;
        S2t[i * 132 + j] = g_Sc[(size_t)ch * 16384 + x];
    }
    for (int x = tid; x < 8192; x += 256) {
        int t = x >> 7, i = x & 127;
        Qs[t * 132 + i] = g_Q[eb + x];
        Ut[i * 68 + t]  = g_U[eb + x];
        Ks[x]           = g_K[eb + x];
    }
    if (tid < 64) gam[tid] = g_Gm[(size_t)ch * LCH + tid];
    __syncthreads();

    {   // P[t][s]
        const int t0 = (tid >> 4) * 4, s0 = (tid & 15) * 4;
        float pa[4][4];
#pragma unroll
        for (int a = 0; a < 4; ++a)
#pragma unroll
            for (int e = 0; e < 4; ++e) pa[a][e] = 0.0f;
        for (int i = 0; i < 128; ++i) {
            float qv[4];
#pragma unroll
            for (int a = 0; a < 4; ++a) qv[a] = Qs[(t0 + a) * 132 + i];
            float4 dv = *(float4*)&Ut[i * 68 + s0];
            float dr[4] = {dv.x, dv.y, dv.z, dv.w};
#pragma unroll
            for (int a = 0; a < 4; ++a)
#pragma unroll
                for (int e = 0; e < 4; ++e) pa[a][e] = fmaf(qv[a], dr[e], pa[a][e]);
        }
#pragma unroll
        for (int a = 0; a < 4; ++a) {
            int t = t0 + a;
#pragma unroll
            for (int e = 0; e < 4; ++e) {
                int s = s0 + e;
                Ps[t * 68 + s] = (s <= t) ? (gam[t] / gam[s]) * pa[a][e] : 0.0f;
            }
        }
    }
    __syncthreads();

    {   // O[t][j]
        const int t0 = (tid >> 4) * 4, j0 = (tid & 15) * 8;
        ull oa[4][4];
#pragma unroll
        for (int a = 0; a < 4; ++a)
#pragma unroll
            for (int p = 0; p < 4; ++p) oa[a][p] = 0ull;
        for (int i = 0; i < 128; ++i) {
            ull qd[4];
#pragma unroll
            for (int a = 0; a < 4; ++a) {
                float q = Qs[(t0 + a) * 132 + i];
                qd[a] = pack2(q, q);
            }
            ulonglong2 sA = *(ulonglong2*)&S2t[i * 132 + j0];
            ulonglong2 sB = *(ulonglong2*)&S2t[i * 132 + j0 + 4];
            ull sp[4] = {sA.x, sA.y, sB.x, sB.y};
#pragma unroll
            for (int a = 0; a < 4; ++a)
#pragma unroll
                for (int p = 0; p < 4; ++p) oa[a][p] = fma2(qd[a], sp[p], oa[a][p]);
        }
#pragma unroll
        for (int a = 0; a < 4; ++a) {
            const ull g2 = pack2(gam[t0 + a], gam[t0 + a]);
#pragma unroll
            for (int p = 0; p < 4; ++p) oa[a][p] = mul2(oa[a][p], g2);
        }
        for (int s = 0; s < 64; ++s) {
            ull pd[4];
#pragma unroll
            for (int a = 0; a < 4; ++a) {
                float pv = Ps[(t0 + a) * 68 + s];
                pd[a] = pack2(pv, pv);
            }
            ulonglong2 kA = *(ulonglong2*)&Ks[s * 128 + j0];
            ulonglong2 kB = *(ulonglong2*)&Ks[s * 128 + j0 + 4];
            ull kp[4] = {kA.x, kA.y, kB.x, kB.y};
#pragma unroll
            for (int a = 0; a < 4; ++a)
#pragma unroll
                for (int p = 0; p < 4; ++p) oa[a][p] = fma2(pd[a], kp[p], oa[a][p]);
        }
#pragma unroll
        for (int a = 0; a < 4; ++a) {
            const size_t row = eb + (size_t)(t0 + a) * CC + j0;
            float f[8];
            unpack2(oa[a][0], f[0], f[1]); unpack2(oa[a][1], f[2], f[3]);
            unpack2(oa[a][2], f[4], f[5]); unpack2(oa[a][3], f[6], f[7]);
            float4 gA = *(const float4*)&g_G[row];
            float4 gB = *(const float4*)&g_G[row + 4];
            *(float4*)&g_O[row]     = make_float4(f[0] * gA.x, f[1] * gA.y, f[2] * gA.z, f[3] * gA.w);
            *(float4*)&g_O[row + 4] = make_float4(f[4] * gB.x, f[5] * gB.y, f[6] * gB.z, f[7] * gB.w);
        }
    }
}

// ====================== Kernel 5: out = O @ Wo + bo =========================
__global__ __launch_bounds__(256) void out_gemm(
    const float* __restrict__ Wo, const float* __restrict__ bo,
    float* __restrict__ out)
{
    __shared__ __align__(16) float As2[16][256];
    __shared__ __align__(16) float Bs[16][128];
    const int row0 = blockIdx.x * 128, col0 = blockIdx.y * 128;
    const int tid = threadIdx.x, tx = tid & 15, ty = tid >> 4;
    const int lr = tid >> 2, lc = (tid & 3) * 4, bkk = tid >> 5, bn = (tid & 31) * 4;

    ull acc[8][4];
#pragma unroll
    for (int m = 0; m < 8; ++m)
#pragma unroll
        for (int n = 0; n < 4; ++n) acc[m][n] = 0ull;

    float4 aR[2], bR[2];
#pragma unroll
    for (int h = 0; h < 2; ++h) {
        aR[h] = *(const float4*)(g_O + (size_t)(row0 + lr + h * 64) * CC + lc);
        bR[h] = *(const float4*)(Wo + (size_t)(bkk + h * 8) * DIMK + col0 + bn);
    }
    for (int k0 = 0; k0 < CC; k0 += 16) {
#pragma unroll
        for (int h = 0; h < 2; ++h) {
            int r = lr + h * 64;
            *(float2*)&As2[lc + 0][2 * r] = make_float2(aR[h].x, aR[h].x);
            *(float2*)&As2[lc + 1][2 * r] = make_float2(aR[h].y, aR[h].y);
            *(float2*)&As2[lc + 2][2 * r] = make_float2(aR[h].z, aR[h].z);
            *(float2*)&As2[lc + 3][2 * r] = make_float2(aR[h].w, aR[h].w);
            *(float4*)&Bs[bkk + h * 8][bn] = bR[h];
        }
        __syncthreads();
        if (k0 + 16 < CC) {
#pragma unroll
            for (int h = 0; h < 2; ++h) {
                aR[h] = *(const float4*)(g_O + (size_t)(row0 + lr + h * 64) * CC + k0 + 16 + lc);
                bR[h] = *(const float4*)(Wo + (size_t)(k0 + 16 + bkk + h * 8) * DIMK + col0 + bn);
            }
        }
#pragma unroll
        for (int kk = 0; kk < 16; ++kk) {
            const ulonglong2* ap = (const ulonglong2*)&As2[kk][2 * (ty * 8)];
            const ulonglong2* bp = (const ulonglong2*)&Bs[kk][tx * 8];
            ulonglong2 a01 = ap[0], a23 = ap[1], a45 = ap[2], a67 = ap[3];
            ulonglong2 b01 = bp[0], b23 = bp[1];
            ull ar[8] = {a01.x, a01.y, a23.x, a23.y, a45.x, a45.y, a67.x, a67.y};
            ull br[4] = {b01.x, b01.y, b23.x, b23.y};
#pragma unroll
            for (int m = 0; m < 8; ++m)
#pragma unroll
                for (int n = 0; n < 4; ++n)
                    acc[m][n] = fma2(ar[m], br[n], acc[m][n]);
        }
        __syncthreads();
    }
#pragma unroll
    for (int m = 0; m < 8; ++m) {
        int row = row0 + ty * 8 + m;
#pragma unroll
        for (int n = 0; n < 4; ++n) {
            int col = col0 + tx * 8 + 2 * n;
            float e0, e1; unpack2(acc[m][n], e0, e1);
            *(float2*)&out[(size_t)row * DIMK + col] =
                make_float2(e0 + bo[col], e1 + bo[col + 1]);
        }
    }
}

// ===========================================================================
extern "C" void kernel_launch(void* const* d_in, const int* in_sizes, int n_in,
                              void* d_out, int out_size)
{
    const float* x  = (const float*)d_in[0];
    const float* Wq = (const float*)d_in[1];  const float* bq = (const float*)d_in[2];
    const float* Wk = (const float*)d_in[3];  const float* bk = (const float*)d_in[4];
    const float* Wv = (const float*)d_in[5];  const float* bv = (const float*)d_in[6];
    const float* Wa = (const float*)d_in[7];  const float* ba = (const float*)d_in[8];
    const float* Wb = (const float*)d_in[9];  const float* bb = (const float*)d_in[10];
    const float* Wg = (const float*)d_in[11]; const float* bg = (const float*)d_in[12];
    const float* Wo = (const float*)d_in[13]; const float* bo = (const float*)d_in[14];
    float* out = (float*)d_out;

    static int attr_done = 0;
    if (!attr_done) {
        cudaFuncSetAttribute(prep_kernel, cudaFuncAttributeMaxDynamicSharedMemorySize, PREP_SMEM);
        cudaFuncSetAttribute(seq_kernel,  cudaFuncAttributeMaxDynamicSharedMemorySize, SEQ_SMEM);
        cudaFuncSetAttribute(outp_kernel, cudaFuncAttributeMaxDynamicSharedMemorySize, OUTP_SMEM);
        attr_done = 1;
    }

    proj_gemm<<<dim3(128, 4), 256>>>(x, Wq, Wk, Wv, Wg, bq, bk, bv, bg);
    ab_kernel<<<2048, 256>>>(x, Wa, ba, Wb, bb);
    knorm_kernel<<<2048, 256>>>();
    prep_kernel<<<NCHT, 256, PREP_SMEM>>>();
    seq_kernel<<<BB * 4, 256, SEQ_SMEM>>>();
    outp_kernel<<<NCHT, 256, OUTP_SMEM>>>();
    out_gemm<<<dim3(128, 8), 256>>>(Wo, bo, out);
}

// round 10
// speedup vs baseline: 2.7556x; 1.3585x over previous
#include <cuda_runtime.h>
#include <cuda_bf16.h>
#include <math.h>

#define DIMK 1024
#define CC   128
#define BB   8
#define TT   2048
#define ROWS (BB*TT)
#define LCH  64
#define NCH  (TT/LCH)     // 32
#define NCHT (BB*NCH)     // 256

typedef unsigned long long ull;

__device__ float g_Q [ROWS*CC];
__device__ float g_K [ROWS*CC];
__device__ float g_V [ROWS*CC];
__device__ float g_G [ROWS*CC];
__device__ float g_O [ROWS*CC];
__device__ float g_Al[ROWS];
__device__ float g_Be[ROWS];
__device__ float g_U0[NCHT*LCH*CC];
__device__ float g_W [NCHT*LCH*CC];
__device__ float g_U [NCHT*LCH*CC];
__device__ float g_Sc[NCHT*CC*CC];     // chunk-start state, [j][i] = S[i][j]
__device__ float g_Gm[NCHT*LCH];

__device__ __forceinline__ float sigmoidf_(float x) { return 1.0f / (1.0f + expf(-x)); }
__device__ __forceinline__ ull pack2(float lo, float hi) {
    ull r; asm("mov.b64 %0, {%1, %2};" : "=l"(r) : "f"(lo), "f"(hi)); return r;
}
__device__ __forceinline__ void unpack2(ull v, float& lo, float& hi) {
    asm("mov.b64 {%0, %1}, %2;" : "=f"(lo), "=f"(hi) : "l"(v));
}
__device__ __forceinline__ ull fma2(ull a, ull b, ull c) {
    ull d; asm("fma.rn.f32x2 %0, %1, %2, %3;" : "=l"(d) : "l"(a), "l"(b), "l"(c)); return d;
}
__device__ __forceinline__ ull mul2(ull a, ull b) {
    ull d; asm("mul.rn.f32x2 %0, %1, %2;" : "=l"(d) : "l"(a), "l"(b)); return d;
}

// ====================== Kernel 1: projections (f32x2 SGEMM) ================
// A tile stored plain; replicated pairs built with mov (ALU pipe) to halve LDS.
__global__ __launch_bounds__(256) void proj_gemm(
    const float* __restrict__ x,
    const float* __restrict__ Wq, const float* __restrict__ Wk,
    const float* __restrict__ Wv, const float* __restrict__ Wg,
    const float* __restrict__ bq, const float* __restrict__ bk,
    const float* __restrict__ bv, const float* __restrict__ bg)
{
    __shared__ __align__(16) float As[16][128];
    __shared__ __align__(16) float Bs[16][128];
    const int mid  = blockIdx.y;
    const float* W    = (mid == 0) ? Wq : (mid == 1) ? Wk : (mid == 2) ? Wv : Wg;
    const float* bias = (mid == 0) ? bq : (mid == 1) ? bk : (mid == 2) ? bv : bg;
    float* outp       = (mid == 0) ? g_Q : (mid == 1) ? g_K : (mid == 2) ? g_V : g_G;
    const int row0 = blockIdx.x * 128;
    const int tid = threadIdx.x, tx = tid & 15, ty = tid >> 4;
    const int lr = tid >> 2, lc = (tid & 3) * 4, bkk = tid >> 5, bn = (tid & 31) * 4;

    ull acc[8][4];
#pragma unroll
    for (int m = 0; m < 8; ++m)
#pragma unroll
        for (int n = 0; n < 4; ++n) acc[m][n] = 0ull;

    float4 aR[2], bR[2];
#pragma unroll
    for (int h = 0; h < 2; ++h) {
        aR[h] = *(const float4*)(x + (size_t)(row0 + lr + h * 64) * DIMK + lc);
        bR[h] = *(const float4*)(W + (size_t)(bkk + h * 8) * CC + bn);
    }
    for (int k0 = 0; k0 < DIMK; k0 += 16) {
#pragma unroll
        for (int h = 0; h < 2; ++h) {
            int r = lr + h * 64;
            As[lc + 0][r] = aR[h].x;
            As[lc + 1][r] = aR[h].y;
            As[lc + 2][r] = aR[h].z;
            As[lc + 3][r] = aR[h].w;
            *(float4*)&Bs[bkk + h * 8][bn] = bR[h];
        }
        __syncthreads();
        if (k0 + 16 < DIMK) {
#pragma unroll
            for (int h = 0; h < 2; ++h) {
                aR[h] = *(const float4*)(x + (size_t)(row0 + lr + h * 64) * DIMK + k0 + 16 + lc);
                bR[h] = *(const float4*)(W + (size_t)(k0 + 16 + bkk + h * 8) * CC + bn);
            }
        }
#pragma unroll
        for (int kk = 0; kk < 16; ++kk) {
            float4 a0 = *(float4*)&As[kk][ty * 8];
            float4 a1 = *(float4*)&As[kk][ty * 8 + 4];
            const ulonglong2* bp = (const ulonglong2*)&Bs[kk][tx * 8];
            ulonglong2 b01 = bp[0], b23 = bp[1];
            ull br[4] = {b01.x, b01.y, b23.x, b23.y};
            ull ar[8] = {pack2(a0.x, a0.x), pack2(a0.y, a0.y),
                         pack2(a0.z, a0.z), pack2(a0.w, a0.w),
                         pack2(a1.x, a1.x), pack2(a1.y, a1.y),
                         pack2(a1.z, a1.z), pack2(a1.w, a1.w)};
#pragma unroll
            for (int m = 0; m < 8; ++m)
#pragma unroll
                for (int n = 0; n < 4; ++n)
                    acc[m][n] = fma2(ar[m], br[n], acc[m][n]);
        }
        __syncthreads();
    }
#pragma unroll
    for (int m = 0; m < 8; ++m) {
        int row = row0 + ty * 8 + m;
#pragma unroll
        for (int n = 0; n < 4; ++n) {
            int col = tx * 8 + 2 * n;
            float e0, e1; unpack2(acc[m][n], e0, e1);
            float v0 = e0 + bias[col], v1 = e1 + bias[col + 1];
            if (mid == 3) { v0 = sigmoidf_(v0); v1 = sigmoidf_(v1); }
            *(float2*)&outp[(size_t)row * CC + col] = make_float2(v0, v1);
        }
    }
}

// ====================== Kernel 2: alpha/beta ================================
__global__ __launch_bounds__(256) void ab_kernel(
    const float* __restrict__ x,
    const float* __restrict__ Wa, const float* __restrict__ ba,
    const float* __restrict__ Wb, const float* __restrict__ bb)
{
    const int warp = threadIdx.x >> 5, lane = threadIdx.x & 31;
    const int row  = blockIdx.x * 8 + warp;
    const float* xr = x + (size_t)row * DIMK;
    float accA = 0.0f, accB = 0.0f;
#pragma unroll
    for (int it = 0; it < 8; ++it) {
        int kidx = it * 128 + lane * 4;
        float4 xv = *(const float4*)(xr + kidx);
        float4 wa = *(const float4*)(Wa + kidx);
        float4 wb = *(const float4*)(Wb + kidx);
        accA += xv.x * wa.x + xv.y * wa.y + xv.z * wa.z + xv.w * wa.w;
        accB += xv.x * wb.x + xv.y * wb.y + xv.z * wb.z + xv.w * wb.w;
    }
#pragma unroll
    for (int o = 16; o; o >>= 1) {
        accA += __shfl_xor_sync(0xffffffffu, accA, o);
        accB += __shfl_xor_sync(0xffffffffu, accB, o);
    }
    if (lane == 0) {
        g_Al[row] = sigmoidf_(accA + ba[0]);
        g_Be[row] = sigmoidf_(accB + bb[0]);
    }
}

// ====================== Kernel 3: k normalize ===============================
__global__ __launch_bounds__(256) void knorm_kernel()
{
    const int warp = threadIdx.x >> 5, lane = threadIdx.x & 31;
    const int row  = blockIdx.x * 8 + warp;
    float* kp = g_K + (size_t)row * CC + lane * 4;
    float4 kv = *(float4*)kp;
    float ss = kv.x * kv.x + kv.y * kv.y + kv.z * kv.z + kv.w * kv.w;
#pragma unroll
    for (int o = 16; o; o >>= 1) ss += __shfl_xor_sync(0xffffffffu, ss, o);
    float scale = 1.0f / fmaxf(sqrtf(ss), 1e-12f);
    kv.x *= scale; kv.y *= scale; kv.z *= scale; kv.w *= scale;
    *(float4*)kp = kv;
}

// ====================== Kernel P: per-chunk precompute ======================
// A-build register-tiled 4x4 with transposed K; substitution in registers.
#define PREP_SMEM ((64*132 + 128*68 + 64*64 + 192) * 4)
__global__ __launch_bounds__(256) void prep_kernel()
{
    extern __shared__ float sh[];
    float* Kp  = sh;               // [64][132] row-major
    float* KpT = Kp + 64 * 132;    // [128][68] transposed (i-major)
    float* Am  = KpT + 128 * 68;   // [64][64]
    float* gam = Am + 4096;
    float* asv = gam + 64;
    float* bsv = asv + 64;

    const int ch = blockIdx.x, tid = threadIdx.x;
    const size_t rbase = (size_t)ch * LCH, eb = rbase * CC;

    for (int x = tid; x < LCH * CC; x += 256) {
        int t = x >> 7, i = x & 127;
        float kv = g_K[eb + x];
        Kp[t * 132 + i] = kv;
        KpT[i * 68 + t] = kv;
    }
    if (tid < 64) { asv[tid] = g_Al[rbase + tid]; bsv[tid] = g_Be[rbase + tid]; }
    __syncthreads();
    if (tid == 0) {
        float g = 1.0f;
        for (int t = 0; t < 64; ++t) { g *= asv[t]; gam[t] = g; }
    }
    __syncthreads();

    {   // A[t][s] = b_t*(gam_t/gam_s)*(k_t.k_s), s<t  — 4x4 tile per thread
        const int t0 = (tid >> 4) * 4, s0p = (tid & 15) * 4;
        float pa[4][4];
#pragma unroll
        for (int a = 0; a < 4; ++a)
#pragma unroll
            for (int e = 0; e < 4; ++e) pa[a][e] = 0.0f;
        for (int i = 0; i < 128; ++i) {
            float4 ksv = *(float4*)&KpT[i * 68 + s0p];
            float kt0 = Kp[(t0 + 0) * 132 + i];
            float kt1 = Kp[(t0 + 1) * 132 + i];
            float kt2 = Kp[(t0 + 2) * 132 + i];
            float kt3 = Kp[(t0 + 3) * 132 + i];
            pa[0][0] = fmaf(kt0, ksv.x, pa[0][0]); pa[0][1] = fmaf(kt0, ksv.y, pa[0][1]);
            pa[0][2] = fmaf(kt0, ksv.z, pa[0][2]); pa[0][3] = fmaf(kt0, ksv.w, pa[0][3]);
            pa[1][0] = fmaf(kt1, ksv.x, pa[1][0]); pa[1][1] = fmaf(kt1, ksv.y, pa[1][1]);
            pa[1][2] = fmaf(kt1, ksv.z, pa[1][2]); pa[1][3] = fmaf(kt1, ksv.w, pa[1][3]);
            pa[2][0] = fmaf(kt2, ksv.x, pa[2][0]); pa[2][1] = fmaf(kt2, ksv.y, pa[2][1]);
            pa[2][2] = fmaf(kt2, ksv.z, pa[2][2]); pa[2][3] = fmaf(kt2, ksv.w, pa[2][3]);
            pa[3][0] = fmaf(kt3, ksv.x, pa[3][0]); pa[3][1] = fmaf(kt3, ksv.y, pa[3][1]);
            pa[3][2] = fmaf(kt3, ksv.z, pa[3][2]); pa[3][3] = fmaf(kt3, ksv.w, pa[3][3]);
        }
#pragma unroll
        for (int a = 0; a < 4; ++a) {
            int t = t0 + a;
#pragma unroll
            for (int e = 0; e < 4; ++e) {
                int s = s0p + e;
                Am[t * 64 + s] = (s < t) ? bsv[t] * (gam[t] / gam[s]) * pa[a][e] : 0.0f;
            }
        }
    }
    __syncthreads();

    {   // register-resident forward substitution
        const int  i   = tid & 127;
        const bool isU = (tid < 128);
        float X[64];
#pragma unroll
        for (int t = 0; t < 64; ++t) {
            float rhs = isU ? bsv[t] * g_V[eb + (size_t)t * CC + i]
                            : (bsv[t] * gam[t]) * Kp[t * 132 + i];
            float a0 = 0.f, a1 = 0.f, a2 = 0.f, a3 = 0.f;
#pragma unroll
            for (int s = 0; s + 4 <= t; s += 4) {
                a0 = fmaf(Am[t * 64 + s + 0], X[s + 0], a0);
                a1 = fmaf(Am[t * 64 + s + 1], X[s + 1], a1);
                a2 = fmaf(Am[t * 64 + s + 2], X[s + 2], a2);
                a3 = fmaf(Am[t * 64 + s + 3], X[s + 3], a3);
            }
#pragma unroll
            for (int s = t & ~3; s < t; ++s)
                a0 = fmaf(Am[t * 64 + s], X[s], a0);
            X[t] = rhs - ((a0 + a1) + (a2 + a3));
        }
        float* dst = isU ? g_U0 : g_W;
#pragma unroll
        for (int t = 0; t < 64; ++t)
            dst[eb + (size_t)t * CC + i] = X[t];
    }
    if (tid < 64) g_Gm[rbase + tid] = gam[tid];
}

// ====================== Kernel S: sequential chunk recurrence ===============
// 8 CTAs per batch, each owning a 16-column slice of the state (index i).
#define SEQ_SMEM ((128*16 + 64*260 + 64*260 + 64*16 + 64) * 4)
__global__ __launch_bounds__(256, 1) void seq_kernel()
{
    extern __shared__ float sh[];
    float* Ssh = sh;               // [j][ii] 128*16
    float* Wd  = Ssh + 2048;       // -W dup pairs, row stride 260
    float* Kd  = Wd + 64 * 260;    // K dup pairs, row stride 260
    float* Ysh = Kd + 64 * 260;    // [t][ii] 64*16
    float* gam = Ysh + 1024;

    const int b   = blockIdx.x >> 3;
    const int sl  = blockIdx.x & 7;
    const int tid = threadIdx.x;
    const int icol0 = sl * 16;

    for (int x = tid; x < 2048; x += 256) Ssh[x] = 0.0f;

    const int t1  = tid >> 2;            // GEMM1: one t-row per thread
    const int ii0 = (tid & 3) * 4;       // 4 state-cols (2 packed pairs)
    const int jg2 = tid >> 1;            // GEMM2: one j-row per thread
    const int c0  = (tid & 1) * 8;       // 8 cols (4 pairs)

    for (int c = 0; c < NCH; ++c) {
        const size_t ch = (size_t)(b * NCH + c);
        const size_t eb = ch * LCH * CC;
        __syncthreads();

        // chunk-start state slice -> g_Sc
        for (int x = tid; x < 512; x += 256) {
            int j = x >> 2, ii = (x & 3) * 4;
            *(float4*)&g_Sc[ch * 16384 + (size_t)j * 128 + icol0 + ii] =
                *(float4*)&Ssh[j * 16 + ii];
        }
        // stage -W (dup) and K (dup)
        for (int x = tid; x < 2048; x += 256) {
            int base = x * 4, t = base >> 7, j = base & 127;
            float4 w4 = *(const float4*)&g_W[eb + base];
            *(float4*)&Wd[t * 260 + 2 * j]     = make_float4(-w4.x, -w4.x, -w4.y, -w4.y);
            *(float4*)&Wd[t * 260 + 2 * j + 4] = make_float4(-w4.z, -w4.z, -w4.w, -w4.w);
            float4 k4 = *(const float4*)&g_K[eb + base];
            *(float4*)&Kd[t * 260 + 2 * j]     = make_float4(k4.x, k4.x, k4.y, k4.y);
            *(float4*)&Kd[t * 260 + 2 * j + 4] = make_float4(k4.z, k4.z, k4.w, k4.w);
        }
        if (tid < 64) gam[tid] = g_Gm[ch * LCH + tid];
        float4 u0a = *(const float4*)&g_U0[eb + (size_t)t1 * CC + icol0 + ii0];
        __syncthreads();
        const float gamL = gam[63];

        // GEMM1: U[t1][ii] = U0 - sum_j W[t1][j] * Ssh[j][ii]
        ull acc0 = pack2(u0a.x, u0a.y), acc1 = pack2(u0a.z, u0a.w);
#pragma unroll 8
        for (int j = 0; j < 128; ++j) {
            ull w = *(ull*)&Wd[t1 * 260 + 2 * j];
            ulonglong2 sA = *(ulonglong2*)&Ssh[j * 16 + ii0];
            acc0 = fma2(w, sA.x, acc0);
            acc1 = fma2(w, sA.y, acc1);
        }
        {
            float f0, f1, f2, f3;
            unpack2(acc0, f0, f1); unpack2(acc1, f2, f3);
            const float rt = gamL / gam[t1];
            *(float4*)&g_U[eb + (size_t)t1 * CC + icol0 + ii0] = make_float4(f0, f1, f2, f3);
            *(float4*)&Ysh[t1 * 16 + ii0] = make_float4(rt * f0, rt * f1, rt * f2, rt * f3);
        }
        __syncthreads();

        // GEMM2: Ssh[j][c] = gamL*Ssh + sum_t K[t][j]*Y[t][c]
        ull s2[4];
        const ull gl2 = pack2(gamL, gamL);
        {
            ulonglong2 oA = *(ulonglong2*)&Ssh[jg2 * 16 + c0];
            ulonglong2 oB = *(ulonglong2*)&Ssh[jg2 * 16 + c0 + 4];
            s2[0] = mul2(oA.x, gl2); s2[1] = mul2(oA.y, gl2);
            s2[2] = mul2(oB.x, gl2); s2[3] = mul2(oB.y, gl2);
        }
#pragma unroll 8
        for (int t = 0; t < 64; ++t) {
            ull k = *(ull*)&Kd[t * 260 + 2 * jg2];
            ulonglong2 yA = *(ulonglong2*)&Ysh[t * 16 + c0];
            ulonglong2 yB = *(ulonglong2*)&Ysh[t * 16 + c0 + 4];
            s2[0] = fma2(k, yA.x, s2[0]); s2[1] = fma2(k, yA.y, s2[1]);
            s2[2] = fma2(k, yB.x, s2[2]); s2[3] = fma2(k, yB.y, s2[3]);
        }
        *(ulonglong2*)&Ssh[jg2 * 16 + c0]     = make_ulonglong2(s2[0], s2[1]);
        *(ulonglong2*)&Ssh[jg2 * 16 + c0 + 4] = make_ulonglong2(s2[2], s2[3]);
    }
}

// ====================== Kernel O: per-chunk outputs =========================
#define OUTP_SMEM ((128*132 + 64*132 + 128*68 + 64*128 + 64*68 + 64) * 4)
__global__ __launch_bounds__(256) void outp_kernel()
{
    extern __shared__ float sh[];
    float* S2t = sh;               // [i][j] = S0[i][j]
    float* Qs  = S2t + 128 * 132;  // [t][i]
    float* Ut  = Qs  + 64 * 132;   // [i][t] = U[t][i]
    float* Ks  = Ut  + 128 * 68;   // [s][j]
    float* Ps  = Ks  + 64 * 128;   // [t][s]
    float* gam = Ps  + 64 * 68;

    const int ch = blockIdx.x, tid = threadIdx.x;
    const size_t eb = (size_t)ch * LCH * CC;

    for (int x = tid; x < 16384; x += 256) {
        int j = x >> 7, i = x & 127;
        S2t[i * 132 + j] = g_Sc[(size_t)ch * 16384 + x];
    }
    for (int x = tid; x < 8192; x += 256) {
        int t = x >> 7, i = x & 127;
        Qs[t * 132 + i] = g_Q[eb + x];
        Ut[i * 68 + t]  = g_U[eb + x];
        Ks[x]           = g_K[eb + x];
    }
    if (tid < 64) gam[tid] = g_Gm[(size_t)ch * LCH + tid];
    __syncthreads();

    {   // P[t][s]
        const int t0 = (tid >> 4) * 4, s0 = (tid & 15) * 4;
        float pa[4][4];
#pragma unroll
        for (int a = 0; a < 4; ++a)
#pragma unroll
            for (int e = 0; e < 4; ++e) pa[a][e] = 0.0f;
        for (int i = 0; i < 128; ++i) {
            float qv[4];
#pragma unroll
            for (int a = 0; a < 4; ++a) qv[a] = Qs[(t0 + a) * 132 + i];
            float4 dv = *(float4*)&Ut[i * 68 + s0];
            float dr[4] = {dv.x, dv.y, dv.z, dv.w};
#pragma unroll
            for (int a = 0; a < 4; ++a)
#pragma unroll
                for (int e = 0; e < 4; ++e) pa[a][e] = fmaf(qv[a], dr[e], pa[a][e]);
        }
#pragma unroll
        for (int a = 0; a < 4; ++a) {
            int t = t0 + a;
#pragma unroll
            for (int e = 0; e < 4; ++e) {
                int s = s0 + e;
                Ps[t * 68 + s] = (s <= t) ? (gam[t] / gam[s]) * pa[a][e] : 0.0f;
            }
        }
    }
    __syncthreads();

    {   // O[t][j]
        const int t0 = (tid >> 4) * 4, j0 = (tid & 15) * 8;
        ull oa[4][4];
#pragma unroll
        for (int a = 0; a < 4; ++a)
#pragma unroll
            for (int p = 0; p < 4; ++p) oa[a][p] = 0ull;
        for (int i = 0; i < 128; ++i) {
            ull qd[4];
#pragma unroll
            for (int a = 0; a < 4; ++a) {
                float q = Qs[(t0 + a) * 132 + i];
                qd[a] = pack2(q, q);
            }
            ulonglong2 sA = *(ulonglong2*)&S2t[i * 132 + j0];
            ulonglong2 sB = *(ulonglong2*)&S2t[i * 132 + j0 + 4];
            ull sp[4] = {sA.x, sA.y, sB.x, sB.y};
#pragma unroll
            for (int a = 0; a < 4; ++a)
#pragma unroll
                for (int p = 0; p < 4; ++p) oa[a][p] = fma2(qd[a], sp[p], oa[a][p]);
        }
#pragma unroll
        for (int a = 0; a < 4; ++a) {
            const ull g2 = pack2(gam[t0 + a], gam[t0 + a]);
#pragma unroll
            for (int p = 0; p < 4; ++p) oa[a][p] = mul2(oa[a][p], g2);
        }
        for (int s = 0; s < 64; ++s) {
            ull pd[4];
#pragma unroll
            for (int a = 0; a < 4; ++a) {
                float pv = Ps[(t0 + a) * 68 + s];
                pd[a] = pack2(pv, pv);
            }
            ulonglong2 kA = *(ulonglong2*)&Ks[s * 128 + j0];
            ulonglong2 kB = *(ulonglong2*)&Ks[s * 128 + j0 + 4];
            ull kp[4] = {kA.x, kA.y, kB.x, kB.y};
#pragma unroll
            for (int a = 0; a < 4; ++a)
#pragma unroll
                for (int p = 0; p < 4; ++p) oa[a][p] = fma2(pd[a], kp[p], oa[a][p]);
        }
#pragma unroll
        for (int a = 0; a < 4; ++a) {
            const size_t row = eb + (size_t)(t0 + a) * CC + j0;
            float f[8];
            unpack2(oa[a][0], f[0], f[1]); unpack2(oa[a][1], f[2], f[3]);
            unpack2(oa[a][2], f[4], f[5]); unpack2(oa[a][3], f[6], f[7]);
            float4 gA = *(const float4*)&g_G[row];
            float4 gB = *(const float4*)&g_G[row + 4];
            *(float4*)&g_O[row]     = make_float4(f[0] * gA.x, f[1] * gA.y, f[2] * gA.z, f[3] * gA.w);
            *(float4*)&g_O[row + 4] = make_float4(f[4] * gB.x, f[5] * gB.y, f[6] * gB.z, f[7] * gB.w);
        }
    }
}

// ====================== Kernel 5: out = O @ Wo + bo =========================
__global__ __launch_bounds__(256) void out_gemm(
    const float* __restrict__ Wo, const float* __restrict__ bo,
    float* __restrict__ out)
{
    __shared__ __align__(16) float As[16][128];
    __shared__ __align__(16) float Bs[16][128];
    const int row0 = blockIdx.x * 128, col0 = blockIdx.y * 128;
    const int tid = threadIdx.x, tx = tid & 15, ty = tid >> 4;
    const int lr = tid >> 2, lc = (tid & 3) * 4, bkk = tid >> 5, bn = (tid & 31) * 4;

    ull acc[8][4];
#pragma unroll
    for (int m = 0; m < 8; ++m)
#pragma unroll
        for (int n = 0; n < 4; ++n) acc[m][n] = 0ull;

    float4 aR[2], bR[2];
#pragma unroll
    for (int h = 0; h < 2; ++h) {
        aR[h] = *(const float4*)(g_O + (size_t)(row0 + lr + h * 64) * CC + lc);
        bR[h] = *(const float4*)(Wo + (size_t)(bkk + h * 8) * DIMK + col0 + bn);
    }
    for (int k0 = 0; k0 < CC; k0 += 16) {
#pragma unroll
        for (int h = 0; h < 2; ++h) {
            int r = lr + h * 64;
            As[lc + 0][r] = aR[h].x;
            As[lc + 1][r] = aR[h].y;
            As[lc + 2][r] = aR[h].z;
            As[lc + 3][r] = aR[h].w;
            *(float4*)&Bs[bkk + h * 8][bn] = bR[h];
        }
        __syncthreads();
        if (k0 + 16 < CC) {
#pragma unroll
            for (int h = 0; h < 2; ++h) {
                aR[h] = *(const float4*)(g_O + (size_t)(row0 + lr + h * 64) * CC + k0 + 16 + lc);
                bR[h] = *(const float4*)(Wo + (size_t)(k0 + 16 + bkk + h * 8) * DIMK + col0 + bn);
            }
        }
#pragma unroll
        for (int kk = 0; kk < 16; ++kk) {
            float4 a0 = *(float4*)&As[kk][ty * 8];
            float4 a1 = *(float4*)&As[kk][ty * 8 + 4];
            const ulonglong2* bp = (const ulonglong2*)&Bs[kk][tx * 8];
            ulonglong2 b01 = bp[0], b23 = bp[1];
            ull br[4] = {b01.x, b01.y, b23.x, b23.y};
            ull ar[8] = {pack2(a0.x, a0.x), pack2(a0.y, a0.y),
                         pack2(a0.z, a0.z), pack2(a0.w, a0.w),
                         pack2(a1.x, a1.x), pack2(a1.y, a1.y),
                         pack2(a1.z, a1.z), pack2(a1.w, a1.w)};
#pragma unroll
            for (int m = 0; m < 8; ++m)
#pragma unroll
                for (int n = 0; n < 4; ++n)
                    acc[m][n] = fma2(ar[m], br[n], acc[m][n]);
        }
        __syncthreads();
    }
#pragma unroll
    for (int m = 0; m < 8; ++m) {
        int row = row0 + ty * 8 + m;
#pragma unroll
        for (int n = 0; n < 4; ++n) {
            int col = col0 + tx * 8 + 2 * n;
            float e0, e1; unpack2(acc[m][n], e0, e1);
            *(float2*)&out[(size_t)row * DIMK + col] =
                make_float2(e0 + bo[col], e1 + bo[col + 1]);
        }
    }
}

// ===========================================================================
extern "C" void kernel_launch(void* const* d_in, const int* in_sizes, int n_in,
                              void* d_out, int out_size)
{
    const float* x  = (const float*)d_in[0];
    const float* Wq = (const float*)d_in[1];  const float* bq = (const float*)d_in[2];
    const float* Wk = (const float*)d_in[3];  const float* bk = (const float*)d_in[4];
    const float* Wv = (const float*)d_in[5];  const float* bv = (const float*)d_in[6];
    const float* Wa = (const float*)d_in[7];  const float* ba = (const float*)d_in[8];
    const float* Wb = (const float*)d_in[9];  const float* bb = (const float*)d_in[10];
    const float* Wg = (const float*)d_in[11]; const float* bg = (const float*)d_in[12];
    const float* Wo = (const float*)d_in[13]; const float* bo = (const float*)d_in[14];
    float* out = (float*)d_out;

    static int attr_done = 0;
    if (!attr_done) {
        cudaFuncSetAttribute(prep_kernel, cudaFuncAttributeMaxDynamicSharedMemorySize, PREP_SMEM);
        cudaFuncSetAttribute(seq_kernel,  cudaFuncAttributeMaxDynamicSharedMemorySize, SEQ_SMEM);
        cudaFuncSetAttribute(outp_kernel, cudaFuncAttributeMaxDynamicSharedMemorySize, OUTP_SMEM);
        attr_done = 1;
    }

    proj_gemm<<<dim3(128, 4), 256>>>(x, Wq, Wk, Wv, Wg, bq, bk, bv, bg);
    ab_kernel<<<2048, 256>>>(x, Wa, ba, Wb, bb);
    knorm_kernel<<<2048, 256>>>();
    prep_kernel<<<NCHT, 256, PREP_SMEM>>>();
    seq_kernel<<<BB * 8, 256, SEQ_SMEM>>>();
    outp_kernel<<<NCHT, 256, OUTP_SMEM>>>();
    out_gemm<<<dim3(128, 8), 256>>>(Wo, bo, out);
}

// round 14
// speedup vs baseline: 3.3312x; 1.2089x over previous
#include <cuda_runtime.h>
#include <cuda_bf16.h>
#include <cstdint>
#include <math.h>

#define DIMK 1024
#define CC   128
#define BB   8
#define TT   2048
#define ROWS (BB*TT)
#define LCH  64
#define NCH  (TT/LCH)     // 32
#define NCHT (BB*NCH)     // 256

typedef unsigned long long ull;

// ------------------------- device scratch ---------------------------------
__device__ float g_Q [ROWS*CC];
__device__ float g_K [ROWS*CC];
__device__ float g_V [ROWS*CC];
__device__ float g_G [ROWS*CC];
__device__ float g_Al[ROWS];
__device__ float g_Be[ROWS];
__device__ float g_U0[NCHT*LCH*CC];
__device__ float g_W [NCHT*LCH*CC];
__device__ float g_U [NCHT*LCH*CC];
__device__ float g_Sc[NCHT*CC*CC];
__device__ float g_Gm[NCHT*LCH];
// bf16 split operands
__device__ __nv_bfloat16 g_xh [ROWS*DIMK];
__device__ __nv_bfloat16 g_xl [ROWS*DIMK];
__device__ __nv_bfloat16 g_Wth[4*CC*DIMK];     // W^T per mat: [mat][n=128][k=1024]
__device__ __nv_bfloat16 g_Wtl[4*CC*DIMK];
__device__ __nv_bfloat16 g_Woth[DIMK*CC];      // Wo^T: [n=1024][k=128]
__device__ __nv_bfloat16 g_Wotl[DIMK*CC];
__device__ __nv_bfloat16 g_Oh [ROWS*CC];       // gated output, split
__device__ __nv_bfloat16 g_Ol [ROWS*CC];

__device__ __forceinline__ float sigmoidf_(float x) { return 1.0f / (1.0f + expf(-x)); }
__device__ __forceinline__ ull pack2(float lo, float hi) {
    ull r; asm("mov.b64 %0, {%1, %2};" : "=l"(r) : "f"(lo), "f"(hi)); return r;
}
__device__ __forceinline__ void unpack2(ull v, float& lo, float& hi) {
    asm("mov.b64 {%0, %1}, %2;" : "=f"(lo), "=f"(hi) : "l"(v));
}
__device__ __forceinline__ ull fma2(ull a, ull b, ull c) {
    ull d; asm("fma.rn.f32x2 %0, %1, %2, %3;" : "=l"(d) : "l"(a), "l"(b), "l"(c)); return d;
}
__device__ __forceinline__ ull mul2(ull a, ull b) {
    ull d; asm("mul.rn.f32x2 %0, %1, %2;" : "=l"(d) : "l"(a), "l"(b)); return d;
}
__device__ __forceinline__ uint32_t smem_u32(const void* p) {
    uint32_t a;
    asm("{ .reg .u64 t; cvta.to.shared.u64 t, %1; cvt.u32.u64 %0, t; }" : "=r"(a) : "l"(p));
    return a;
}
__device__ __forceinline__ void ldm_x4(uint32_t* r, uint32_t addr) {
    asm volatile("ldmatrix.sync.aligned.m8n8.x4.shared.b16 {%0,%1,%2,%3}, [%4];"
        : "=r"(r[0]), "=r"(r[1]), "=r"(r[2]), "=r"(r[3]) : "r"(addr));
}
__device__ __forceinline__ void mma16816(float* c, const uint32_t* a, const uint32_t* b) {
    asm volatile("mma.sync.aligned.m16n8k16.row.col.f32.bf16.bf16.f32 "
        "{%0,%1,%2,%3}, {%4,%5,%6,%7}, {%8,%9}, {%0,%1,%2,%3};"
        : "+f"(c[0]), "+f"(c[1]), "+f"(c[2]), "+f"(c[3])
        : "r"(a[0]), "r"(a[1]), "r"(a[2]), "r"(a[3]), "r"(b[0]), "r"(b[1]));
}

// ====================== split kernels ======================================
__global__ __launch_bounds__(256) void split_x(const float* __restrict__ x)
{
    size_t i = ((size_t)blockIdx.x * 256 + threadIdx.x) * 4;
    float4 v = *(const float4*)(x + i);
    __nv_bfloat16 h0 = __float2bfloat16(v.x), h1 = __float2bfloat16(v.y);
    __nv_bfloat16 h2 = __float2bfloat16(v.z), h3 = __float2bfloat16(v.w);
    __nv_bfloat16 l0 = __float2bfloat16(v.x - __bfloat162float(h0));
    __nv_bfloat16 l1 = __float2bfloat16(v.y - __bfloat162float(h1));
    __nv_bfloat16 l2 = __float2bfloat16(v.z - __bfloat162float(h2));
    __nv_bfloat16 l3 = __float2bfloat16(v.w - __bfloat162float(h3));
    *(__nv_bfloat162*)(g_xh + i)     = __halves2bfloat162(h0, h1);
    *(__nv_bfloat162*)(g_xh + i + 2) = __halves2bfloat162(h2, h3);
    *(__nv_bfloat162*)(g_xl + i)     = __halves2bfloat162(l0, l1);
    *(__nv_bfloat162*)(g_xl + i + 2) = __halves2bfloat162(l2, l3);
}

__global__ __launch_bounds__(256) void split_w(
    const float* __restrict__ Wq, const float* __restrict__ Wk,
    const float* __restrict__ Wv, const float* __restrict__ Wg,
    const float* __restrict__ Wo)
{
    int gidx = blockIdx.x * 256 + threadIdx.x;   // 0 .. 655359
    float v; __nv_bfloat16* dh; __nv_bfloat16* dl; size_t didx;
    if (gidx < 4 * 131072) {
        int mat = gidx >> 17, rem = gidx & 131071;
        int n = rem >> 10, k = rem & 1023;
        const float* W = (mat == 0) ? Wq : (mat == 1) ? Wk : (mat == 2) ? Wv : Wg;
        v = W[(size_t)k * CC + n];
        didx = (size_t)mat * 131072 + (size_t)n * 1024 + k;
        dh = g_Wth; dl = g_Wtl;
    } else {
        int rem = gidx - 4 * 131072;
        int n = rem >> 7, k = rem & 127;
        v = Wo[(size_t)k * DIMK + n];
        didx = (size_t)n * 128 + k;
        dh = g_Woth; dl = g_Wotl;
    }
    __nv_bfloat16 h = __float2bfloat16(v);
    dh[didx] = h;
    dl[didx] = __float2bfloat16(v - __bfloat162float(h));
}

// ====================== mma.sync split-bf16 GEMM core =======================
// C tile [128 x 128]. Warp (of 8) tile: 32 rows x 64 cols (2 m-tiles x 8 n-tiles).
// K staged in chunks of 32 (4 tiles of [128][40] bf16, padded stride).
#define GM_SMEM (4 * 128 * 40 * 2)   // 40960 B
__device__ __forceinline__ void mm_core(
    const __nv_bfloat16* __restrict__ Ah, const __nv_bfloat16* __restrict__ Al, int lda,
    const __nv_bfloat16* __restrict__ Bth, const __nv_bfloat16* __restrict__ Btl, int ldb,
    int K,
    const float* __restrict__ bias, float* __restrict__ Cout, int ldc,
    int row0, int gate)
{
    extern __shared__ __align__(16) __nv_bfloat16 sm[];
    __nv_bfloat16* AsH = sm;
    __nv_bfloat16* AsL = sm + 128 * 40;
    __nv_bfloat16* BsH = sm + 2 * 128 * 40;
    __nv_bfloat16* BsL = sm + 3 * 128 * 40;

    const int tid = threadIdx.x, wid = tid >> 5, lane = tid & 31;
    const int mrow = (wid >> 1) * 32;
    const int ncol = (wid & 1) * 64;
    const int g  = lane >> 2, tg = lane & 3;
    const int lj = lane >> 3, lr = lane & 7;

    float acc[2][8][4];
#pragma unroll
    for (int mt = 0; mt < 2; ++mt)
#pragma unroll
        for (int nt = 0; nt < 8; ++nt)
#pragma unroll
            for (int e = 0; e < 4; ++e) acc[mt][nt][e] = 0.0f;

    for (int k0 = 0; k0 < K; k0 += 32) {
        __syncthreads();
#pragma unroll
        for (int it = 0; it < 8; ++it) {
            int idx = it * 256 + tid;
            int tile = idx >> 9, rem = idx & 511;
            int row = rem >> 2, c8 = (rem & 3) * 8;
            const __nv_bfloat16* src;
            __nv_bfloat16* dst;
            if      (tile == 0) { src = Ah  + (size_t)(row0 + row) * lda + k0 + c8; dst = AsH; }
            else if (tile == 1) { src = Al  + (size_t)(row0 + row) * lda + k0 + c8; dst = AsL; }
            else if (tile == 2) { src = Bth + (size_t)row * ldb + k0 + c8; dst = BsH; }
            else                { src = Btl + (size_t)row * ldb + k0 + c8; dst = BsL; }
            *(uint4*)(dst + row * 40 + c8) = *(const uint4*)src;
        }
        __syncthreads();

#pragma unroll
        for (int ks = 0; ks < 2; ++ks) {
            const int kb = ks * 16;
            uint32_t ah[2][4], al[2][4], bh[8][2], bl[8][2];
            // A frags: j&1 -> +8 rows, j>>1 -> +8 k
#pragma unroll
            for (int mt = 0; mt < 2; ++mt) {
                int arow = mrow + mt * 16 + (lj & 1) * 8 + lr;
                int acol = kb + (lj >> 1) * 8;
                ldm_x4(ah[mt], smem_u32(AsH + arow * 40 + acol));
                ldm_x4(al[mt], smem_u32(AsL + arow * 40 + acol));
            }
            // B frags: j>>1 -> n-tile select, j&1 -> +8 k
#pragma unroll
            for (int np = 0; np < 4; ++np) {
                int brow = ncol + np * 16 + (lj >> 1) * 8 + lr;
                int bcol = kb + (lj & 1) * 8;
                uint32_t r4[4];
                ldm_x4(r4, smem_u32(BsH + brow * 40 + bcol));
                bh[np * 2][0] = r4[0]; bh[np * 2][1] = r4[1];
                bh[np * 2 + 1][0] = r4[2]; bh[np * 2 + 1][1] = r4[3];
                ldm_x4(r4, smem_u32(BsL + brow * 40 + bcol));
                bl[np * 2][0] = r4[0]; bl[np * 2][1] = r4[1];
                bl[np * 2 + 1][0] = r4[2]; bl[np * 2 + 1][1] = r4[3];
            }
#pragma unroll
            for (int mt = 0; mt < 2; ++mt)
#pragma unroll
                for (int nt = 0; nt < 8; ++nt) {
                    mma16816(acc[mt][nt], ah[mt], bh[nt]);
                    mma16816(acc[mt][nt], ah[mt], bl[nt]);
                    mma16816(acc[mt][nt], al[mt], bh[nt]);
                }
        }
    }

    // epilogue: c0,c1 = (row g, cols 2tg,2tg+1); c2,c3 = row g+8
#pragma unroll
    for (int mt = 0; mt < 2; ++mt) {
#pragma unroll
        for (int nt = 0; nt < 8; ++nt) {
            int col = ncol + nt * 8 + tg * 2;
            float b0 = bias[col], b1 = bias[col + 1];
            int rA = row0 + mrow + mt * 16 + g;
            float v0 = acc[mt][nt][0] + b0, v1 = acc[mt][nt][1] + b1;
            float v2 = acc[mt][nt][2] + b0, v3 = acc[mt][nt][3] + b1;
            if (gate) { v0 = sigmoidf_(v0); v1 = sigmoidf_(v1); v2 = sigmoidf_(v2); v3 = sigmoidf_(v3); }
            *(float2*)&Cout[(size_t)rA * ldc + col]       = make_float2(v0, v1);
            *(float2*)&Cout[(size_t)(rA + 8) * ldc + col] = make_float2(v2, v3);
        }
    }
}

__global__ __launch_bounds__(256) void proj_mma(
    const float* __restrict__ bq, const float* __restrict__ bk,
    const float* __restrict__ bv, const float* __restrict__ bg)
{
    const int mat = blockIdx.y;
    const float* bias = (mat == 0) ? bq : (mat == 1) ? bk : (mat == 2) ? bv : bg;
    float* Cout = (mat == 0) ? g_Q : (mat == 1) ? g_K : (mat == 2) ? g_V : g_G;
    mm_core(g_xh, g_xl, DIMK,
            g_Wth + (size_t)mat * CC * DIMK, g_Wtl + (size_t)mat * CC * DIMK, DIMK,
            DIMK, bias, Cout, CC, blockIdx.x * 128, mat == 3);
}

__global__ __launch_bounds__(256) void out_mma(
    const float* __restrict__ bo, float* __restrict__ out)
{
    const int col0 = blockIdx.y * 128;
    mm_core(g_Oh, g_Ol, CC,
            g_Woth + (size_t)col0 * CC, g_Wotl + (size_t)col0 * CC, CC,
            CC, bo + col0, out + col0, DIMK, blockIdx.x * 128, 0);
}

// ====================== alpha/beta ==========================================
__global__ __launch_bounds__(256) void ab_kernel(
    const float* __restrict__ x,
    const float* __restrict__ Wa, const float* __restrict__ ba,
    const float* __restrict__ Wb, const float* __restrict__ bb)
{
    const int warp = threadIdx.x >> 5, lane = threadIdx.x & 31;
    const int row  = blockIdx.x * 8 + warp;
    const float* xr = x + (size_t)row * DIMK;
    float accA = 0.0f, accB = 0.0f;
#pragma unroll
    for (int it = 0; it < 8; ++it) {
        int kidx = it * 128 + lane * 4;
        float4 xv = *(const float4*)(xr + kidx);
        float4 wa = *(const float4*)(Wa + kidx);
        float4 wb = *(const float4*)(Wb + kidx);
        accA += xv.x * wa.x + xv.y * wa.y + xv.z * wa.z + xv.w * wa.w;
        accB += xv.x * wb.x + xv.y * wb.y + xv.z * wb.z + xv.w * wb.w;
    }
#pragma unroll
    for (int o = 16; o; o >>= 1) {
        accA += __shfl_xor_sync(0xffffffffu, accA, o);
        accB += __shfl_xor_sync(0xffffffffu, accB, o);
    }
    if (lane == 0) {
        g_Al[row] = sigmoidf_(accA + ba[0]);
        g_Be[row] = sigmoidf_(accB + bb[0]);
    }
}

// ====================== k normalize =========================================
__global__ __launch_bounds__(256) void knorm_kernel()
{
    const int warp = threadIdx.x >> 5, lane = threadIdx.x & 31;
    const int row  = blockIdx.x * 8 + warp;
    float* kp = g_K + (size_t)row * CC + lane * 4;
    float4 kv = *(float4*)kp;
    float ss = kv.x * kv.x + kv.y * kv.y + kv.z * kv.z + kv.w * kv.w;
#pragma unroll
    for (int o = 16; o; o >>= 1) ss += __shfl_xor_sync(0xffffffffu, ss, o);
    float scale = 1.0f / fmaxf(sqrtf(ss), 1e-12f);
    kv.x *= scale; kv.y *= scale; kv.z *= scale; kv.w *= scale;
    *(float4*)kp = kv;
}

// ====================== per-chunk precompute ================================
#define PREP_SMEM ((64*132 + 128*68 + 64*64 + 192) * 4)
__global__ __launch_bounds__(256) void prep_kernel()
{
    extern __shared__ float sh[];
    float* Kp  = sh;
    float* KpT = Kp + 64 * 132;
    float* Am  = KpT + 128 * 68;
    float* gam = Am + 4096;
    float* asv = gam + 64;
    float* bsv = asv + 64;

    const int ch = blockIdx.x, tid = threadIdx.x;
    const size_t rbase = (size_t)ch * LCH, eb = rbase * CC;

    for (int x = tid; x < LCH * CC; x += 256) {
        int t = x >> 7, i = x & 127;
        float kv = g_K[eb + x];
        Kp[t * 132 + i] = kv;
        KpT[i * 68 + t] = kv;
    }
    if (tid < 64) { asv[tid] = g_Al[rbase + tid]; bsv[tid] = g_Be[rbase + tid]; }
    __syncthreads();
    if (tid == 0) {
        float g = 1.0f;
        for (int t = 0; t < 64; ++t) { g *= asv[t]; gam[t] = g; }
    }
    __syncthreads();

    {
        const int t0 = (tid >> 4) * 4, s0p = (tid & 15) * 4;
        float pa[4][4];
#pragma unroll
        for (int a = 0; a < 4; ++a)
#pragma unroll
            for (int e = 0; e < 4; ++e) pa[a][e] = 0.0f;
        for (int i = 0; i < 128; ++i) {
            float4 ksv = *(float4*)&KpT[i * 68 + s0p];
            float kt0 = Kp[(t0 + 0) * 132 + i];
            float kt1 = Kp[(t0 + 1) * 132 + i];
            float kt2 = Kp[(t0 + 2) * 132 + i];
            float kt3 = Kp[(t0 + 3) * 132 + i];
            pa[0][0] = fmaf(kt0, ksv.x, pa[0][0]); pa[0][1] = fmaf(kt0, ksv.y, pa[0][1]);
            pa[0][2] = fmaf(kt0, ksv.z, pa[0][2]); pa[0][3] = fmaf(kt0, ksv.w, pa[0][3]);
            pa[1][0] = fmaf(kt1, ksv.x, pa[1][0]); pa[1][1] = fmaf(kt1, ksv.y, pa[1][1]);
            pa[1][2] = fmaf(kt1, ksv.z, pa[1][2]); pa[1][3] = fmaf(kt1, ksv.w, pa[1][3]);
            pa[2][0] = fmaf(kt2, ksv.x, pa[2][0]); pa[2][1] = fmaf(kt2, ksv.y, pa[2][1]);
            pa[2][2] = fmaf(kt2, ksv.z, pa[2][2]); pa[2][3] = fmaf(kt2, ksv.w, pa[2][3]);
            pa[3][0] = fmaf(kt3, ksv.x, pa[3][0]); pa[3][1] = fmaf(kt3, ksv.y, pa[3][1]);
            pa[3][2] = fmaf(kt3, ksv.z, pa[3][2]); pa[3][3] = fmaf(kt3, ksv.w, pa[3][3]);
        }
#pragma unroll
        for (int a = 0; a < 4; ++a) {
            int t = t0 + a;
#pragma unroll
            for (int e = 0; e < 4; ++e) {
                int s = s0p + e;
                Am[t * 64 + s] = (s < t) ? bsv[t] * (gam[t] / gam[s]) * pa[a][e] : 0.0f;
            }
        }
    }
    __syncthreads();

    {
        const int  i   = tid & 127;
        const bool isU = (tid < 128);
        float X[64];
#pragma unroll
        for (int t = 0; t < 64; ++t) {
            float rhs = isU ? bsv[t] * g_V[eb + (size_t)t * CC + i]
                            : (bsv[t] * gam[t]) * Kp[t * 132 + i];
            float a0 = 0.f, a1 = 0.f, a2 = 0.f, a3 = 0.f;
#pragma unroll
            for (int s = 0; s + 4 <= t; s += 4) {
                a0 = fmaf(Am[t * 64 + s + 0], X[s + 0], a0);
                a1 = fmaf(Am[t * 64 + s + 1], X[s + 1], a1);
                a2 = fmaf(Am[t * 64 + s + 2], X[s + 2], a2);
                a3 = fmaf(Am[t * 64 + s + 3], X[s + 3], a3);
            }
#pragma unroll
            for (int s = t & ~3; s < t; ++s)
                a0 = fmaf(Am[t * 64 + s], X[s], a0);
            X[t] = rhs - ((a0 + a1) + (a2 + a3));
        }
        float* dst = isU ? g_U0 : g_W;
#pragma unroll
        for (int t = 0; t < 64; ++t)
            dst[eb + (size_t)t * CC + i] = X[t];
    }
    if (tid < 64) g_Gm[rbase + tid] = gam[tid];
}

// ====================== sequential chunk recurrence =========================
#define SEQ_SMEM ((128*16 + 64*260 + 64*260 + 64*16 + 64) * 4)
__global__ __launch_bounds__(256, 1) void seq_kernel()
{
    extern __shared__ float sh[];
    float* Ssh = sh;
    float* Wd  = Ssh + 2048;
    float* Kd  = Wd + 64 * 260;
    float* Ysh = Kd + 64 * 260;
    float* gam = Ysh + 1024;

    const int b   = blockIdx.x >> 3;
    const int sl  = blockIdx.x & 7;
    const int tid = threadIdx.x;
    const int icol0 = sl * 16;

    for (int x = tid; x < 2048; x += 256) Ssh[x] = 0.0f;

    const int t1  = tid >> 2;
    const int ii0 = (tid & 3) * 4;
    const int jg2 = tid >> 1;
    const int c0  = (tid & 1) * 8;

    for (int c = 0; c < NCH; ++c) {
        const size_t ch = (size_t)(b * NCH + c);
        const size_t eb = ch * LCH * CC;
        __syncthreads();

        for (int x = tid; x < 512; x += 256) {
            int j = x >> 2, ii = (x & 3) * 4;
            *(float4*)&g_Sc[ch * 16384 + (size_t)j * 128 + icol0 + ii] =
                *(float4*)&Ssh[j * 16 + ii];
        }
        for (int x = tid; x < 2048; x += 256) {
            int base = x * 4, t = base >> 7, j = base & 127;
            float4 w4 = *(const float4*)&g_W[eb + base];
            *(float4*)&Wd[t * 260 + 2 * j]     = make_float4(-w4.x, -w4.x, -w4.y, -w4.y);
            *(float4*)&Wd[t * 260 + 2 * j + 4] = make_float4(-w4.z, -w4.z, -w4.w, -w4.w);
            float4 k4 = *(const float4*)&g_K[eb + base];
            *(float4*)&Kd[t * 260 + 2 * j]     = make_float4(k4.x, k4.x, k4.y, k4.y);
            *(float4*)&Kd[t * 260 + 2 * j + 4] = make_float4(k4.z, k4.z, k4.w, k4.w);
        }
        if (tid < 64) gam[tid] = g_Gm[ch * LCH + tid];
        float4 u0a = *(const float4*)&g_U0[eb + (size_t)t1 * CC + icol0 + ii0];
        __syncthreads();
        const float gamL = gam[63];

        ull acc0 = pack2(u0a.x, u0a.y), acc1 = pack2(u0a.z, u0a.w);
#pragma unroll 8
        for (int j = 0; j < 128; ++j) {
            ull w = *(ull*)&Wd[t1 * 260 + 2 * j];
            ulonglong2 sA = *(ulonglong2*)&Ssh[j * 16 + ii0];
            acc0 = fma2(w, sA.x, acc0);
            acc1 = fma2(w, sA.y, acc1);
        }
        {
            float f0, f1, f2, f3;
            unpack2(acc0, f0, f1); unpack2(acc1, f2, f3);
            const float rt = gamL / gam[t1];
            *(float4*)&g_U[eb + (size_t)t1 * CC + icol0 + ii0] = make_float4(f0, f1, f2, f3);
            *(float4*)&Ysh[t1 * 16 + ii0] = make_float4(rt * f0, rt * f1, rt * f2, rt * f3);
        }
        __syncthreads();

        ull s2[4];
        const ull gl2 = pack2(gamL, gamL);
        {
            ulonglong2 oA = *(ulonglong2*)&Ssh[jg2 * 16 + c0];
            ulonglong2 oB = *(ulonglong2*)&Ssh[jg2 * 16 + c0 + 4];
            s2[0] = mul2(oA.x, gl2); s2[1] = mul2(oA.y, gl2);
            s2[2] = mul2(oB.x, gl2); s2[3] = mul2(oB.y, gl2);
        }
#pragma unroll 8
        for (int t = 0; t < 64; ++t) {
            ull k = *(ull*)&Kd[t * 260 + 2 * jg2];
            ulonglong2 yA = *(ulonglong2*)&Ysh[t * 16 + c0];
            ulonglong2 yB = *(ulonglong2*)&Ysh[t * 16 + c0 + 4];
            s2[0] = fma2(k, yA.x, s2[0]); s2[1] = fma2(k, yA.y, s2[1]);
            s2[2] = fma2(k, yB.x, s2[2]); s2[3] = fma2(k, yB.y, s2[3]);
        }
        *(ulonglong2*)&Ssh[jg2 * 16 + c0]     = make_ulonglong2(s2[0], s2[1]);
        *(ulonglong2*)&Ssh[jg2 * 16 + c0 + 4] = make_ulonglong2(s2[2], s2[3]);
    }
}

// ====================== per-chunk outputs (writes bf16 splits) ==============
#define OUTP_SMEM ((128*132 + 64*132 + 128*68 + 64*128 + 64*68 + 64) * 4)
__global__ __launch_bounds__(256) void outp_kernel()
{
    extern __shared__ float sh[];
    float* S2t = sh;
    float* Qs  = S2t + 128 * 132;
    float* Ut  = Qs  + 64 * 132;
    float* Ks  = Ut  + 128 * 68;
    float* Ps  = Ks  + 64 * 128;
    float* gam = Ps  + 64 * 68;

    const int ch = blockIdx.x, tid = threadIdx.x;
    const size_t eb = (size_t)ch * LCH * CC;

    for (int x = tid; x < 16384; x += 256) {
        int j = x >> 7, i = x & 127;
        S2t[i * 132 + j] = g_Sc[(size_t)ch * 16384 + x];
    }
    for (int x = tid; x < 8192; x += 256) {
        int t = x >> 7, i = x & 127;
        Qs[t * 132 + i] = g_Q[eb + x];
        Ut[i * 68 + t]  = g_U[eb + x];
        Ks[x]           = g_K[eb + x];
    }
    if (tid < 64) gam[tid] = g_Gm[(size_t)ch * LCH + tid];
    __syncthreads();

    {
        const int t0 = (tid >> 4) * 4, s0 = (tid & 15) * 4;
        float pa[4][4];
#pragma unroll
        for (int a = 0; a < 4; ++a)
#pragma unroll
            for (int e = 0; e < 4; ++e) pa[a][e] = 0.0f;
        for (int i = 0; i < 128; ++i) {
            float qv[4];
#pragma unroll
            for (int a = 0; a < 4; ++a) qv[a] = Qs[(t0 + a) * 132 + i];
            float4 dv = *(float4*)&Ut[i * 68 + s0];
            float dr[4] = {dv.x, dv.y, dv.z, dv.w};
#pragma unroll
            for (int a = 0; a < 4; ++a)
#pragma unroll
                for (int e = 0; e < 4; ++e) pa[a][e] = fmaf(qv[a], dr[e], pa[a][e]);
        }
#pragma unroll
        for (int a = 0; a < 4; ++a) {
            int t = t0 + a;
#pragma unroll
            for (int e = 0; e < 4; ++e) {
                int s = s0 + e;
                Ps[t * 68 + s] = (s <= t) ? (gam[t] / gam[s]) * pa[a][e] : 0.0f;
            }
        }
    }
    __syncthreads();

    {
        const int t0 = (tid >> 4) * 4, j0 = (tid & 15) * 8;
        ull oa[4][4];
#pragma unroll
        for (int a = 0; a < 4; ++a)
#pragma unroll
            for (int p = 0; p < 4; ++p) oa[a][p] = 0ull;
        for (int i = 0; i < 128; ++i) {
            ull qd[4];
#pragma unroll
            for (int a = 0; a < 4; ++a) {
                float q = Qs[(t0 + a) * 132 + i];
                qd[a] = pack2(q, q);
            }
            ulonglong2 sA = *(ulonglong2*)&S2t[i * 132 + j0];
            ulonglong2 sB = *(ulonglong2*)&S2t[i * 132 + j0 + 4];
            ull sp[4] = {sA.x, sA.y, sB.x, sB.y};
#pragma unroll
            for (int a = 0; a < 4; ++a)
#pragma unroll
                for (int p = 0; p < 4; ++p) oa[a][p] = fma2(qd[a], sp[p], oa[a][p]);
        }
#pragma unroll
        for (int a = 0; a < 4; ++a) {
            const ull g2 = pack2(gam[t0 + a], gam[t0 + a]);
#pragma unroll
            for (int p = 0; p < 4; ++p) oa[a][p] = mul2(oa[a][p], g2);
        }
        for (int s = 0; s < 64; ++s) {
            ull pd[4];
#pragma unroll
            for (int a = 0; a < 4; ++a) {
                float pv = Ps[(t0 + a) * 68 + s];
                pd[a] = pack2(pv, pv);
            }
            ulonglong2 kA = *(ulonglong2*)&Ks[s * 128 + j0];
            ulonglong2 kB = *(ulonglong2*)&Ks[s * 128 + j0 + 4];
            ull kp[4] = {kA.x, kA.y, kB.x, kB.y};
#pragma unroll
            for (int a = 0; a < 4; ++a)
#pragma unroll
                for (int p = 0; p < 4; ++p) oa[a][p] = fma2(pd[a], kp[p], oa[a][p]);
        }
#pragma unroll
        for (int a = 0; a < 4; ++a) {
            const size_t row = eb + (size_t)(t0 + a) * CC + j0;
            float f[8];
            unpack2(oa[a][0], f[0], f[1]); unpack2(oa[a][1], f[2], f[3]);
            unpack2(oa[a][2], f[4], f[5]); unpack2(oa[a][3], f[6], f[7]);
            float4 gA = *(const float4*)&g_G[row];
            float4 gB = *(const float4*)&g_G[row + 4];
            float v[8];
            v[0] = f[0] * gA.x; v[1] = f[1] * gA.y; v[2] = f[2] * gA.z; v[3] = f[3] * gA.w;
            v[4] = f[4] * gB.x; v[5] = f[5] * gB.y; v[6] = f[6] * gB.z; v[7] = f[7] * gB.w;
#pragma unroll
            for (int q = 0; q < 4; ++q) {
                __nv_bfloat16 h0 = __float2bfloat16(v[2 * q]);
                __nv_bfloat16 h1 = __float2bfloat16(v[2 * q + 1]);
                __nv_bfloat16 l0 = __float2bfloat16(v[2 * q]     - __bfloat162float(h0));
                __nv_bfloat16 l1 = __float2bfloat16(v[2 * q + 1] - __bfloat162float(h1));
                *(__nv_bfloat162*)(g_Oh + row + 2 * q) = __halves2bfloat162(h0, h1);
                *(__nv_bfloat162*)(g_Ol + row + 2 * q) = __halves2bfloat162(l0, l1);
            }
        }
    }
}

// ===========================================================================
extern "C" void kernel_launch(void* const* d_in, const int* in_sizes, int n_in,
                              void* d_out, int out_size)
{
    const float* x  = (const float*)d_in[0];
    const float* Wq = (const float*)d_in[1];  const float* bq = (const float*)d_in[2];
    const float* Wk = (const float*)d_in[3];  const float* bk = (const float*)d_in[4];
    const float* Wv = (const float*)d_in[5];  const float* bv = (const float*)d_in[6];
    const float* Wa = (const float*)d_in[7];  const float* ba = (const float*)d_in[8];
    const float* Wb = (const float*)d_in[9];  const float* bb = (const float*)d_in[10];
    const float* Wg = (const float*)d_in[11]; const float* bg = (const float*)d_in[12];
    const float* Wo = (const float*)d_in[13]; const float* bo = (const float*)d_in[14];
    float* out = (float*)d_out;

    static int attr_done = 0;
    if (!attr_done) {
        cudaFuncSetAttribute(prep_kernel, cudaFuncAttributeMaxDynamicSharedMemorySize, PREP_SMEM);
        cudaFuncSetAttribute(seq_kernel,  cudaFuncAttributeMaxDynamicSharedMemorySize, SEQ_SMEM);
        cudaFuncSetAttribute(outp_kernel, cudaFuncAttributeMaxDynamicSharedMemorySize, OUTP_SMEM);
        cudaFuncSetAttribute(proj_mma,    cudaFuncAttributeMaxDynamicSharedMemorySize, GM_SMEM);
        cudaFuncSetAttribute(out_mma,     cudaFuncAttributeMaxDynamicSharedMemorySize, GM_SMEM);
        attr_done = 1;
    }

    split_x<<<ROWS * DIMK / 1024, 256>>>(x);
    split_w<<<(4 * 131072 + 131072) / 256, 256>>>(Wq, Wk, Wv, Wg, Wo);
    proj_mma<<<dim3(128, 4), 256, GM_SMEM>>>(bq, bk, bv, bg);
    ab_kernel<<<2048, 256>>>(x, Wa, ba, Wb, bb);
    knorm_kernel<<<2048, 256>>>();
    prep_kernel<<<NCHT, 256, PREP_SMEM>>>();
    seq_kernel<<<BB * 8, 256, SEQ_SMEM>>>();
    outp_kernel<<<NCHT, 256, OUTP_SMEM>>>();
    out_mma<<<dim3(128, 8), 256, GM_SMEM>>>(bo, out);
}

// round 15
// speedup vs baseline: 3.7975x; 1.1400x over previous
#include <cuda_runtime.h>
#include <cuda_bf16.h>
#include <cstdint>
#include <math.h>

#define DIMK 1024
#define CC   128
#define BB   8
#define TT   2048
#define ROWS (BB*TT)
#define LCH  64
#define NCH  (TT/LCH)     // 32
#define NCHT (BB*NCH)     // 256

typedef unsigned long long ull;

// ------------------------- device scratch ---------------------------------
__device__ float g_Q [ROWS*CC];
__device__ float g_K [ROWS*CC];
__device__ float g_V [ROWS*CC];
__device__ float g_G [ROWS*CC];
__device__ float g_Al[ROWS];
__device__ float g_Be[ROWS];
__device__ float g_U0[NCHT*LCH*CC];
__device__ float g_W [NCHT*LCH*CC];
__device__ float g_U [NCHT*LCH*CC];
__device__ float g_Sc[NCHT*CC*CC];
__device__ float g_Gm[NCHT*LCH];
// bf16 split operands
__device__ __nv_bfloat16 g_xh [ROWS*DIMK];
__device__ __nv_bfloat16 g_xl [ROWS*DIMK];
__device__ __nv_bfloat16 g_Wth[4*CC*DIMK];     // W^T per mat: [mat][n=128][k=1024]
__device__ __nv_bfloat16 g_Wtl[4*CC*DIMK];
__device__ __nv_bfloat16 g_Woth[DIMK*CC];      // Wo^T: [n=1024][k=128]
__device__ __nv_bfloat16 g_Wotl[DIMK*CC];
__device__ __nv_bfloat16 g_Oh [ROWS*CC];       // gated output, split
__device__ __nv_bfloat16 g_Ol [ROWS*CC];

__device__ __forceinline__ float sigmoidf_(float x) { return 1.0f / (1.0f + expf(-x)); }
__device__ __forceinline__ ull pack2(float lo, float hi) {
    ull r; asm("mov.b64 %0, {%1, %2};" : "=l"(r) : "f"(lo), "f"(hi)); return r;
}
__device__ __forceinline__ void unpack2(ull v, float& lo, float& hi) {
    asm("mov.b64 {%0, %1}, %2;" : "=f"(lo), "=f"(hi) : "l"(v));
}
__device__ __forceinline__ ull fma2(ull a, ull b, ull c) {
    ull d; asm("fma.rn.f32x2 %0, %1, %2, %3;" : "=l"(d) : "l"(a), "l"(b), "l"(c)); return d;
}
__device__ __forceinline__ ull mul2(ull a, ull b) {
    ull d; asm("mul.rn.f32x2 %0, %1, %2;" : "=l"(d) : "l"(a), "l"(b)); return d;
}
__device__ __forceinline__ uint32_t smem_u32(const void* p) {
    uint32_t a;
    asm("{ .reg .u64 t; cvta.to.shared.u64 t, %1; cvt.u32.u64 %0, t; }" : "=r"(a) : "l"(p));
    return a;
}
__device__ __forceinline__ void ldm_x4(uint32_t* r, uint32_t addr) {
    asm volatile("ldmatrix.sync.aligned.m8n8.x4.shared.b16 {%0,%1,%2,%3}, [%4];"
        : "=r"(r[0]), "=r"(r[1]), "=r"(r[2]), "=r"(r[3]) : "r"(addr));
}
__device__ __forceinline__ void mma16816(float* c, const uint32_t* a, const uint32_t* b) {
    asm volatile("mma.sync.aligned.m16n8k16.row.col.f32.bf16.bf16.f32 "
        "{%0,%1,%2,%3}, {%4,%5,%6,%7}, {%8,%9}, {%0,%1,%2,%3};"
        : "+f"(c[0]), "+f"(c[1]), "+f"(c[2]), "+f"(c[3])
        : "r"(a[0]), "r"(a[1]), "r"(a[2]), "r"(a[3]), "r"(b[0]), "r"(b[1]));
}

// ====================== split kernels ======================================
__global__ __launch_bounds__(256) void split_x(const float* __restrict__ x)
{
    size_t i = ((size_t)blockIdx.x * 256 + threadIdx.x) * 4;
    float4 v = *(const float4*)(x + i);
    __nv_bfloat16 h0 = __float2bfloat16(v.x), h1 = __float2bfloat16(v.y);
    __nv_bfloat16 h2 = __float2bfloat16(v.z), h3 = __float2bfloat16(v.w);
    __nv_bfloat16 l0 = __float2bfloat16(v.x - __bfloat162float(h0));
    __nv_bfloat16 l1 = __float2bfloat16(v.y - __bfloat162float(h1));
    __nv_bfloat16 l2 = __float2bfloat16(v.z - __bfloat162float(h2));
    __nv_bfloat16 l3 = __float2bfloat16(v.w - __bfloat162float(h3));
    *(__nv_bfloat162*)(g_xh + i)     = __halves2bfloat162(h0, h1);
    *(__nv_bfloat162*)(g_xh + i + 2) = __halves2bfloat162(h2, h3);
    *(__nv_bfloat162*)(g_xl + i)     = __halves2bfloat162(l0, l1);
    *(__nv_bfloat162*)(g_xl + i + 2) = __halves2bfloat162(l2, l3);
}

__global__ __launch_bounds__(256) void split_w(
    const float* __restrict__ Wq, const float* __restrict__ Wk,
    const float* __restrict__ Wv, const float* __restrict__ Wg,
    const float* __restrict__ Wo)
{
    int gidx = blockIdx.x * 256 + threadIdx.x;   // 0 .. 655359
    float v; __nv_bfloat16* dh; __nv_bfloat16* dl; size_t didx;
    if (gidx < 4 * 131072) {
        int mat = gidx >> 17, rem = gidx & 131071;
        int n = rem >> 10, k = rem & 1023;
        const float* W = (mat == 0) ? Wq : (mat == 1) ? Wk : (mat == 2) ? Wv : Wg;
        v = W[(size_t)k * CC + n];
        didx = (size_t)mat * 131072 + (size_t)n * 1024 + k;
        dh = g_Wth; dl = g_Wtl;
    } else {
        int rem = gidx - 4 * 131072;
        int n = rem >> 7, k = rem & 127;
        v = Wo[(size_t)k * DIMK + n];
        didx = (size_t)n * 128 + k;
        dh = g_Woth; dl = g_Wotl;
    }
    __nv_bfloat16 h = __float2bfloat16(v);
    dh[didx] = h;
    dl[didx] = __float2bfloat16(v - __bfloat162float(h));
}

// ====================== mma.sync split-bf16 GEMM core (double-buffered) ====
// C tile [128 x 128]. Warp (of 8) tile: 32 rows x 64 cols (2 m-tiles x 8 n-tiles).
// K staged in chunks of 32; 2 smem buffers of 4 x [128][40] bf16 each.
#define GM_BUF  (4 * 128 * 40)            // bf16 elems per buffer
#define GM_SMEM (2 * GM_BUF * 2)          // 81920 B
__device__ __forceinline__ void mm_core(
    const __nv_bfloat16* __restrict__ Ah, const __nv_bfloat16* __restrict__ Al, int lda,
    const __nv_bfloat16* __restrict__ Bth, const __nv_bfloat16* __restrict__ Btl, int ldb,
    int K,
    const float* __restrict__ bias, float* __restrict__ Cout, int ldc,
    int row0, int gate)
{
    extern __shared__ __align__(16) __nv_bfloat16 sm[];

    const int tid = threadIdx.x, wid = tid >> 5, lane = tid & 31;
    const int mrow = (wid >> 1) * 32;
    const int ncol = (wid & 1) * 64;
    const int g  = lane >> 2, tg = lane & 3;
    const int lj = lane >> 3, lr = lane & 7;

    // this thread's 8 staging slots (tile, row, col8) — fixed across chunks
    int st_tile[8], st_row[8], st_c8[8];
#pragma unroll
    for (int it = 0; it < 8; ++it) {
        int idx = it * 256 + tid;
        st_tile[it] = idx >> 9;
        st_row[it]  = (idx & 511) >> 2;
        st_c8[it]   = (idx & 3) * 8;
    }
    const __nv_bfloat16* srcb[4] = { Ah, Al, Bth, Btl };
    const int ldv[4] = { lda, lda, ldb, ldb };
    const int rofs[4] = { row0, row0, 0, 0 };

    float acc[2][8][4];
#pragma unroll
    for (int mt = 0; mt < 2; ++mt)
#pragma unroll
        for (int nt = 0; nt < 8; ++nt)
#pragma unroll
            for (int e = 0; e < 4; ++e) acc[mt][nt][e] = 0.0f;

    // prologue: stage chunk 0 into buffer 0
#pragma unroll
    for (int it = 0; it < 8; ++it) {
        int t = st_tile[it];
        uint4 v = *(const uint4*)(srcb[t] + (size_t)(rofs[t] + st_row[it]) * ldv[t] + st_c8[it]);
        *(uint4*)(sm + t * 128 * 40 + st_row[it] * 40 + st_c8[it]) = v;
    }
    __syncthreads();

    const int NC = K >> 5;
    for (int c = 0; c < NC; ++c) {
        __nv_bfloat16* buf = sm + (c & 1) * GM_BUF;
        // prefetch chunk c+1 into registers (overlaps MMAs below)
        uint4 pf[8];
        if (c + 1 < NC) {
            const int kn = (c + 1) * 32;
#pragma unroll
            for (int it = 0; it < 8; ++it) {
                int t = st_tile[it];
                pf[it] = *(const uint4*)(srcb[t] + (size_t)(rofs[t] + st_row[it]) * ldv[t] + kn + st_c8[it]);
            }
        }

        __nv_bfloat16* AsH = buf;
        __nv_bfloat16* AsL = buf + 128 * 40;
        __nv_bfloat16* BsH = buf + 2 * 128 * 40;
        __nv_bfloat16* BsL = buf + 3 * 128 * 40;
#pragma unroll
        for (int ks = 0; ks < 2; ++ks) {
            const int kb = ks * 16;
            uint32_t ah[2][4], al[2][4], bh[8][2], bl[8][2];
#pragma unroll
            for (int mt = 0; mt < 2; ++mt) {
                int arow = mrow + mt * 16 + (lj & 1) * 8 + lr;
                int acol = kb + (lj >> 1) * 8;
                ldm_x4(ah[mt], smem_u32(AsH + arow * 40 + acol));
                ldm_x4(al[mt], smem_u32(AsL + arow * 40 + acol));
            }
#pragma unroll
            for (int np = 0; np < 4; ++np) {
                int brow = ncol + np * 16 + (lj >> 1) * 8 + lr;
                int bcol = kb + (lj & 1) * 8;
                uint32_t r4[4];
                ldm_x4(r4, smem_u32(BsH + brow * 40 + bcol));
                bh[np * 2][0] = r4[0]; bh[np * 2][1] = r4[1];
                bh[np * 2 + 1][0] = r4[2]; bh[np * 2 + 1][1] = r4[3];
                ldm_x4(r4, smem_u32(BsL + brow * 40 + bcol));
                bl[np * 2][0] = r4[0]; bl[np * 2][1] = r4[1];
                bl[np * 2 + 1][0] = r4[2]; bl[np * 2 + 1][1] = r4[3];
            }
#pragma unroll
            for (int mt = 0; mt < 2; ++mt)
#pragma unroll
                for (int nt = 0; nt < 8; ++nt) {
                    mma16816(acc[mt][nt], ah[mt], bh[nt]);
                    mma16816(acc[mt][nt], ah[mt], bl[nt]);
                    mma16816(acc[mt][nt], al[mt], bh[nt]);
                }
        }

        if (c + 1 < NC) {
            __nv_bfloat16* nbuf = sm + ((c + 1) & 1) * GM_BUF;
#pragma unroll
            for (int it = 0; it < 8; ++it)
                *(uint4*)(nbuf + st_tile[it] * 128 * 40 + st_row[it] * 40 + st_c8[it]) = pf[it];
        }
        __syncthreads();
    }

    // epilogue: c0,c1 = (row g, cols 2tg,2tg+1); c2,c3 = row g+8
#pragma unroll
    for (int mt = 0; mt < 2; ++mt) {
#pragma unroll
        for (int nt = 0; nt < 8; ++nt) {
            int col = ncol + nt * 8 + tg * 2;
            float b0 = bias[col], b1 = bias[col + 1];
            int rA = row0 + mrow + mt * 16 + g;
            float v0 = acc[mt][nt][0] + b0, v1 = acc[mt][nt][1] + b1;
            float v2 = acc[mt][nt][2] + b0, v3 = acc[mt][nt][3] + b1;
            if (gate) { v0 = sigmoidf_(v0); v1 = sigmoidf_(v1); v2 = sigmoidf_(v2); v3 = sigmoidf_(v3); }
            *(float2*)&Cout[(size_t)rA * ldc + col]       = make_float2(v0, v1);
            *(float2*)&Cout[(size_t)(rA + 8) * ldc + col] = make_float2(v2, v3);
        }
    }
}

__global__ __launch_bounds__(256) void proj_mma(
    const float* __restrict__ bq, const float* __restrict__ bk,
    const float* __restrict__ bv, const float* __restrict__ bg)
{
    const int mat = blockIdx.y;
    const float* bias = (mat == 0) ? bq : (mat == 1) ? bk : (mat == 2) ? bv : bg;
    float* Cout = (mat == 0) ? g_Q : (mat == 1) ? g_K : (mat == 2) ? g_V : g_G;
    mm_core(g_xh, g_xl, DIMK,
            g_Wth + (size_t)mat * CC * DIMK, g_Wtl + (size_t)mat * CC * DIMK, DIMK,
            DIMK, bias, Cout, CC, blockIdx.x * 128, mat == 3);
}

__global__ __launch_bounds__(256) void out_mma(
    const float* __restrict__ bo, float* __restrict__ out)
{
    const int col0 = blockIdx.y * 128;
    mm_core(g_Oh, g_Ol, CC,
            g_Woth + (size_t)col0 * CC, g_Wotl + (size_t)col0 * CC, CC,
            CC, bo + col0, out + col0, DIMK, blockIdx.x * 128, 0);
}

// ====================== alpha/beta ==========================================
__global__ __launch_bounds__(256) void ab_kernel(
    const float* __restrict__ x,
    const float* __restrict__ Wa, const float* __restrict__ ba,
    const float* __restrict__ Wb, const float* __restrict__ bb)
{
    const int warp = threadIdx.x >> 5, lane = threadIdx.x & 31;
    const int row  = blockIdx.x * 8 + warp;
    const float* xr = x + (size_t)row * DIMK;
    float accA = 0.0f, accB = 0.0f;
#pragma unroll
    for (int it = 0; it < 8; ++it) {
        int kidx = it * 128 + lane * 4;
        float4 xv = *(const float4*)(xr + kidx);
        float4 wa = *(const float4*)(Wa + kidx);
        float4 wb = *(const float4*)(Wb + kidx);
        accA += xv.x * wa.x + xv.y * wa.y + xv.z * wa.z + xv.w * wa.w;
        accB += xv.x * wb.x + xv.y * wb.y + xv.z * wb.z + xv.w * wb.w;
    }
#pragma unroll
    for (int o = 16; o; o >>= 1) {
        accA += __shfl_xor_sync(0xffffffffu, accA, o);
        accB += __shfl_xor_sync(0xffffffffu, accB, o);
    }
    if (lane == 0) {
        g_Al[row] = sigmoidf_(accA + ba[0]);
        g_Be[row] = sigmoidf_(accB + bb[0]);
    }
}

// ====================== k normalize =========================================
__global__ __launch_bounds__(256) void knorm_kernel()
{
    const int warp = threadIdx.x >> 5, lane = threadIdx.x & 31;
    const int row  = blockIdx.x * 8 + warp;
    float* kp = g_K + (size_t)row * CC + lane * 4;
    float4 kv = *(float4*)kp;
    float ss = kv.x * kv.x + kv.y * kv.y + kv.z * kv.z + kv.w * kv.w;
#pragma unroll
    for (int o = 16; o; o >>= 1) ss += __shfl_xor_sync(0xffffffffu, ss, o);
    float scale = 1.0f / fmaxf(sqrtf(ss), 1e-12f);
    kv.x *= scale; kv.y *= scale; kv.z *= scale; kv.w *= scale;
    *(float4*)kp = kv;
}

// ====================== per-chunk precompute ================================
#define PREP_SMEM ((64*132 + 128*68 + 64*64 + 192) * 4)
__global__ __launch_bounds__(256) void prep_kernel()
{
    extern __shared__ float sh[];
    float* Kp  = sh;
    float* KpT = Kp + 64 * 132;
    float* Am  = KpT + 128 * 68;
    float* gam = Am + 4096;
    float* asv = gam + 64;
    float* bsv = asv + 64;

    const int ch = blockIdx.x, tid = threadIdx.x;
    const size_t rbase = (size_t)ch * LCH, eb = rbase * CC;

    for (int x = tid; x < LCH * CC; x += 256) {
        int t = x >> 7, i = x & 127;
        float kv = g_K[eb + x];
        Kp[t * 132 + i] = kv;
        KpT[i * 68 + t] = kv;
    }
    if (tid < 64) { asv[tid] = g_Al[rbase + tid]; bsv[tid] = g_Be[rbase + tid]; }
    __syncthreads();
    if (tid == 0) {
        float g = 1.0f;
        for (int t = 0; t < 64; ++t) { g *= asv[t]; gam[t] = g; }
    }
    __syncthreads();

    {
        const int t0 = (tid >> 4) * 4, s0p = (tid & 15) * 4;
        float pa[4][4];
#pragma unroll
        for (int a = 0; a < 4; ++a)
#pragma unroll
            for (int e = 0; e < 4; ++e) pa[a][e] = 0.0f;
        for (int i = 0; i < 128; ++i) {
            float4 ksv = *(float4*)&KpT[i * 68 + s0p];
            float kt0 = Kp[(t0 + 0) * 132 + i];
            float kt1 = Kp[(t0 + 1) * 132 + i];
            float kt2 = Kp[(t0 + 2) * 132 + i];
            float kt3 = Kp[(t0 + 3) * 132 + i];
            pa[0][0] = fmaf(kt0, ksv.x, pa[0][0]); pa[0][1] = fmaf(kt0, ksv.y, pa[0][1]);
            pa[0][2] = fmaf(kt0, ksv.z, pa[0][2]); pa[0][3] = fmaf(kt0, ksv.w, pa[0][3]);
            pa[1][0] = fmaf(kt1, ksv.x, pa[1][0]); pa[1][1] = fmaf(kt1, ksv.y, pa[1][1]);
            pa[1][2] = fmaf(kt1, ksv.z, pa[1][2]); pa[1][3] = fmaf(kt1, ksv.w, pa[1][3]);
            pa[2][0] = fmaf(kt2, ksv.x, pa[2][0]); pa[2][1] = fmaf(kt2, ksv.y, pa[2][1]);
            pa[2][2] = fmaf(kt2, ksv.z, pa[2][2]); pa[2][3] = fmaf(kt2, ksv.w, pa[2][3]);
            pa[3][0] = fmaf(kt3, ksv.x, pa[3][0]); pa[3][1] = fmaf(kt3, ksv.y, pa[3][1]);
            pa[3][2] = fmaf(kt3, ksv.z, pa[3][2]); pa[3][3] = fmaf(kt3, ksv.w, pa[3][3]);
        }
#pragma unroll
        for (int a = 0; a < 4; ++a) {
            int t = t0 + a;
#pragma unroll
            for (int e = 0; e < 4; ++e) {
                int s = s0p + e;
                Am[t * 64 + s] = (s < t) ? bsv[t] * (gam[t] / gam[s]) * pa[a][e] : 0.0f;
            }
        }
    }
    __syncthreads();

    {
        const int  i   = tid & 127;
        const bool isU = (tid < 128);
        float X[64];
#pragma unroll
        for (int t = 0; t < 64; ++t) {
            float rhs = isU ? bsv[t] * g_V[eb + (size_t)t * CC + i]
                            : (bsv[t] * gam[t]) * Kp[t * 132 + i];
            float a0 = 0.f, a1 = 0.f, a2 = 0.f, a3 = 0.f;
#pragma unroll
            for (int s = 0; s + 4 <= t; s += 4) {
                a0 = fmaf(Am[t * 64 + s + 0], X[s + 0], a0);
                a1 = fmaf(Am[t * 64 + s + 1], X[s + 1], a1);
                a2 = fmaf(Am[t * 64 + s + 2], X[s + 2], a2);
                a3 = fmaf(Am[t * 64 + s + 3], X[s + 3], a3);
            }
#pragma unroll
            for (int s = t & ~3; s < t; ++s)
                a0 = fmaf(Am[t * 64 + s], X[s], a0);
            X[t] = rhs - ((a0 + a1) + (a2 + a3));
        }
        float* dst = isU ? g_U0 : g_W;
#pragma unroll
        for (int t = 0; t < 64; ++t)
            dst[eb + (size_t)t * CC + i] = X[t];
    }
    if (tid < 64) g_Gm[rbase + tid] = gam[tid];
}

// ====================== sequential chunk recurrence =========================
#define SEQ_SMEM ((128*16 + 64*260 + 64*260 + 64*16 + 64) * 4)
__global__ __launch_bounds__(256, 1) void seq_kernel()
{
    extern __shared__ float sh[];
    float* Ssh = sh;
    float* Wd  = Ssh + 2048;
    float* Kd  = Wd + 64 * 260;
    float* Ysh = Kd + 64 * 260;
    float* gam = Ysh + 1024;

    const int b   = blockIdx.x >> 3;
    const int sl  = blockIdx.x & 7;
    const int tid = threadIdx.x;
    const int icol0 = sl * 16;

    for (int x = tid; x < 2048; x += 256) Ssh[x] = 0.0f;

    const int t1  = tid >> 2;
    const int ii0 = (tid & 3) * 4;
    const int jg2 = tid >> 1;
    const int c0  = (tid & 1) * 8;

    for (int c = 0; c < NCH; ++c) {
        const size_t ch = (size_t)(b * NCH + c);
        const size_t eb = ch * LCH * CC;
        __syncthreads();

        for (int x = tid; x < 512; x += 256) {
            int j = x >> 2, ii = (x & 3) * 4;
            *(float4*)&g_Sc[ch * 16384 + (size_t)j * 128 + icol0 + ii] =
                *(float4*)&Ssh[j * 16 + ii];
        }
        for (int x = tid; x < 2048; x += 256) {
            int base = x * 4, t = base >> 7, j = base & 127;
            float4 w4 = *(const float4*)&g_W[eb + base];
            *(float4*)&Wd[t * 260 + 2 * j]     = make_float4(-w4.x, -w4.x, -w4.y, -w4.y);
            *(float4*)&Wd[t * 260 + 2 * j + 4] = make_float4(-w4.z, -w4.z, -w4.w, -w4.w);
            float4 k4 = *(const float4*)&g_K[eb + base];
            *(float4*)&Kd[t * 260 + 2 * j]     = make_float4(k4.x, k4.x, k4.y, k4.y);
            *(float4*)&Kd[t * 260 + 2 * j + 4] = make_float4(k4.z, k4.z, k4.w, k4.w);
        }
        if (tid < 64) gam[tid] = g_Gm[ch * LCH + tid];
        float4 u0a = *(const float4*)&g_U0[eb + (size_t)t1 * CC + icol0 + ii0];
        __syncthreads();
        const float gamL = gam[63];

        ull acc0 = pack2(u0a.x, u0a.y), acc1 = pack2(u0a.z, u0a.w);
#pragma unroll 8
        for (int j = 0; j < 128; ++j) {
            ull w = *(ull*)&Wd[t1 * 260 + 2 * j];
            ulonglong2 sA = *(ulonglong2*)&Ssh[j * 16 + ii0];
            acc0 = fma2(w, sA.x, acc0);
            acc1 = fma2(w, sA.y, acc1);
        }
        {
            float f0, f1, f2, f3;
            unpack2(acc0, f0, f1); unpack2(acc1, f2, f3);
            const float rt = gamL / gam[t1];
            *(float4*)&g_U[eb + (size_t)t1 * CC + icol0 + ii0] = make_float4(f0, f1, f2, f3);
            *(float4*)&Ysh[t1 * 16 + ii0] = make_float4(rt * f0, rt * f1, rt * f2, rt * f3);
        }
        __syncthreads();

        ull s2[4];
        const ull gl2 = pack2(gamL, gamL);
        {
            ulonglong2 oA = *(ulonglong2*)&Ssh[jg2 * 16 + c0];
            ulonglong2 oB = *(ulonglong2*)&Ssh[jg2 * 16 + c0 + 4];
            s2[0] = mul2(oA.x, gl2); s2[1] = mul2(oA.y, gl2);
            s2[2] = mul2(oB.x, gl2); s2[3] = mul2(oB.y, gl2);
        }
#pragma unroll 8
        for (int t = 0; t < 64; ++t) {
            ull k = *(ull*)&Kd[t * 260 + 2 * jg2];
            ulonglong2 yA = *(ulonglong2*)&Ysh[t * 16 + c0];
            ulonglong2 yB = *(ulonglong2*)&Ysh[t * 16 + c0 + 4];
            s2[0] = fma2(k, yA.x, s2[0]); s2[1] = fma2(k, yA.y, s2[1]);
            s2[2] = fma2(k, yB.x, s2[2]); s2[3] = fma2(k, yB.y, s2[3]);
        }
        *(ulonglong2*)&Ssh[jg2 * 16 + c0]     = make_ulonglong2(s2[0], s2[1]);
        *(ulonglong2*)&Ssh[jg2 * 16 + c0 + 4] = make_ulonglong2(s2[2], s2[3]);
    }
}

// ====================== per-chunk outputs (writes bf16 splits) ==============
#define OUTP_SMEM ((128*132 + 64*132 + 128*68 + 64*128 + 64*68 + 64) * 4)
__global__ __launch_bounds__(256) void outp_kernel()
{
    extern __shared__ float sh[];
    float* S2t = sh;
    float* Qs  = S2t + 128 * 132;
    float* Ut  = Qs  + 64 * 132;
    float* Ks  = Ut  + 128 * 68;
    float* Ps  = Ks  + 64 * 128;
    float* gam = Ps  + 64 * 68;

    const int ch = blockIdx.x, tid = threadIdx.x;
    const size_t eb = (size_t)ch * LCH * CC;

    for (int x = tid; x < 16384; x += 256) {
        int j = x >> 7, i = x & 127;
        S2t[i * 132 + j] = g_Sc[(size_t)ch * 16384 + x];
    }
    for (int x = tid; x < 8192; x += 256) {
        int t = x >> 7, i = x & 127;
        Qs[t * 132 + i] = g_Q[eb + x];
        Ut[i * 68 + t]  = g_U[eb + x];
        Ks[x]           = g_K[eb + x];
    }
    if (tid < 64) gam[tid] = g_Gm[(size_t)ch * LCH + tid];
    __syncthreads();

    {
        const int t0 = (tid >> 4) * 4, s0 = (tid & 15) * 4;
        float pa[4][4];
#pragma unroll
        for (int a = 0; a < 4; ++a)
#pragma unroll
            for (int e = 0; e < 4; ++e) pa[a][e] = 0.0f;
        for (int i = 0; i < 128; ++i) {
            float qv[4];
#pragma unroll
            for (int a = 0; a < 4; ++a) qv[a] = Qs[(t0 + a) * 132 + i];
            float4 dv = *(float4*)&Ut[i * 68 + s0];
            float dr[4] = {dv.x, dv.y, dv.z, dv.w};
#pragma unroll
            for (int a = 0; a < 4; ++a)
#pragma unroll
                for (int e = 0; e < 4; ++e) pa[a][e] = fmaf(qv[a], dr[e], pa[a][e]);
        }
#pragma unroll
        for (int a = 0; a < 4; ++a) {
            int t = t0 + a;
#pragma unroll
            for (int e = 0; e < 4; ++e) {
                int s = s0 + e;
                Ps[t * 68 + s] = (s <= t) ? (gam[t] / gam[s]) * pa[a][e] : 0.0f;
            }
        }
    }
    __syncthreads();

    {
        const int t0 = (tid >> 4) * 4, j0 = (tid & 15) * 8;
        ull oa[4][4];
#pragma unroll
        for (int a = 0; a < 4; ++a)
#pragma unroll
            for (int p = 0; p < 4; ++p) oa[a][p] = 0ull;
        for (int i = 0; i < 128; ++i) {
            ull qd[4];
#pragma unroll
            for (int a = 0; a < 4; ++a) {
                float q = Qs[(t0 + a) * 132 + i];
                qd[a] = pack2(q, q);
            }
            ulonglong2 sA = *(ulonglong2*)&S2t[i * 132 + j0];
            ulonglong2 sB = *(ulonglong2*)&S2t[i * 132 + j0 + 4];
            ull sp[4] = {sA.x, sA.y, sB.x, sB.y};
#pragma unroll
            for (int a = 0; a < 4; ++a)
#pragma unroll
                for (int p = 0; p < 4; ++p) oa[a][p] = fma2(qd[a], sp[p], oa[a][p]);
        }
#pragma unroll
        for (int a = 0; a < 4; ++a) {
            const ull g2 = pack2(gam[t0 + a], gam[t0 + a]);
#pragma unroll
            for (int p = 0; p < 4; ++p) oa[a][p] = mul2(oa[a][p], g2);
        }
        for (int s = 0; s < 64; ++s) {
            ull pd[4];
#pragma unroll
            for (int a = 0; a < 4; ++a) {
                float pv = Ps[(t0 + a) * 68 + s];
                pd[a] = pack2(pv, pv);
            }
            ulonglong2 kA = *(ulonglong2*)&Ks[s * 128 + j0];
            ulonglong2 kB = *(ulonglong2*)&Ks[s * 128 + j0 + 4];
            ull kp[4] = {kA.x, kA.y, kB.x, kB.y};
#pragma unroll
            for (int a = 0; a < 4; ++a)
#pragma unroll
                for (int p = 0; p < 4; ++p) oa[a][p] = fma2(pd[a], kp[p], oa[a][p]);
        }
#pragma unroll
        for (int a = 0; a < 4; ++a) {
            const size_t row = eb + (size_t)(t0 + a) * CC + j0;
            float f[8];
            unpack2(oa[a][0], f[0], f[1]); unpack2(oa[a][1], f[2], f[3]);
            unpack2(oa[a][2], f[4], f[5]); unpack2(oa[a][3], f[6], f[7]);
            float4 gA = *(const float4*)&g_G[row];
            float4 gB = *(const float4*)&g_G[row + 4];
            float v[8];
            v[0] = f[0] * gA.x; v[1] = f[1] * gA.y; v[2] = f[2] * gA.z; v[3] = f[3] * gA.w;
            v[4] = f[4] * gB.x; v[5] = f[5] * gB.y; v[6] = f[6] * gB.z; v[7] = f[7] * gB.w;
#pragma unroll
            for (int q = 0; q < 4; ++q) {
                __nv_bfloat16 h0 = __float2bfloat16(v[2 * q]);
                __nv_bfloat16 h1 = __float2bfloat16(v[2 * q + 1]);
                __nv_bfloat16 l0 = __float2bfloat16(v[2 * q]     - __bfloat162float(h0));
                __nv_bfloat16 l1 = __float2bfloat16(v[2 * q + 1] - __bfloat162float(h1));
                *(__nv_bfloat162*)(g_Oh + row + 2 * q) = __halves2bfloat162(h0, h1);
                *(__nv_bfloat162*)(g_Ol + row + 2 * q) = __halves2bfloat162(l0, l1);
            }
        }
    }
}

// ===========================================================================
extern "C" void kernel_launch(void* const* d_in, const int* in_sizes, int n_in,
                              void* d_out, int out_size)
{
    const float* x  = (const float*)d_in[0];
    const float* Wq = (const float*)d_in[1];  const float* bq = (const float*)d_in[2];
    const float* Wk = (const float*)d_in[3];  const float* bk = (const float*)d_in[4];
    const float* Wv = (const float*)d_in[5];  const float* bv = (const float*)d_in[6];
    const float* Wa = (const float*)d_in[7];  const float* ba = (const float*)d_in[8];
    const float* Wb = (const float*)d_in[9];  const float* bb = (const float*)d_in[10];
    const float* Wg = (const float*)d_in[11]; const float* bg = (const float*)d_in[12];
    const float* Wo = (const float*)d_in[13]; const float* bo = (const float*)d_in[14];
    float* out = (float*)d_out;

    static int attr_done = 0;
    if (!attr_done) {
        cudaFuncSetAttribute(prep_kernel, cudaFuncAttributeMaxDynamicSharedMemorySize, PREP_SMEM);
        cudaFuncSetAttribute(seq_kernel,  cudaFuncAttributeMaxDynamicSharedMemorySize, SEQ_SMEM);
        cudaFuncSetAttribute(outp_kernel, cudaFuncAttributeMaxDynamicSharedMemorySize, OUTP_SMEM);
        cudaFuncSetAttribute(proj_mma,    cudaFuncAttributeMaxDynamicSharedMemorySize, GM_SMEM);
        cudaFuncSetAttribute(out_mma,     cudaFuncAttributeMaxDynamicSharedMemorySize, GM_SMEM);
        attr_done = 1;
    }

    split_x<<<ROWS * DIMK / 1024, 256>>>(x);
    split_w<<<(4 * 131072 + 131072) / 256, 256>>>(Wq, Wk, Wv, Wg, Wo);
    proj_mma<<<dim3(128, 4), 256, GM_SMEM>>>(bq, bk, bv, bg);
    ab_kernel<<<2048, 256>>>(x, Wa, ba, Wb, bb);
    knorm_kernel<<<2048, 256>>>();
    prep_kernel<<<NCHT, 256, PREP_SMEM>>>();
    seq_kernel<<<BB * 8, 256, SEQ_SMEM>>>();
    outp_kernel<<<NCHT, 256, OUTP_SMEM>>>();
    out_mma<<<dim3(128, 8), 256, GM_SMEM>>>(bo, out);
}

// round 17
// speedup vs baseline: 3.8573x; 1.0157x over previous
#include <cuda_runtime.h>
#include <cuda_bf16.h>
#include <cstdint>
#include <math.h>

#define DIMK 1024
#define CC   128
#define BB   8
#define TT   2048
#define ROWS (BB*TT)
#define LCH  64
#define NCH  (TT/LCH)     // 32
#define NCHT (BB*NCH)     // 256

typedef unsigned long long ull;

// ------------------------- device scratch ---------------------------------
__device__ float g_Q [ROWS*CC];
__device__ float g_K [ROWS*CC];
__device__ float g_V [ROWS*CC];
__device__ float g_G [ROWS*CC];
__device__ float g_Al[ROWS];
__device__ float g_Be[ROWS];
__device__ float g_U0[NCHT*LCH*CC];
__device__ float g_W [NCHT*LCH*CC];
__device__ float g_U [NCHT*LCH*CC];
__device__ float g_Sc[NCHT*CC*CC];
__device__ float g_Gm[NCHT*LCH];
// bf16 split operands
__device__ __nv_bfloat16 g_Wth[4*CC*DIMK];     // W^T per mat: [mat][n=128][k=1024]
__device__ __nv_bfloat16 g_Wtl[4*CC*DIMK];
__device__ __nv_bfloat16 g_Woth[DIMK*CC];      // Wo^T: [n=1024][k=128]
__device__ __nv_bfloat16 g_Wotl[DIMK*CC];
__device__ __nv_bfloat16 g_Oh [ROWS*CC];       // gated output, split
__device__ __nv_bfloat16 g_Ol [ROWS*CC];

__device__ __forceinline__ float sigmoidf_(float x) { return 1.0f / (1.0f + expf(-x)); }
__device__ __forceinline__ ull pack2(float lo, float hi) {
    ull r; asm("mov.b64 %0, {%1, %2};" : "=l"(r) : "f"(lo), "f"(hi)); return r;
}
__device__ __forceinline__ void unpack2(ull v, float& lo, float& hi) {
    asm("mov.b64 {%0, %1}, %2;" : "=f"(lo), "=f"(hi) : "l"(v));
}
__device__ __forceinline__ ull fma2(ull a, ull b, ull c) {
    ull d; asm("fma.rn.f32x2 %0, %1, %2, %3;" : "=l"(d) : "l"(a), "l"(b), "l"(c)); return d;
}
__device__ __forceinline__ ull mul2(ull a, ull b) {
    ull d; asm("mul.rn.f32x2 %0, %1, %2;" : "=l"(d) : "l"(a), "l"(b)); return d;
}
__device__ __forceinline__ uint32_t smem_u32(const void* p) {
    uint32_t a;
    asm("{ .reg .u64 t; cvta.to.shared.u64 t, %1; cvt.u32.u64 %0, t; }" : "=r"(a) : "l"(p));
    return a;
}
__device__ __forceinline__ void ldm_x4(uint32_t* r, uint32_t addr) {
    asm volatile("ldmatrix.sync.aligned.m8n8.x4.shared.b16 {%0,%1,%2,%3}, [%4];"
        : "=r"(r[0]), "=r"(r[1]), "=r"(r[2]), "=r"(r[3]) : "r"(addr));
}
__device__ __forceinline__ void mma16816(float* c, const uint32_t* a, const uint32_t* b) {
    asm volatile("mma.sync.aligned.m16n8k16.row.col.f32.bf16.bf16.f32 "
        "{%0,%1,%2,%3}, {%4,%5,%6,%7}, {%8,%9}, {%0,%1,%2,%3};"
        : "+f"(c[0]), "+f"(c[1]), "+f"(c[2]), "+f"(c[3])
        : "r"(a[0]), "r"(a[1]), "r"(a[2]), "r"(a[3]), "r"(b[0]), "r"(b[1]));
}
// split one float4 into 4 hi + 4 lo bf16, packed as 2x uint32 each
__device__ __forceinline__ void split4(float4 v, uint32_t* h, uint32_t* l) {
    __nv_bfloat16 h0 = __float2bfloat16(v.x), h1 = __float2bfloat16(v.y);
    __nv_bfloat16 h2 = __float2bfloat16(v.z), h3 = __float2bfloat16(v.w);
    __nv_bfloat162 H0 = __halves2bfloat162(h0, h1);
    __nv_bfloat162 H1 = __halves2bfloat162(h2, h3);
    __nv_bfloat162 L0 = __halves2bfloat162(
        __float2bfloat16(v.x - __bfloat162float(h0)),
        __float2bfloat16(v.y - __bfloat162float(h1)));
    __nv_bfloat162 L1 = __halves2bfloat162(
        __float2bfloat16(v.z - __bfloat162float(h2)),
        __float2bfloat16(v.w - __bfloat162float(h3)));
    h[0] = *(uint32_t*)&H0; h[1] = *(uint32_t*)&H1;
    l[0] = *(uint32_t*)&L0; l[1] = *(uint32_t*)&L1;
}

// ====================== weight split kernel =================================
__global__ __launch_bounds__(256) void split_w(
    const float* __restrict__ Wq, const float* __restrict__ Wk,
    const float* __restrict__ Wv, const float* __restrict__ Wg,
    const float* __restrict__ Wo)
{
    int gidx = blockIdx.x * 256 + threadIdx.x;   // 0 .. 655359
    float v; __nv_bfloat16* dh; __nv_bfloat16* dl; size_t didx;
    if (gidx < 4 * 131072) {
        int mat = gidx >> 17, rem = gidx & 131071;
        int n = rem >> 10, k = rem & 1023;
        const float* W = (mat == 0) ? Wq : (mat == 1) ? Wk : (mat == 2) ? Wv : Wg;
        v = W[(size_t)k * CC + n];
        didx = (size_t)mat * 131072 + (size_t)n * 1024 + k;
        dh = g_Wth; dl = g_Wtl;
    } else {
        int rem = gidx - 4 * 131072;
        int n = rem >> 7, k = rem & 127;
        v = Wo[(size_t)k * DIMK + n];
        didx = (size_t)n * 128 + k;
        dh = g_Woth; dl = g_Wotl;
    }
    __nv_bfloat16 h = __float2bfloat16(v);
    dh[didx] = h;
    dl[didx] = __float2bfloat16(v - __bfloat162float(h));
}

// ====================== mma.sync split-bf16 GEMM core (double-buffered) ====
// C tile [128 x 128]. Warp tile: 32 rows x 64 cols. K chunks of 32.
// A_FP32: A operand read as fp32 (Af) and hi/lo-split in registers.
//   A slots: it = 0..3 (idx<1024): row=idx>>3, c4=(idx&7)*4, one float4 each.
//   B slots: it = 4..7: bt=(idx-1024)>>9, row, c8.
#define GM_BUF  (4 * 128 * 40)
#define GM_SMEM (2 * GM_BUF * 2)          // 81920 B
template<bool A_FP32>
__device__ __forceinline__ void mm_core(
    const float* __restrict__ Af,
    const __nv_bfloat16* __restrict__ Ah, const __nv_bfloat16* __restrict__ Al, int lda,
    const __nv_bfloat16* __restrict__ Bth, const __nv_bfloat16* __restrict__ Btl, int ldb,
    int K,
    const float* __restrict__ bias, float* __restrict__ Cout, int ldc,
    int row0, int gate)
{
    extern __shared__ __align__(16) __nv_bfloat16 sm[];

    const int tid = threadIdx.x, wid = tid >> 5, lane = tid & 31;
    const int mrow = (wid >> 1) * 32;
    const int ncol = (wid & 1) * 64;
    const int g  = lane >> 2, tg = lane & 3;
    const int lj = lane >> 3, lr = lane & 7;

    float acc[2][8][4];
#pragma unroll
    for (int mt = 0; mt < 2; ++mt)
#pragma unroll
        for (int nt = 0; nt < 8; ++nt)
#pragma unroll
            for (int e = 0; e < 4; ++e) acc[mt][nt][e] = 0.0f;

    const int NC = K >> 5;

    // prologue: stage chunk 0 into buffer 0 (direct loads)
    {
        __nv_bfloat16* AsH_ = sm;
        __nv_bfloat16* AsL_ = sm + 128 * 40;
        __nv_bfloat16* BsH_ = sm + 2 * 128 * 40;
        __nv_bfloat16* BsL_ = sm + 3 * 128 * 40;
#pragma unroll
        for (int it = 0; it < 8; ++it) {
            int idx = it * 256 + tid;
            if (A_FP32) {
                if (idx < 1024) {
                    int row = idx >> 3, c4 = (idx & 7) * 4;
                    float4 v = *(const float4*)(Af + (size_t)(row0 + row) * lda + c4);
                    uint32_t hh[2], ll[2];
                    split4(v, hh, ll);
                    *(uint2*)(AsH_ + row * 40 + c4) = make_uint2(hh[0], hh[1]);
                    *(uint2*)(AsL_ + row * 40 + c4) = make_uint2(ll[0], ll[1]);
                } else {
                    int rem = idx - 1024;
                    int bt = rem >> 9, row = (rem & 511) >> 2, c8 = (rem & 3) * 8;
                    const __nv_bfloat16* src = (bt == 0 ? Bth : Btl) + (size_t)row * ldb + c8;
                    *(uint4*)((bt == 0 ? BsH_ : BsL_) + row * 40 + c8) = *(const uint4*)src;
                }
            } else {
                int t4 = idx >> 9, rem = idx & 511;
                int row = rem >> 2, c8 = (rem & 3) * 8;
                const __nv_bfloat16* src;
                __nv_bfloat16* dst;
                if      (t4 == 0) { src = Ah  + (size_t)(row0 + row) * lda + c8; dst = AsH_; }
                else if (t4 == 1) { src = Al  + (size_t)(row0 + row) * lda + c8; dst = AsL_; }
                else if (t4 == 2) { src = Bth + (size_t)row * ldb + c8; dst = BsH_; }
                else              { src = Btl + (size_t)row * ldb + c8; dst = BsL_; }
                *(uint4*)(dst + row * 40 + c8) = *(const uint4*)src;
            }
        }
    }
    __syncthreads();

    for (int c = 0; c < NC; ++c) {
        __nv_bfloat16* buf = sm + (c & 1) * GM_BUF;

        // prefetch chunk c+1 into registers (FIX: pfa[it], it = 0..3)
        float4 pfa[4]; uint4 pfb[8];
        if (c + 1 < NC) {
            const int kn = (c + 1) * 32;
#pragma unroll
            for (int it = 0; it < 8; ++it) {
                int idx = it * 256 + tid;
                if (A_FP32) {
                    if (idx < 1024) {
                        int row = idx >> 3, c4 = (idx & 7) * 4;
                        pfa[it] = *(const float4*)(Af + (size_t)(row0 + row) * lda + kn + c4);
                    } else {
                        int rem = idx - 1024;
                        int bt = rem >> 9, row = (rem & 511) >> 2, c8 = (rem & 3) * 8;
                        pfb[it] = *(const uint4*)((bt == 0 ? Bth : Btl) + (size_t)row * ldb + kn + c8);
                    }
                } else {
                    int t4 = idx >> 9, rem = idx & 511;
                    int row = rem >> 2, c8 = (rem & 3) * 8;
                    const __nv_bfloat16* src;
                    if      (t4 == 0) src = Ah  + (size_t)(row0 + row) * lda + kn + c8;
                    else if (t4 == 1) src = Al  + (size_t)(row0 + row) * lda + kn + c8;
                    else if (t4 == 2) src = Bth + (size_t)row * ldb + kn + c8;
                    else              src = Btl + (size_t)row * ldb + kn + c8;
                    pfb[it] = *(const uint4*)src;
                }
            }
        }

        __nv_bfloat16* AsH = buf;
        __nv_bfloat16* AsL = buf + 128 * 40;
        __nv_bfloat16* BsH = buf + 2 * 128 * 40;
        __nv_bfloat16* BsL = buf + 3 * 128 * 40;
#pragma unroll
        for (int ks = 0; ks < 2; ++ks) {
            const int kb = ks * 16;
            uint32_t ah[2][4], al[2][4], bh[8][2], bl[8][2];
#pragma unroll
            for (int mt = 0; mt < 2; ++mt) {
                int arow = mrow + mt * 16 + (lj & 1) * 8 + lr;
                int acol = kb + (lj >> 1) * 8;
                ldm_x4(ah[mt], smem_u32(AsH + arow * 40 + acol));
                ldm_x4(al[mt], smem_u32(AsL + arow * 40 + acol));
            }
#pragma unroll
            for (int np = 0; np < 4; ++np) {
                int brow = ncol + np * 16 + (lj >> 1) * 8 + lr;
                int bcol = kb + (lj & 1) * 8;
                uint32_t r4[4];
                ldm_x4(r4, smem_u32(BsH + brow * 40 + bcol));
                bh[np * 2][0] = r4[0]; bh[np * 2][1] = r4[1];
                bh[np * 2 + 1][0] = r4[2]; bh[np * 2 + 1][1] = r4[3];
                ldm_x4(r4, smem_u32(BsL + brow * 40 + bcol));
                bl[np * 2][0] = r4[0]; bl[np * 2][1] = r4[1];
                bl[np * 2 + 1][0] = r4[2]; bl[np * 2 + 1][1] = r4[3];
            }
#pragma unroll
            for (int mt = 0; mt < 2; ++mt)
#pragma unroll
                for (int nt = 0; nt < 8; ++nt) {
                    mma16816(acc[mt][nt], ah[mt], bh[nt]);
                    mma16816(acc[mt][nt], ah[mt], bl[nt]);
                    mma16816(acc[mt][nt], al[mt], bh[nt]);
                }
        }

        if (c + 1 < NC) {
            __nv_bfloat16* nbuf = sm + ((c + 1) & 1) * GM_BUF;
            __nv_bfloat16* nAsH = nbuf;
            __nv_bfloat16* nAsL = nbuf + 128 * 40;
            __nv_bfloat16* nBsH = nbuf + 2 * 128 * 40;
            __nv_bfloat16* nBsL = nbuf + 3 * 128 * 40;
#pragma unroll
            for (int it = 0; it < 8; ++it) {
                int idx = it * 256 + tid;
                if (A_FP32) {
                    if (idx < 1024) {
                        int row = idx >> 3, c4 = (idx & 7) * 4;
                        uint32_t hh[2], ll[2];
                        split4(pfa[it], hh, ll);
                        *(uint2*)(nAsH + row * 40 + c4) = make_uint2(hh[0], hh[1]);
                        *(uint2*)(nAsL + row * 40 + c4) = make_uint2(ll[0], ll[1]);
                    } else {
                        int rem = idx - 1024;
                        int bt = rem >> 9, row = (rem & 511) >> 2, c8 = (rem & 3) * 8;
                        *(uint4*)((bt == 0 ? nBsH : nBsL) + row * 40 + c8) = pfb[it];
                    }
                } else {
                    int t4 = idx >> 9, rem = idx & 511;
                    int row = rem >> 2, c8 = (rem & 3) * 8;
                    __nv_bfloat16* dst = (t4 == 0) ? nAsH : (t4 == 1) ? nAsL : (t4 == 2) ? nBsH : nBsL;
                    *(uint4*)(dst + row * 40 + c8) = pfb[it];
                }
            }
        }
        __syncthreads();
    }

    // epilogue
#pragma unroll
    for (int mt = 0; mt < 2; ++mt) {
#pragma unroll
        for (int nt = 0; nt < 8; ++nt) {
            int col = ncol + nt * 8 + tg * 2;
            float b0 = bias[col], b1 = bias[col + 1];
            int rA = row0 + mrow + mt * 16 + g;
            float v0 = acc[mt][nt][0] + b0, v1 = acc[mt][nt][1] + b1;
            float v2 = acc[mt][nt][2] + b0, v3 = acc[mt][nt][3] + b1;
            if (gate) { v0 = sigmoidf_(v0); v1 = sigmoidf_(v1); v2 = sigmoidf_(v2); v3 = sigmoidf_(v3); }
            *(float2*)&Cout[(size_t)rA * ldc + col]       = make_float2(v0, v1);
            *(float2*)&Cout[(size_t)(rA + 8) * ldc + col] = make_float2(v2, v3);
        }
    }
}

__global__ __launch_bounds__(256) void proj_mma(
    const float* __restrict__ x,
    const float* __restrict__ bq, const float* __restrict__ bk,
    const float* __restrict__ bv, const float* __restrict__ bg)
{
    const int mat = blockIdx.y;
    const float* bias = (mat == 0) ? bq : (mat == 1) ? bk : (mat == 2) ? bv : bg;
    float* Cout = (mat == 0) ? g_Q : (mat == 1) ? g_K : (mat == 2) ? g_V : g_G;
    mm_core<true>(x, nullptr, nullptr, DIMK,
            g_Wth + (size_t)mat * CC * DIMK, g_Wtl + (size_t)mat * CC * DIMK, DIMK,
            DIMK, bias, Cout, CC, blockIdx.x * 128, mat == 3);
}

__global__ __launch_bounds__(256) void out_mma(
    const float* __restrict__ bo, float* __restrict__ out)
{
    const int col0 = blockIdx.y * 128;
    mm_core<false>(nullptr, g_Oh, g_Ol, CC,
            g_Woth + (size_t)col0 * CC, g_Wotl + (size_t)col0 * CC, CC,
            CC, bo + col0, out + col0, DIMK, blockIdx.x * 128, 0);
}

// ====================== alpha/beta ==========================================
__global__ __launch_bounds__(256) void ab_kernel(
    const float* __restrict__ x,
    const float* __restrict__ Wa, const float* __restrict__ ba,
    const float* __restrict__ Wb, const float* __restrict__ bb)
{
    const int warp = threadIdx.x >> 5, lane = threadIdx.x & 31;
    const int row  = blockIdx.x * 8 + warp;
    const float* xr = x + (size_t)row * DIMK;
    float accA = 0.0f, accB = 0.0f;
#pragma unroll
    for (int it = 0; it < 8; ++it) {
        int kidx = it * 128 + lane * 4;
        float4 xv = *(const float4*)(xr + kidx);
        float4 wa = *(const float4*)(Wa + kidx);
        float4 wb = *(const float4*)(Wb + kidx);
        accA += xv.x * wa.x + xv.y * wa.y + xv.z * wa.z + xv.w * wa.w;
        accB += xv.x * wb.x + xv.y * wb.y + xv.z * wb.z + xv.w * wb.w;
    }
#pragma unroll
    for (int o = 16; o; o >>= 1) {
        accA += __shfl_xor_sync(0xffffffffu, accA, o);
        accB += __shfl_xor_sync(0xffffffffu, accB, o);
    }
    if (lane == 0) {
        g_Al[row] = sigmoidf_(accA + ba[0]);
        g_Be[row] = sigmoidf_(accB + bb[0]);
    }
}

// ====================== k normalize =========================================
__global__ __launch_bounds__(256) void knorm_kernel()
{
    const int warp = threadIdx.x >> 5, lane = threadIdx.x & 31;
    const int row  = blockIdx.x * 8 + warp;
    float* kp = g_K + (size_t)row * CC + lane * 4;
    float4 kv = *(float4*)kp;
    float ss = kv.x * kv.x + kv.y * kv.y + kv.z * kv.z + kv.w * kv.w;
#pragma unroll
    for (int o = 16; o; o >>= 1) ss += __shfl_xor_sync(0xffffffffu, ss, o);
    float scale = 1.0f / fmaxf(sqrtf(ss), 1e-12f);
    kv.x *= scale; kv.y *= scale; kv.z *= scale; kv.w *= scale;
    *(float4*)kp = kv;
}

// ====================== per-chunk precompute ================================
#define PREP_SMEM ((64*132 + 128*68 + 64*64 + 192) * 4)
__global__ __launch_bounds__(256) void prep_kernel()
{
    extern __shared__ float sh[];
    float* Kp  = sh;
    float* KpT = Kp + 64 * 132;
    float* Am  = KpT + 128 * 68;
    float* gam = Am + 4096;
    float* asv = gam + 64;
    float* bsv = asv + 64;

    const int ch = blockIdx.x, tid = threadIdx.x;
    const size_t rbase = (size_t)ch * LCH, eb = rbase * CC;

    for (int x = tid; x < LCH * CC; x += 256) {
        int t = x >> 7, i = x & 127;
        float kv = g_K[eb + x];
        Kp[t * 132 + i] = kv;
        KpT[i * 68 + t] = kv;
    }
    if (tid < 64) { asv[tid] = g_Al[rbase + tid]; bsv[tid] = g_Be[rbase + tid]; }
    __syncthreads();
    if (tid == 0) {
        float g = 1.0f;
        for (int t = 0; t < 64; ++t) { g *= asv[t]; gam[t] = g; }
    }
    __syncthreads();

    {
        const int t0 = (tid >> 4) * 4, s0p = (tid & 15) * 4;
        float pa[4][4];
#pragma unroll
        for (int a = 0; a < 4; ++a)
#pragma unroll
            for (int e = 0; e < 4; ++e) pa[a][e] = 0.0f;
        for (int i = 0; i < 128; ++i) {
            float4 ksv = *(float4*)&KpT[i * 68 + s0p];
            float kt0 = Kp[(t0 + 0) * 132 + i];
            float kt1 = Kp[(t0 + 1) * 132 + i];
            float kt2 = Kp[(t0 + 2) * 132 + i];
            float kt3 = Kp[(t0 + 3) * 132 + i];
            pa[0][0] = fmaf(kt0, ksv.x, pa[0][0]); pa[0][1] = fmaf(kt0, ksv.y, pa[0][1]);
            pa[0][2] = fmaf(kt0, ksv.z, pa[0][2]); pa[0][3] = fmaf(kt0, ksv.w, pa[0][3]);
            pa[1][0] = fmaf(kt1, ksv.x, pa[1][0]); pa[1][1] = fmaf(kt1, ksv.y, pa[1][1]);
            pa[1][2] = fmaf(kt1, ksv.z, pa[1][2]); pa[1][3] = fmaf(kt1, ksv.w, pa[1][3]);
            pa[2][0] = fmaf(kt2, ksv.x, pa[2][0]); pa[2][1] = fmaf(kt2, ksv.y, pa[2][1]);
            pa[2][2] = fmaf(kt2, ksv.z, pa[2][2]); pa[2][3] = fmaf(kt2, ksv.w, pa[2][3]);
            pa[3][0] = fmaf(kt3, ksv.x, pa[3][0]); pa[3][1] = fmaf(kt3, ksv.y, pa[3][1]);
            pa[3][2] = fmaf(kt3, ksv.z, pa[3][2]); pa[3][3] = fmaf(kt3, ksv.w, pa[3][3]);
        }
#pragma unroll
        for (int a = 0; a < 4; ++a) {
            int t = t0 + a;
#pragma unroll
            for (int e = 0; e < 4; ++e) {
                int s = s0p + e;
                Am[t * 64 + s] = (s < t) ? bsv[t] * (gam[t] / gam[s]) * pa[a][e] : 0.0f;
            }
        }
    }
    __syncthreads();

    {
        const int  i   = tid & 127;
        const bool isU = (tid < 128);
        float X[64];
#pragma unroll
        for (int t = 0; t < 64; ++t) {
            float rhs = isU ? bsv[t] * g_V[eb + (size_t)t * CC + i]
                            : (bsv[t] * gam[t]) * Kp[t * 132 + i];
            float a0 = 0.f, a1 = 0.f, a2 = 0.f, a3 = 0.f;
#pragma unroll
            for (int s = 0; s + 4 <= t; s += 4) {
                a0 = fmaf(Am[t * 64 + s + 0], X[s + 0], a0);
                a1 = fmaf(Am[t * 64 + s + 1], X[s + 1], a1);
                a2 = fmaf(Am[t * 64 + s + 2], X[s + 2], a2);
                a3 = fmaf(Am[t * 64 + s + 3], X[s + 3], a3);
            }
#pragma unroll
            for (int s = t & ~3; s < t; ++s)
                a0 = fmaf(Am[t * 64 + s], X[s], a0);
            X[t] = rhs - ((a0 + a1) + (a2 + a3));
        }
        float* dst = isU ? g_U0 : g_W;
#pragma unroll
        for (int t = 0; t < 64; ++t)
            dst[eb + (size_t)t * CC + i] = X[t];
    }
    if (tid < 64) g_Gm[rbase + tid] = gam[tid];
}

// ====================== sequential chunk recurrence =========================
#define SEQ_SMEM ((128*16 + 64*260 + 64*260 + 64*16 + 64) * 4)
__global__ __launch_bounds__(256, 1) void seq_kernel()
{
    extern __shared__ float sh[];
    float* Ssh = sh;
    float* Wd  = Ssh + 2048;
    float* Kd  = Wd + 64 * 260;
    float* Ysh = Kd + 64 * 260;
    float* gam = Ysh + 1024;

    const int b   = blockIdx.x >> 3;
    const int sl  = blockIdx.x & 7;
    const int tid = threadIdx.x;
    const int icol0 = sl * 16;

    for (int x = tid; x < 2048; x += 256) Ssh[x] = 0.0f;

    const int t1  = tid >> 2;
    const int ii0 = (tid & 3) * 4;
    const int jg2 = tid >> 1;
    const int c0  = (tid & 1) * 8;

    for (int c = 0; c < NCH; ++c) {
        const size_t ch = (size_t)(b * NCH + c);
        const size_t eb = ch * LCH * CC;
        __syncthreads();

        for (int x = tid; x < 512; x += 256) {
            int j = x >> 2, ii = (x & 3) * 4;
            *(float4*)&g_Sc[ch * 16384 + (size_t)j * 128 + icol0 + ii] =
                *(float4*)&Ssh[j * 16 + ii];
        }
        for (int x = tid; x < 2048; x += 256) {
            int base = x * 4, t = base >> 7, j = base & 127;
            float4 w4 = *(const float4*)&g_W[eb + base];
            *(float4*)&Wd[t * 260 + 2 * j]     = make_float4(-w4.x, -w4.x, -w4.y, -w4.y);
            *(float4*)&Wd[t * 260 + 2 * j + 4] = make_float4(-w4.z, -w4.z, -w4.w, -w4.w);
            float4 k4 = *(const float4*)&g_K[eb + base];
            *(float4*)&Kd[t * 260 + 2 * j]     = make_float4(k4.x, k4.x, k4.y, k4.y);
            *(float4*)&Kd[t * 260 + 2 * j + 4] = make_float4(k4.z, k4.z, k4.w, k4.w);
        }
        if (tid < 64) gam[tid] = g_Gm[ch * LCH + tid];
        float4 u0a = *(const float4*)&g_U0[eb + (size_t)t1 * CC + icol0 + ii0];
        __syncthreads();
        const float gamL = gam[63];

        ull acc0 = pack2(u0a.x, u0a.y), acc1 = pack2(u0a.z, u0a.w);
#pragma unroll 8
        for (int j = 0; j < 128; ++j) {
            ull w = *(ull*)&Wd[t1 * 260 + 2 * j];
            ulonglong2 sA = *(ulonglong2*)&Ssh[j * 16 + ii0];
            acc0 = fma2(w, sA.x, acc0);
            acc1 = fma2(w, sA.y, acc1);
        }
        {
            float f0, f1, f2, f3;
            unpack2(acc0, f0, f1); unpack2(acc1, f2, f3);
            const float rt = gamL / gam[t1];
            *(float4*)&g_U[eb + (size_t)t1 * CC + icol0 + ii0] = make_float4(f0, f1, f2, f3);
            *(float4*)&Ysh[t1 * 16 + ii0] = make_float4(rt * f0, rt * f1, rt * f2, rt * f3);
        }
        __syncthreads();

        ull s2[4];
        const ull gl2 = pack2(gamL, gamL);
        {
            ulonglong2 oA = *(ulonglong2*)&Ssh[jg2 * 16 + c0];
            ulonglong2 oB = *(ulonglong2*)&Ssh[jg2 * 16 + c0 + 4];
            s2[0] = mul2(oA.x, gl2); s2[1] = mul2(oA.y, gl2);
            s2[2] = mul2(oB.x, gl2); s2[3] = mul2(oB.y, gl2);
        }
#pragma unroll 8
        for (int t = 0; t < 64; ++t) {
            ull k = *(ull*)&Kd[t * 260 + 2 * jg2];
            ulonglong2 yA = *(ulonglong2*)&Ysh[t * 16 + c0];
            ulonglong2 yB = *(ulonglong2*)&Ysh[t * 16 + c0 + 4];
            s2[0] = fma2(k, yA.x, s2[0]); s2[1] = fma2(k, yA.y, s2[1]);
            s2[2] = fma2(k, yB.x, s2[2]); s2[3] = fma2(k, yB.y, s2[3]);
        }
        *(ulonglong2*)&Ssh[jg2 * 16 + c0]     = make_ulonglong2(s2[0], s2[1]);
        *(ulonglong2*)&Ssh[jg2 * 16 + c0 + 4] = make_ulonglong2(s2[2], s2[3]);
    }
}

// ====================== per-chunk outputs (writes bf16 splits) ==============
#define OUTP_SMEM ((128*132 + 64*132 + 128*68 + 64*128 + 64*68 + 64) * 4)
__global__ __launch_bounds__(256) void outp_kernel()
{
    extern __shared__ float sh[];
    float* S2t = sh;
    float* Qs  = S2t + 128 * 132;
    float* Ut  = Qs  + 64 * 132;
    float* Ks  = Ut  + 128 * 68;
    float* Ps  = Ks  + 64 * 128;
    float* gam = Ps  + 64 * 68;

    const int ch = blockIdx.x, tid = threadIdx.x;
    const size_t eb = (size_t)ch * LCH * CC;

    for (int x = tid; x < 16384; x += 256) {
        int j = x >> 7, i = x & 127;
        S2t[i * 132 + j] = g_Sc[(size_t)ch * 16384 + x];
    }
    for (int x = tid; x < 8192; x += 256) {
        int t = x >> 7, i = x & 127;
        Qs[t * 132 + i] = g_Q[eb + x];
        Ut[i * 68 + t]  = g_U[eb + x];
        Ks[x]           = g_K[eb + x];
    }
    if (tid < 64) gam[tid] = g_Gm[(size_t)ch * LCH + tid];
    __syncthreads();

    {
        const int t0 = (tid >> 4) * 4, s0 = (tid & 15) * 4;
        float pa[4][4];
#pragma unroll
        for (int a = 0; a < 4; ++a)
#pragma unroll
            for (int e = 0; e < 4; ++e) pa[a][e] = 0.0f;
        for (int i = 0; i < 128; ++i) {
            float qv[4];
#pragma unroll
            for (int a = 0; a < 4; ++a) qv[a] = Qs[(t0 + a) * 132 + i];
            float4 dv = *(float4*)&Ut[i * 68 + s0];
            float dr[4] = {dv.x, dv.y, dv.z, dv.w};
#pragma unroll
            for (int a = 0; a < 4; ++a)
#pragma unroll
                for (int e = 0; e < 4; ++e) pa[a][e] = fmaf(qv[a], dr[e], pa[a][e]);
        }
#pragma unroll
        for (int a = 0; a < 4; ++a) {
            int t = t0 + a;
#pragma unroll
            for (int e = 0; e < 4; ++e) {
                int s = s0 + e;
                Ps[t * 68 + s] = (s <= t) ? (gam[t] / gam[s]) * pa[a][e] : 0.0f;
            }
        }
    }
    __syncthreads();

    {
        const int t0 = (tid >> 4) * 4, j0 = (tid & 15) * 8;
        ull oa[4][4];
#pragma unroll
        for (int a = 0; a < 4; ++a)
#pragma unroll
            for (int p = 0; p < 4; ++p) oa[a][p] = 0ull;
        for (int i = 0; i < 128; ++i) {
            ull qd[4];
#pragma unroll
            for (int a = 0; a < 4; ++a) {
                float q = Qs[(t0 + a) * 132 + i];
                qd[a] = pack2(q, q);
            }
            ulonglong2 sA = *(ulonglong2*)&S2t[i * 132 + j0];
            ulonglong2 sB = *(ulonglong2*)&S2t[i * 132 + j0 + 4];
            ull sp[4] = {sA.x, sA.y, sB.x, sB.y};
#pragma unroll
            for (int a = 0; a < 4; ++a)
#pragma unroll
                for (int p = 0; p < 4; ++p) oa[a][p] = fma2(qd[a], sp[p], oa[a][p]);
        }
#pragma unroll
        for (int a = 0; a < 4; ++a) {
            const ull g2 = pack2(gam[t0 + a], gam[t0 + a]);
#pragma unroll
            for (int p = 0; p < 4; ++p) oa[a][p] = mul2(oa[a][p], g2);
        }
        for (int s = 0; s < 64; ++s) {
            ull pd[4];
#pragma unroll
            for (int a = 0; a < 4; ++a) {
                float pv = Ps[(t0 + a) * 68 + s];
                pd[a] = pack2(pv, pv);
            }
            ulonglong2 kA = *(ulonglong2*)&Ks[s * 128 + j0];
            ulonglong2 kB = *(ulonglong2*)&Ks[s * 128 + j0 + 4];
            ull kp[4] = {kA.x, kA.y, kB.x, kB.y};
#pragma unroll
            for (int a = 0; a < 4; ++a)
#pragma unroll
                for (int p = 0; p < 4; ++p) oa[a][p] = fma2(pd[a], kp[p], oa[a][p]);
        }
#pragma unroll
        for (int a = 0; a < 4; ++a) {
            const size_t row = eb + (size_t)(t0 + a) * CC + j0;
            float f[8];
            unpack2(oa[a][0], f[0], f[1]); unpack2(oa[a][1], f[2], f[3]);
            unpack2(oa[a][2], f[4], f[5]); unpack2(oa[a][3], f[6], f[7]);
            float4 gA = *(const float4*)&g_G[row];
            float4 gB = *(const float4*)&g_G[row + 4];
            float v[8];
            v[0] = f[0] * gA.x; v[1] = f[1] * gA.y; v[2] = f[2] * gA.z; v[3] = f[3] * gA.w;
            v[4] = f[4] * gB.x; v[5] = f[5] * gB.y; v[6] = f[6] * gB.z; v[7] = f[7] * gB.w;
#pragma unroll
            for (int q = 0; q < 4; ++q) {
                __nv_bfloat16 h0 = __float2bfloat16(v[2 * q]);
                __nv_bfloat16 h1 = __float2bfloat16(v[2 * q + 1]);
                __nv_bfloat16 l0 = __float2bfloat16(v[2 * q]     - __bfloat162float(h0));
                __nv_bfloat16 l1 = __float2bfloat16(v[2 * q + 1] - __bfloat162float(h1));
                *(__nv_bfloat162*)(g_Oh + row + 2 * q) = __halves2bfloat162(h0, h1);
                *(__nv_bfloat162*)(g_Ol + row + 2 * q) = __halves2bfloat162(l0, l1);
            }
        }
    }
}

// ===========================================================================
extern "C" void kernel_launch(void* const* d_in, const int* in_sizes, int n_in,
                              void* d_out, int out_size)
{
    const float* x  = (const float*)d_in[0];
    const float* Wq = (const float*)d_in[1];  const float* bq = (const float*)d_in[2];
    const float* Wk = (const float*)d_in[3];  const float* bk = (const float*)d_in[4];
    const float* Wv = (const float*)d_in[5];  const float* bv = (const float*)d_in[6];
    const float* Wa = (const float*)d_in[7];  const float* ba = (const float*)d_in[8];
    const float* Wb = (const float*)d_in[9];  const float* bb = (const float*)d_in[10];
    const float* Wg = (const float*)d_in[11]; const float* bg = (const float*)d_in[12];
    const float* Wo = (const float*)d_in[13]; const float* bo = (const float*)d_in[14];
    float* out = (float*)d_out;

    static int attr_done = 0;
    if (!attr_done) {
        cudaFuncSetAttribute(prep_kernel, cudaFuncAttributeMaxDynamicSharedMemorySize, PREP_SMEM);
        cudaFuncSetAttribute(seq_kernel,  cudaFuncAttributeMaxDynamicSharedMemorySize, SEQ_SMEM);
        cudaFuncSetAttribute(outp_kernel, cudaFuncAttributeMaxDynamicSharedMemorySize, OUTP_SMEM);
        cudaFuncSetAttribute(proj_mma,    cudaFuncAttributeMaxDynamicSharedMemorySize, GM_SMEM);
        cudaFuncSetAttribute(out_mma,     cudaFuncAttributeMaxDynamicSharedMemorySize, GM_SMEM);
        attr_done = 1;
    }

    split_w<<<(4 * 131072 + 131072) / 256, 256>>>(Wq, Wk, Wv, Wg, Wo);
    proj_mma<<<dim3(128, 4), 256, GM_SMEM>>>(x, bq, bk, bv, bg);
    ab_kernel<<<2048, 256>>>(x, Wa, ba, Wb, bb);
    knorm_kernel<<<2048, 256>>>();
    prep_kernel<<<NCHT, 256, PREP_SMEM>>>();
    seq_kernel<<<BB * 8, 256, SEQ_SMEM>>>();
    outp_kernel<<<NCHT, 256, OUTP_SMEM>>>();
    out_mma<<<dim3(128, 8), 256, GM_SMEM>>>(bo, out);
}